// round 1
// baseline (speedup 1.0000x reference)
#include <cuda_runtime.h>
#include <math.h>

// ---------------- problem constants (fixed shapes from setup_inputs) -------
#define S_TOK 1536         // 1024 (img0 32x32) + 512 (img1 32x16) tokens
#define S0    1024
#define HID   1024
#define HEADS 16
#define HD    64
#define INTER 4096
#define NLAYERS 4
#define KPATCH 768         // 3*16*16
#define MAXSIDE 64

// ---------------- scratch (static device globals; no allocation) -----------
__device__ float g_xpatch[S_TOK * KPATCH];
__device__ float g_x [S_TOK * HID];
__device__ float g_h2[S_TOK * HID];
__device__ float g_hn[S_TOK * HID];
__device__ float g_q [S_TOK * HID];
__device__ float g_k [S_TOK * HID];
__device__ float g_v [S_TOK * HID];
__device__ float g_ao[S_TOK * HID];
__device__ float g_t [S_TOK * INTER];
__device__ float g_cos[S_TOK * HD];
__device__ float g_sin[S_TOK * HD];

// ---------------- im2col: build X_patch [S, 768] ---------------------------
__global__ void im2col_kernel(const float* __restrict__ img0,
                              const float* __restrict__ img1) {
    int idx = blockIdx.x * blockDim.x + threadIdx.x;
    if (idx >= S_TOK * KPATCH) return;
    int s = idx / KPATCH;
    int r = idx - s * KPATCH;
    int c  = r >> 8;          // channel 0..2
    int kh = (r >> 4) & 15;
    int kw = r & 15;
    float val;
    if (s < S0) {
        int ph = s >> 5, pw = s & 31;              // 32x32 grid, W=512
        val = img0[c * 512 * 512 + (ph * 16 + kh) * 512 + (pw * 16 + kw)];
    } else {
        int sp = s - S0;
        int ph = sp >> 4, pw = sp & 15;            // 32x16 grid, W=256
        val = img1[c * 512 * 256 + (ph * 16 + kh) * 256 + (pw * 16 + kw)];
    }
    g_xpatch[idx] = val;
}

// ---------------- RoPE table: cos/sin [S, 64] -------------------------------
__global__ void rope_table_kernel() {
    int s = blockIdx.x;
    int d = threadIdx.x;          // 0..63
    int ph, pw;
    if (s < S0) { ph = s >> 5; pw = s & 31; }
    else        { int sp = s - S0; ph = sp >> 4; pw = sp & 15; }
    int j = d & 31;
    float e, base;
    if (j < 16) { e = (4.0f * j) / 64.0f;             base = (float)ph; }
    else        { e = (2.0f + 4.0f * (j - 16)) / 64.0f; base = (float)pw; }
    float f = base * expf(-e * 9.2103403719761836f);  // 10000^(-e)
    g_cos[s * HD + d] = cosf(f);
    g_sin[s * HD + d] = sinf(f);
}

// ---------------- RMSNorm: y = x * rsqrt(mean(x^2)+eps) * w ----------------
__global__ void rms_kernel(const float* __restrict__ x,
                           const float* __restrict__ w,
                           float* __restrict__ y) {
    int s = blockIdx.x;
    int tid = threadIdx.x;        // 256
    const float* xr = x + s * HID;
    float ss = 0.f;
    #pragma unroll 4
    for (int i = tid; i < HID; i += 256) { float v = xr[i]; ss += v * v; }
    __shared__ float sh[8];
    #pragma unroll
    for (int o = 16; o > 0; o >>= 1) ss += __shfl_xor_sync(0xffffffffu, ss, o);
    if ((tid & 31) == 0) sh[tid >> 5] = ss;
    __syncthreads();
    if (tid < 8) {
        float v = sh[tid];
        #pragma unroll
        for (int o = 4; o > 0; o >>= 1) v += __shfl_xor_sync(0xffu, v, o);
        if (tid == 0) sh[0] = v;
    }
    __syncthreads();
    float r = rsqrtf(sh[0] * (1.0f / HID) + 1e-5f);
    for (int i = tid; i < HID; i += 256) y[s * HID + i] = xr[i] * r * w[i];
}

// ---------------- generic fp32 GEMM: C[M,N] = A[M,K] @ B[N,K]^T (+res) -----
// 64x64 tile, BK=16, 256 threads, 4x4 per thread
template<int RES>
__global__ void gemm_kernel(const float* __restrict__ A,
                            const float* __restrict__ B,
                            const float* __restrict__ res,
                            float* __restrict__ C,
                            int M, int N, int K) {
    __shared__ float As[16][64];
    __shared__ float Bs[16][64];
    int tid = threadIdx.x;
    int m0 = blockIdx.y * 64, n0 = blockIdx.x * 64;
    float acc[4][4] = {};
    int lr = tid >> 2;            // 0..63
    int lc = (tid & 3) * 4;       // 0,4,8,12
    int ty = tid >> 4, tx = tid & 15;

    for (int k0 = 0; k0 < K; k0 += 16) {
        float4 av = *(const float4*)&A[(m0 + lr) * K + k0 + lc];
        float4 bv = *(const float4*)&B[(n0 + lr) * K + k0 + lc];
        As[lc + 0][lr] = av.x; As[lc + 1][lr] = av.y;
        As[lc + 2][lr] = av.z; As[lc + 3][lr] = av.w;
        Bs[lc + 0][lr] = bv.x; Bs[lc + 1][lr] = bv.y;
        Bs[lc + 2][lr] = bv.z; Bs[lc + 3][lr] = bv.w;
        __syncthreads();
        #pragma unroll
        for (int c = 0; c < 16; c++) {
            float a[4], b[4];
            #pragma unroll
            for (int j = 0; j < 4; j++) { a[j] = As[c][ty * 4 + j]; b[j] = Bs[c][tx * 4 + j]; }
            #pragma unroll
            for (int j = 0; j < 4; j++)
                #pragma unroll
                for (int l = 0; l < 4; l++) acc[j][l] += a[j] * b[l];
        }
        __syncthreads();
    }
    #pragma unroll
    for (int j = 0; j < 4; j++)
        #pragma unroll
        for (int l = 0; l < 4; l++) {
            int m = m0 + ty * 4 + j, n = n0 + tx * 4 + l;
            float v = acc[j][l];
            if (RES) v += res[m * N + n];
            C[m * N + n] = v;
        }
}

// ---------------- fused gate/up GEMM with SiLU epilogue --------------------
// C[M,N] = silu(A@G^T) * (A@U^T)
__global__ void gateup_kernel(const float* __restrict__ A,
                              const float* __restrict__ G,
                              const float* __restrict__ U,
                              float* __restrict__ C,
                              int M, int N, int K) {
    __shared__ float As[16][64];
    __shared__ float Gs[16][64];
    __shared__ float Us[16][64];
    int tid = threadIdx.x;
    int m0 = blockIdx.y * 64, n0 = blockIdx.x * 64;
    float accg[4][4] = {}, accu[4][4] = {};
    int lr = tid >> 2;
    int lc = (tid & 3) * 4;
    int ty = tid >> 4, tx = tid & 15;

    for (int k0 = 0; k0 < K; k0 += 16) {
        float4 av = *(const float4*)&A[(m0 + lr) * K + k0 + lc];
        float4 gv = *(const float4*)&G[(n0 + lr) * K + k0 + lc];
        float4 uv = *(const float4*)&U[(n0 + lr) * K + k0 + lc];
        As[lc + 0][lr] = av.x; As[lc + 1][lr] = av.y; As[lc + 2][lr] = av.z; As[lc + 3][lr] = av.w;
        Gs[lc + 0][lr] = gv.x; Gs[lc + 1][lr] = gv.y; Gs[lc + 2][lr] = gv.z; Gs[lc + 3][lr] = gv.w;
        Us[lc + 0][lr] = uv.x; Us[lc + 1][lr] = uv.y; Us[lc + 2][lr] = uv.z; Us[lc + 3][lr] = uv.w;
        __syncthreads();
        #pragma unroll
        for (int c = 0; c < 16; c++) {
            float a[4], g[4], u[4];
            #pragma unroll
            for (int j = 0; j < 4; j++) {
                a[j] = As[c][ty * 4 + j];
                g[j] = Gs[c][tx * 4 + j];
                u[j] = Us[c][tx * 4 + j];
            }
            #pragma unroll
            for (int j = 0; j < 4; j++)
                #pragma unroll
                for (int l = 0; l < 4; l++) {
                    accg[j][l] += a[j] * g[l];
                    accu[j][l] += a[j] * u[l];
                }
        }
        __syncthreads();
    }
    #pragma unroll
    for (int j = 0; j < 4; j++)
        #pragma unroll
        for (int l = 0; l < 4; l++) {
            int m = m0 + ty * 4 + j, n = n0 + tx * 4 + l;
            float gg = accg[j][l];
            float sig = 1.0f / (1.0f + __expf(-gg));
            C[m * N + n] = gg * sig * accu[j][l];
        }
}

// ---------------- RoPE apply (in-place on q and k) --------------------------
__global__ void rope_kernel(float* __restrict__ q, float* __restrict__ k) {
    int idx = blockIdx.x * blockDim.x + threadIdx.x;  // S*HEADS*32
    if (idx >= S_TOK * HEADS * 32) return;
    int d = idx & 31;
    int h = (idx >> 5) & 15;
    int s = idx >> 9;
    float c  = g_cos[s * HD + d];
    float sn = g_sin[s * HD + d];
    int base = s * HID + h * HD;
    float q0 = q[base + d], q1 = q[base + d + 32];
    q[base + d]      = q0 * c - q1 * sn;
    q[base + d + 32] = q1 * c + q0 * sn;
    float k0 = k[base + d], k1 = k[base + d + 32];
    k[base + d]      = k0 * c - k1 * sn;
    k[base + d + 32] = k1 * c + k0 * sn;
}

// ---------------- attention: one CTA per (query, head) ----------------------
// Exploits block-diagonal mask exactly: query attends only to its own image.
__global__ void attn_kernel(const float* __restrict__ q,
                            const float* __restrict__ k,
                            const float* __restrict__ v,
                            float* __restrict__ o) {
    int s = blockIdx.x, h = blockIdx.y;
    int tid = threadIdx.x;   // 128
    int key0 = (s < S0) ? 0 : S0;
    int nk   = (s < S0) ? S0 : (S_TOK - S0);
    __shared__ float qs[HD];
    __shared__ float sc[S0];
    __shared__ float red[4];
    __shared__ float part[HD];
    if (tid < HD) qs[tid] = q[s * HID + h * HD + tid];
    __syncthreads();

    const float scale = 0.125f;   // 64^-0.5
    for (int kk = tid; kk < nk; kk += 128) {
        const float4* kp = (const float4*)&k[(key0 + kk) * HID + h * HD];
        float dot = 0.f;
        #pragma unroll
        for (int i = 0; i < 16; i++) {
            float4 kv = kp[i];
            dot += qs[4 * i] * kv.x + qs[4 * i + 1] * kv.y +
                   qs[4 * i + 2] * kv.z + qs[4 * i + 3] * kv.w;
        }
        sc[kk] = dot * scale;
    }
    __syncthreads();

    float lm = -1e30f;
    for (int kk = tid; kk < nk; kk += 128) lm = fmaxf(lm, sc[kk]);
    #pragma unroll
    for (int o2 = 16; o2 > 0; o2 >>= 1) lm = fmaxf(lm, __shfl_xor_sync(0xffffffffu, lm, o2));
    if ((tid & 31) == 0) red[tid >> 5] = lm;
    __syncthreads();
    float m = fmaxf(fmaxf(red[0], red[1]), fmaxf(red[2], red[3]));

    float ls = 0.f;
    for (int kk = tid; kk < nk; kk += 128) {
        float e = __expf(sc[kk] - m);
        sc[kk] = e;
        ls += e;
    }
    #pragma unroll
    for (int o2 = 16; o2 > 0; o2 >>= 1) ls += __shfl_xor_sync(0xffffffffu, ls, o2);
    __syncthreads();   // everyone done reading red[] for m
    if ((tid & 31) == 0) red[tid >> 5] = ls;
    __syncthreads();
    float inv = 1.0f / (red[0] + red[1] + red[2] + red[3]);

    // output: 2 groups of 64 threads split the key range
    int d = tid & 63, g = tid >> 6;
    float acc = 0.f;
    for (int kk = g; kk < nk; kk += 2)
        acc += sc[kk] * v[(key0 + kk) * HID + h * HD + d];
    if (g == 1) part[d] = acc;
    __syncthreads();
    if (g == 0) o[s * HID + h * HD + d] = (acc + part[d]) * inv;
}

// ---------------- host orchestration ---------------------------------------
extern "C" void kernel_launch(void* const* d_in, const int* in_sizes, int n_in,
                              void* d_out, int out_size) {
    const float* img0        = (const float*)d_in[0];
    const float* img1        = (const float*)d_in[1];
    const float* conv_w      = (const float*)d_in[2];
    const float* ln_pre_w    = (const float*)d_in[3];
    const float* attn_norm_w = (const float*)d_in[4];
    const float* q_w         = (const float*)d_in[5];
    const float* k_w         = (const float*)d_in[6];
    const float* v_w         = (const float*)d_in[7];
    const float* o_w         = (const float*)d_in[8];
    const float* ffn_norm_w  = (const float*)d_in[9];
    const float* gate_w      = (const float*)d_in[10];
    const float* up_w        = (const float*)d_in[11];
    const float* down_w      = (const float*)d_in[12];
    float* out = (float*)d_out;

    float *p_xpatch, *p_x, *p_h2, *p_hn, *p_q, *p_k, *p_v, *p_ao, *p_t;
    cudaGetSymbolAddress((void**)&p_xpatch, g_xpatch);
    cudaGetSymbolAddress((void**)&p_x,  g_x);
    cudaGetSymbolAddress((void**)&p_h2, g_h2);
    cudaGetSymbolAddress((void**)&p_hn, g_hn);
    cudaGetSymbolAddress((void**)&p_q,  g_q);
    cudaGetSymbolAddress((void**)&p_k,  g_k);
    cudaGetSymbolAddress((void**)&p_v,  g_v);
    cudaGetSymbolAddress((void**)&p_ao, g_ao);
    cudaGetSymbolAddress((void**)&p_t,  g_t);

    // patch embed: im2col + GEMM [1536,768] x [1024,768]^T -> g_h2
    im2col_kernel<<<(S_TOK * KPATCH + 255) / 256, 256>>>(img0, img1);
    gemm_kernel<0><<<dim3(HID / 64, S_TOK / 64), 256>>>(
        p_xpatch, conv_w, nullptr, p_h2, S_TOK, HID, KPATCH);

    // ln_pre
    rms_kernel<<<S_TOK, 256>>>(p_h2, ln_pre_w, p_x);

    // RoPE tables
    rope_table_kernel<<<S_TOK, 64>>>();

    dim3 gemm_grid_1k(HID / 64, S_TOK / 64);     // (16, 24)
    dim3 gemm_grid_4k(INTER / 64, S_TOK / 64);   // (64, 24)

    for (int l = 0; l < NLAYERS; l++) {
        const float* qw = q_w + (size_t)l * HID * HID;
        const float* kw = k_w + (size_t)l * HID * HID;
        const float* vw = v_w + (size_t)l * HID * HID;
        const float* ow = o_w + (size_t)l * HID * HID;
        const float* gw = gate_w + (size_t)l * INTER * HID;
        const float* uw = up_w   + (size_t)l * INTER * HID;
        const float* dw = down_w + (size_t)l * HID * INTER;

        // attn norm
        rms_kernel<<<S_TOK, 256>>>(p_x, attn_norm_w + l * HID, p_hn);

        // QKV projections
        gemm_kernel<0><<<gemm_grid_1k, 256>>>(p_hn, qw, nullptr, p_q, S_TOK, HID, HID);
        gemm_kernel<0><<<gemm_grid_1k, 256>>>(p_hn, kw, nullptr, p_k, S_TOK, HID, HID);
        gemm_kernel<0><<<gemm_grid_1k, 256>>>(p_hn, vw, nullptr, p_v, S_TOK, HID, HID);

        // RoPE
        rope_kernel<<<(S_TOK * HEADS * 32 + 255) / 256, 256>>>(p_q, p_k);

        // attention (block-diagonal, per-image key range)
        attn_kernel<<<dim3(S_TOK, HEADS), 128>>>(p_q, p_k, p_v, p_ao);

        // output projection + residual: h2 = x + ao @ ow^T
        gemm_kernel<1><<<gemm_grid_1k, 256>>>(p_ao, ow, p_x, p_h2, S_TOK, HID, HID);

        // ffn norm
        rms_kernel<<<S_TOK, 256>>>(p_h2, ffn_norm_w + l * HID, p_hn);

        // fused gate/up + SiLU
        gateup_kernel<<<gemm_grid_4k, 256>>>(p_hn, gw, uw, p_t, S_TOK, INTER, HID);

        // down projection + residual; last layer writes directly to d_out
        float* dst = (l == NLAYERS - 1) ? out : p_x;
        gemm_kernel<1><<<gemm_grid_1k, 256>>>(p_t, dw, p_h2, dst, S_TOK, HID, INTER);
    }
}

// round 2
// speedup vs baseline: 1.0003x; 1.0003x over previous
#include <cuda_runtime.h>
#include <math.h>

// ---------------- problem constants (fixed shapes from setup_inputs) -------
#define S_TOK 1536         // 1024 (img0 32x32) + 512 (img1 32x16) tokens
#define S0    1024
#define HID   1024
#define HEADS 16
#define HD    64
#define INTER 4096
#define NLAYERS 4
#define KPATCH 768         // 3*16*16
#define MAXSIDE 64

// ---------------- scratch (static device globals; no allocation) -----------
__device__ float g_xpatch[S_TOK * KPATCH];
__device__ float g_x [S_TOK * HID];
__device__ float g_h2[S_TOK * HID];
__device__ float g_hn[S_TOK * HID];
__device__ float g_q [S_TOK * HID];
__device__ float g_k [S_TOK * HID];
__device__ float g_v [S_TOK * HID];
__device__ float g_ao[S_TOK * HID];
__device__ float g_t [S_TOK * INTER];
__device__ float g_cos[S_TOK * HD];
__device__ float g_sin[S_TOK * HD];

// ---------------- im2col: build X_patch [S, 768] ---------------------------
__global__ void im2col_kernel(const float* __restrict__ img0,
                              const float* __restrict__ img1) {
    int idx = blockIdx.x * blockDim.x + threadIdx.x;
    if (idx >= S_TOK * KPATCH) return;
    int s = idx / KPATCH;
    int r = idx - s * KPATCH;
    int c  = r >> 8;          // channel 0..2
    int kh = (r >> 4) & 15;
    int kw = r & 15;
    float val;
    if (s < S0) {
        int ph = s >> 5, pw = s & 31;              // 32x32 grid, W=512
        val = img0[c * 512 * 512 + (ph * 16 + kh) * 512 + (pw * 16 + kw)];
    } else {
        int sp = s - S0;
        int ph = sp >> 4, pw = sp & 15;            // 32x16 grid, W=256
        val = img1[c * 512 * 256 + (ph * 16 + kh) * 256 + (pw * 16 + kw)];
    }
    g_xpatch[idx] = val;
}

// ---------------- RoPE table: cos/sin [S, 64] -------------------------------
__global__ void rope_table_kernel() {
    int s = blockIdx.x;
    int d = threadIdx.x;          // 0..63
    int ph, pw;
    if (s < S0) { ph = s >> 5; pw = s & 31; }
    else        { int sp = s - S0; ph = sp >> 4; pw = sp & 15; }
    int j = d & 31;
    float e, base;
    if (j < 16) { e = (4.0f * j) / 64.0f;             base = (float)ph; }
    else        { e = (2.0f + 4.0f * (j - 16)) / 64.0f; base = (float)pw; }
    float f = base * expf(-e * 9.2103403719761836f);  // 10000^(-e)
    g_cos[s * HD + d] = cosf(f);
    g_sin[s * HD + d] = sinf(f);
}

// ---------------- RMSNorm: y = x * rsqrt(mean(x^2)+eps) * w ----------------
__global__ void rms_kernel(const float* __restrict__ x,
                           const float* __restrict__ w,
                           float* __restrict__ y) {
    int s = blockIdx.x;
    int tid = threadIdx.x;        // 256
    const float* xr = x + s * HID;
    float ss = 0.f;
    #pragma unroll 4
    for (int i = tid; i < HID; i += 256) { float v = xr[i]; ss += v * v; }
    __shared__ float sh[8];
    #pragma unroll
    for (int o = 16; o > 0; o >>= 1) ss += __shfl_xor_sync(0xffffffffu, ss, o);
    if ((tid & 31) == 0) sh[tid >> 5] = ss;
    __syncthreads();
    if (tid < 8) {
        float v = sh[tid];
        #pragma unroll
        for (int o = 4; o > 0; o >>= 1) v += __shfl_xor_sync(0xffu, v, o);
        if (tid == 0) sh[0] = v;
    }
    __syncthreads();
    float r = rsqrtf(sh[0] * (1.0f / HID) + 1e-5f);
    for (int i = tid; i < HID; i += 256) y[s * HID + i] = xr[i] * r * w[i];
}

// ---------------- generic fp32 GEMM: C[M,N] = A[M,K] @ B[N,K]^T (+res) -----
// 64x64 tile, BK=16, 256 threads, 4x4 per thread
template<int RES>
__global__ void gemm_kernel(const float* __restrict__ A,
                            const float* __restrict__ B,
                            const float* __restrict__ res,
                            float* __restrict__ C,
                            int M, int N, int K) {
    __shared__ float As[16][64];
    __shared__ float Bs[16][64];
    int tid = threadIdx.x;
    int m0 = blockIdx.y * 64, n0 = blockIdx.x * 64;
    float acc[4][4] = {};
    int lr = tid >> 2;            // 0..63
    int lc = (tid & 3) * 4;       // 0,4,8,12
    int ty = tid >> 4, tx = tid & 15;

    for (int k0 = 0; k0 < K; k0 += 16) {
        float4 av = *(const float4*)&A[(m0 + lr) * K + k0 + lc];
        float4 bv = *(const float4*)&B[(n0 + lr) * K + k0 + lc];
        As[lc + 0][lr] = av.x; As[lc + 1][lr] = av.y;
        As[lc + 2][lr] = av.z; As[lc + 3][lr] = av.w;
        Bs[lc + 0][lr] = bv.x; Bs[lc + 1][lr] = bv.y;
        Bs[lc + 2][lr] = bv.z; Bs[lc + 3][lr] = bv.w;
        __syncthreads();
        #pragma unroll
        for (int c = 0; c < 16; c++) {
            float a[4], b[4];
            #pragma unroll
            for (int j = 0; j < 4; j++) { a[j] = As[c][ty * 4 + j]; b[j] = Bs[c][tx * 4 + j]; }
            #pragma unroll
            for (int j = 0; j < 4; j++)
                #pragma unroll
                for (int l = 0; l < 4; l++) acc[j][l] += a[j] * b[l];
        }
        __syncthreads();
    }
    #pragma unroll
    for (int j = 0; j < 4; j++)
        #pragma unroll
        for (int l = 0; l < 4; l++) {
            int m = m0 + ty * 4 + j, n = n0 + tx * 4 + l;
            float v = acc[j][l];
            if (RES) v += res[m * N + n];
            C[m * N + n] = v;
        }
}

// ---------------- fused gate/up GEMM with SiLU epilogue --------------------
// C[M,N] = silu(A@G^T) * (A@U^T)
__global__ void gateup_kernel(const float* __restrict__ A,
                              const float* __restrict__ G,
                              const float* __restrict__ U,
                              float* __restrict__ C,
                              int M, int N, int K) {
    __shared__ float As[16][64];
    __shared__ float Gs[16][64];
    __shared__ float Us[16][64];
    int tid = threadIdx.x;
    int m0 = blockIdx.y * 64, n0 = blockIdx.x * 64;
    float accg[4][4] = {}, accu[4][4] = {};
    int lr = tid >> 2;
    int lc = (tid & 3) * 4;
    int ty = tid >> 4, tx = tid & 15;

    for (int k0 = 0; k0 < K; k0 += 16) {
        float4 av = *(const float4*)&A[(m0 + lr) * K + k0 + lc];
        float4 gv = *(const float4*)&G[(n0 + lr) * K + k0 + lc];
        float4 uv = *(const float4*)&U[(n0 + lr) * K + k0 + lc];
        As[lc + 0][lr] = av.x; As[lc + 1][lr] = av.y; As[lc + 2][lr] = av.z; As[lc + 3][lr] = av.w;
        Gs[lc + 0][lr] = gv.x; Gs[lc + 1][lr] = gv.y; Gs[lc + 2][lr] = gv.z; Gs[lc + 3][lr] = gv.w;
        Us[lc + 0][lr] = uv.x; Us[lc + 1][lr] = uv.y; Us[lc + 2][lr] = uv.z; Us[lc + 3][lr] = uv.w;
        __syncthreads();
        #pragma unroll
        for (int c = 0; c < 16; c++) {
            float a[4], g[4], u[4];
            #pragma unroll
            for (int j = 0; j < 4; j++) {
                a[j] = As[c][ty * 4 + j];
                g[j] = Gs[c][tx * 4 + j];
                u[j] = Us[c][tx * 4 + j];
            }
            #pragma unroll
            for (int j = 0; j < 4; j++)
                #pragma unroll
                for (int l = 0; l < 4; l++) {
                    accg[j][l] += a[j] * g[l];
                    accu[j][l] += a[j] * u[l];
                }
        }
        __syncthreads();
    }
    #pragma unroll
    for (int j = 0; j < 4; j++)
        #pragma unroll
        for (int l = 0; l < 4; l++) {
            int m = m0 + ty * 4 + j, n = n0 + tx * 4 + l;
            float gg = accg[j][l];
            float sig = 1.0f / (1.0f + __expf(-gg));
            C[m * N + n] = gg * sig * accu[j][l];
        }
}

// ---------------- RoPE apply (in-place on q and k) --------------------------
__global__ void rope_kernel(float* __restrict__ q, float* __restrict__ k) {
    int idx = blockIdx.x * blockDim.x + threadIdx.x;  // S*HEADS*32
    if (idx >= S_TOK * HEADS * 32) return;
    int d = idx & 31;
    int h = (idx >> 5) & 15;
    int s = idx >> 9;
    float c  = g_cos[s * HD + d];
    float sn = g_sin[s * HD + d];
    int base = s * HID + h * HD;
    float q0 = q[base + d], q1 = q[base + d + 32];
    q[base + d]      = q0 * c - q1 * sn;
    q[base + d + 32] = q1 * c + q0 * sn;
    float k0 = k[base + d], k1 = k[base + d + 32];
    k[base + d]      = k0 * c - k1 * sn;
    k[base + d + 32] = k1 * c + k0 * sn;
}

// ---------------- attention: one CTA per (query, head) ----------------------
// Exploits block-diagonal mask exactly: query attends only to its own image.
__global__ void attn_kernel(const float* __restrict__ q,
                            const float* __restrict__ k,
                            const float* __restrict__ v,
                            float* __restrict__ o) {
    int s = blockIdx.x, h = blockIdx.y;
    int tid = threadIdx.x;   // 128
    int key0 = (s < S0) ? 0 : S0;
    int nk   = (s < S0) ? S0 : (S_TOK - S0);
    __shared__ float qs[HD];
    __shared__ float sc[S0];
    __shared__ float red[4];
    __shared__ float part[HD];
    if (tid < HD) qs[tid] = q[s * HID + h * HD + tid];
    __syncthreads();

    const float scale = 0.125f;   // 64^-0.5
    for (int kk = tid; kk < nk; kk += 128) {
        const float4* kp = (const float4*)&k[(key0 + kk) * HID + h * HD];
        float dot = 0.f;
        #pragma unroll
        for (int i = 0; i < 16; i++) {
            float4 kv = kp[i];
            dot += qs[4 * i] * kv.x + qs[4 * i + 1] * kv.y +
                   qs[4 * i + 2] * kv.z + qs[4 * i + 3] * kv.w;
        }
        sc[kk] = dot * scale;
    }
    __syncthreads();

    float lm = -1e30f;
    for (int kk = tid; kk < nk; kk += 128) lm = fmaxf(lm, sc[kk]);
    #pragma unroll
    for (int o2 = 16; o2 > 0; o2 >>= 1) lm = fmaxf(lm, __shfl_xor_sync(0xffffffffu, lm, o2));
    if ((tid & 31) == 0) red[tid >> 5] = lm;
    __syncthreads();
    float m = fmaxf(fmaxf(red[0], red[1]), fmaxf(red[2], red[3]));

    float ls = 0.f;
    for (int kk = tid; kk < nk; kk += 128) {
        float e = __expf(sc[kk] - m);
        sc[kk] = e;
        ls += e;
    }
    #pragma unroll
    for (int o2 = 16; o2 > 0; o2 >>= 1) ls += __shfl_xor_sync(0xffffffffu, ls, o2);
    __syncthreads();   // everyone done reading red[] for m
    if ((tid & 31) == 0) red[tid >> 5] = ls;
    __syncthreads();
    float inv = 1.0f / (red[0] + red[1] + red[2] + red[3]);

    // output: 2 groups of 64 threads split the key range
    int d = tid & 63, g = tid >> 6;
    float acc = 0.f;
    for (int kk = g; kk < nk; kk += 2)
        acc += sc[kk] * v[(key0 + kk) * HID + h * HD + d];
    if (g == 1) part[d] = acc;
    __syncthreads();
    if (g == 0) o[s * HID + h * HD + d] = (acc + part[d]) * inv;
}

// ---------------- host orchestration ---------------------------------------
extern "C" void kernel_launch(void* const* d_in, const int* in_sizes, int n_in,
                              void* d_out, int out_size) {
    const float* img0        = (const float*)d_in[0];
    const float* img1        = (const float*)d_in[1];
    const float* conv_w      = (const float*)d_in[2];
    const float* ln_pre_w    = (const float*)d_in[3];
    const float* attn_norm_w = (const float*)d_in[4];
    const float* q_w         = (const float*)d_in[5];
    const float* k_w         = (const float*)d_in[6];
    const float* v_w         = (const float*)d_in[7];
    const float* o_w         = (const float*)d_in[8];
    const float* ffn_norm_w  = (const float*)d_in[9];
    const float* gate_w      = (const float*)d_in[10];
    const float* up_w        = (const float*)d_in[11];
    const float* down_w      = (const float*)d_in[12];
    float* out = (float*)d_out;

    float *p_xpatch, *p_x, *p_h2, *p_hn, *p_q, *p_k, *p_v, *p_ao, *p_t;
    cudaGetSymbolAddress((void**)&p_xpatch, g_xpatch);
    cudaGetSymbolAddress((void**)&p_x,  g_x);
    cudaGetSymbolAddress((void**)&p_h2, g_h2);
    cudaGetSymbolAddress((void**)&p_hn, g_hn);
    cudaGetSymbolAddress((void**)&p_q,  g_q);
    cudaGetSymbolAddress((void**)&p_k,  g_k);
    cudaGetSymbolAddress((void**)&p_v,  g_v);
    cudaGetSymbolAddress((void**)&p_ao, g_ao);
    cudaGetSymbolAddress((void**)&p_t,  g_t);

    // patch embed: im2col + GEMM [1536,768] x [1024,768]^T -> g_h2
    im2col_kernel<<<(S_TOK * KPATCH + 255) / 256, 256>>>(img0, img1);
    gemm_kernel<0><<<dim3(HID / 64, S_TOK / 64), 256>>>(
        p_xpatch, conv_w, nullptr, p_h2, S_TOK, HID, KPATCH);

    // ln_pre
    rms_kernel<<<S_TOK, 256>>>(p_h2, ln_pre_w, p_x);

    // RoPE tables
    rope_table_kernel<<<S_TOK, 64>>>();

    dim3 gemm_grid_1k(HID / 64, S_TOK / 64);     // (16, 24)
    dim3 gemm_grid_4k(INTER / 64, S_TOK / 64);   // (64, 24)

    for (int l = 0; l < NLAYERS; l++) {
        const float* qw = q_w + (size_t)l * HID * HID;
        const float* kw = k_w + (size_t)l * HID * HID;
        const float* vw = v_w + (size_t)l * HID * HID;
        const float* ow = o_w + (size_t)l * HID * HID;
        const float* gw = gate_w + (size_t)l * INTER * HID;
        const float* uw = up_w   + (size_t)l * INTER * HID;
        const float* dw = down_w + (size_t)l * HID * INTER;

        // attn norm
        rms_kernel<<<S_TOK, 256>>>(p_x, attn_norm_w + l * HID, p_hn);

        // QKV projections
        gemm_kernel<0><<<gemm_grid_1k, 256>>>(p_hn, qw, nullptr, p_q, S_TOK, HID, HID);
        gemm_kernel<0><<<gemm_grid_1k, 256>>>(p_hn, kw, nullptr, p_k, S_TOK, HID, HID);
        gemm_kernel<0><<<gemm_grid_1k, 256>>>(p_hn, vw, nullptr, p_v, S_TOK, HID, HID);

        // RoPE
        rope_kernel<<<(S_TOK * HEADS * 32 + 255) / 256, 256>>>(p_q, p_k);

        // attention (block-diagonal, per-image key range)
        attn_kernel<<<dim3(S_TOK, HEADS), 128>>>(p_q, p_k, p_v, p_ao);

        // output projection + residual: h2 = x + ao @ ow^T
        gemm_kernel<1><<<gemm_grid_1k, 256>>>(p_ao, ow, p_x, p_h2, S_TOK, HID, HID);

        // ffn norm
        rms_kernel<<<S_TOK, 256>>>(p_h2, ffn_norm_w + l * HID, p_hn);

        // fused gate/up + SiLU
        gateup_kernel<<<gemm_grid_4k, 256>>>(p_hn, gw, uw, p_t, S_TOK, INTER, HID);

        // down projection + residual; last layer writes directly to d_out
        float* dst = (l == NLAYERS - 1) ? out : p_x;
        gemm_kernel<1><<<gemm_grid_1k, 256>>>(p_t, dw, p_h2, dst, S_TOK, HID, INTER);
    }
}

// round 3
// speedup vs baseline: 2.5996x; 2.5988x over previous
#include <cuda_runtime.h>
#include <math.h>
#include <stdint.h>

// ---------------- problem constants ----------------------------------------
#define S_TOK 1536
#define S0    1024
#define HID   1024
#define HEADS 16
#define HD    64
#define INTER 4096
#define NLAYERS 4
#define KPATCH 768

// ---------------- scratch --------------------------------------------------
__device__ float g_xpatch[S_TOK * KPATCH];
__device__ float g_x [S_TOK * HID];
__device__ float g_h2[S_TOK * HID];
__device__ float g_hn[S_TOK * HID];
__device__ float g_q [S_TOK * HID];
__device__ float g_k [S_TOK * HID];
__device__ float g_v [S_TOK * HID];
__device__ float g_ao[S_TOK * HID];
__device__ float g_t [S_TOK * INTER];
__device__ float g_cos[S_TOK * HD];
__device__ float g_sin[S_TOK * HD];

// ---------------- small helpers --------------------------------------------
__device__ __forceinline__ uint32_t f2tf32(float x) {
    uint32_t r;
    asm("cvt.rna.tf32.f32 %0, %1;" : "=r"(r) : "f"(x));
    return r;
}
__device__ __forceinline__ void mma_tf32(float c[4],
                                         uint32_t a0, uint32_t a1, uint32_t a2, uint32_t a3,
                                         uint32_t b0, uint32_t b1) {
    asm volatile(
        "mma.sync.aligned.m16n8k8.row.col.f32.tf32.tf32.f32 "
        "{%0,%1,%2,%3},{%4,%5,%6,%7},{%8,%9},{%0,%1,%2,%3};"
        : "+f"(c[0]), "+f"(c[1]), "+f"(c[2]), "+f"(c[3])
        : "r"(a0), "r"(a1), "r"(a2), "r"(a3), "r"(b0), "r"(b1));
}
__device__ __forceinline__ void cp16(void* smem_dst, const void* gsrc) {
    uint32_t d = (uint32_t)__cvta_generic_to_shared(smem_dst);
    asm volatile("cp.async.cg.shared.global [%0], [%1], 16;\n" :: "r"(d), "l"(gsrc));
}
#define CP_COMMIT() asm volatile("cp.async.commit_group;\n" ::: "memory")
#define CP_WAIT0()  asm volatile("cp.async.wait_group 0;\n" ::: "memory")
#define CP_WAIT1()  asm volatile("cp.async.wait_group 1;\n" ::: "memory")

// ---------------- im2col ----------------------------------------------------
__global__ void im2col_kernel(const float* __restrict__ img0,
                              const float* __restrict__ img1) {
    int idx = blockIdx.x * blockDim.x + threadIdx.x;
    if (idx >= S_TOK * KPATCH) return;
    int s = idx / KPATCH;
    int r = idx - s * KPATCH;
    int c  = r >> 8;
    int kh = (r >> 4) & 15;
    int kw = r & 15;
    float val;
    if (s < S0) {
        int ph = s >> 5, pw = s & 31;
        val = img0[c * 512 * 512 + (ph * 16 + kh) * 512 + (pw * 16 + kw)];
    } else {
        int sp = s - S0;
        int ph = sp >> 4, pw = sp & 15;
        val = img1[c * 512 * 256 + (ph * 16 + kh) * 256 + (pw * 16 + kw)];
    }
    g_xpatch[idx] = val;
}

// ---------------- RoPE table -------------------------------------------------
__global__ void rope_table_kernel() {
    int s = blockIdx.x;
    int d = threadIdx.x;  // 0..63
    int ph, pw;
    if (s < S0) { ph = s >> 5; pw = s & 31; }
    else        { int sp = s - S0; ph = sp >> 4; pw = sp & 15; }
    int j = d & 31;
    float e, base;
    if (j < 16) { e = (4.0f * j) / 64.0f;               base = (float)ph; }
    else        { e = (2.0f + 4.0f * (j - 16)) / 64.0f; base = (float)pw; }
    float f = base * expf(-e * 9.2103403719761836f);
    g_cos[s * HD + d] = cosf(f);
    g_sin[s * HD + d] = sinf(f);
}

// ---------------- RMSNorm ----------------------------------------------------
__global__ void rms_kernel(const float* __restrict__ x,
                           const float* __restrict__ w,
                           float* __restrict__ y) {
    int s = blockIdx.x;
    int tid = threadIdx.x;  // 256
    const float* xr = x + s * HID;
    float ss = 0.f;
    #pragma unroll 4
    for (int i = tid; i < HID; i += 256) { float v = xr[i]; ss += v * v; }
    __shared__ float sh[8];
    #pragma unroll
    for (int o = 16; o > 0; o >>= 1) ss += __shfl_xor_sync(0xffffffffu, ss, o);
    if ((tid & 31) == 0) sh[tid >> 5] = ss;
    __syncthreads();
    if (tid < 8) {
        float v = sh[tid];
        #pragma unroll
        for (int o = 4; o > 0; o >>= 1) v += __shfl_xor_sync(0xffu, v, o);
        if (tid == 0) sh[0] = v;
    }
    __syncthreads();
    float r = rsqrtf(sh[0] * (1.0f / HID) + 1e-5f);
    for (int i = tid; i < HID; i += 256) y[s * HID + i] = xr[i] * r * w[i];
}

// ---------------- tf32 tensor-core GEMM body --------------------------------
// C[M,N] = A[M,K] @ B[N,K]^T, tiles BM x 128 x 16, 256 threads, double-buffered
// EPI: 0=none, 1=+res, 2=silu(aux)*acc
template<int BM, int EPI>
__device__ __forceinline__ void gemm_body(
    const float* __restrict__ A, const float* __restrict__ B,
    const float* __restrict__ aux, float* __restrict__ C,
    int N, int K, float* As, float* Bs)
{
    constexpr int MT = BM / 32;       // m-tiles of 16 per warp
    constexpr int ASTG = BM * 20;     // floats per A stage
    constexpr int BSTG = 128 * 20;

    int tid = threadIdx.x;
    int warp = tid >> 5, lane = tid & 31;
    int gid = lane >> 2, tig = lane & 3;
    int wm = warp >> 2, wn = warp & 3;          // 2 x 4 warps
    int m0 = blockIdx.y * BM, n0 = blockIdx.x * 128;

    float acc[MT][4][4];
    #pragma unroll
    for (int i = 0; i < MT; i++)
        #pragma unroll
        for (int j = 0; j < 4; j++)
            #pragma unroll
            for (int l = 0; l < 4; l++) acc[i][j][l] = 0.f;

    const int KT = K >> 4;
    constexpr int NLOAD = (BM + 128) * 4;   // float4 slots per stage

    auto load_stage = [&](int kt, int buf) {
        int k0 = kt << 4;
        #pragma unroll
        for (int i = tid; i < NLOAD; i += 256) {
            if (i < BM * 4) {
                int r = i >> 2, c = (i & 3) << 2;
                cp16(&As[buf * ASTG + r * 20 + c], &A[(size_t)(m0 + r) * K + k0 + c]);
            } else {
                int i2 = i - BM * 4;
                int r = i2 >> 2, c = (i2 & 3) << 2;
                cp16(&Bs[buf * BSTG + r * 20 + c], &B[(size_t)(n0 + r) * K + k0 + c]);
            }
        }
    };

    load_stage(0, 0);
    CP_COMMIT();
    int buf = 0;
    for (int kt = 0; kt < KT; kt++) {
        if (kt + 1 < KT) { load_stage(kt + 1, buf ^ 1); CP_COMMIT(); CP_WAIT1(); }
        else             { CP_WAIT0(); }
        __syncthreads();
        const float* Ab = &As[buf * ASTG];
        const float* Bb = &Bs[buf * BSTG];
        #pragma unroll
        for (int ks = 0; ks < 2; ks++) {
            int col = ks * 8;
            uint32_t af[MT][4], bf[4][2];
            #pragma unroll
            for (int i = 0; i < MT; i++) {
                int r0 = wm * (BM / 2) + i * 16 + gid;
                af[i][0] = f2tf32(Ab[r0 * 20 + col + tig]);
                af[i][1] = f2tf32(Ab[(r0 + 8) * 20 + col + tig]);
                af[i][2] = f2tf32(Ab[r0 * 20 + col + tig + 4]);
                af[i][3] = f2tf32(Ab[(r0 + 8) * 20 + col + tig + 4]);
            }
            #pragma unroll
            for (int j = 0; j < 4; j++) {
                int n = wn * 32 + j * 8 + gid;
                bf[j][0] = f2tf32(Bb[n * 20 + col + tig]);
                bf[j][1] = f2tf32(Bb[n * 20 + col + tig + 4]);
            }
            #pragma unroll
            for (int i = 0; i < MT; i++)
                #pragma unroll
                for (int j = 0; j < 4; j++)
                    mma_tf32(acc[i][j], af[i][0], af[i][1], af[i][2], af[i][3],
                             bf[j][0], bf[j][1]);
        }
        buf ^= 1;
        __syncthreads();
    }

    // epilogue (float2 stores)
    #pragma unroll
    for (int i = 0; i < MT; i++) {
        #pragma unroll
        for (int j = 0; j < 4; j++) {
            int m = m0 + wm * (BM / 2) + i * 16 + gid;
            int n = n0 + wn * 32 + j * 8 + 2 * tig;
            #pragma unroll
            for (int half = 0; half < 2; half++) {
                int mm = m + half * 8;
                float v0 = acc[i][j][half * 2 + 0];
                float v1 = acc[i][j][half * 2 + 1];
                size_t off = (size_t)mm * N + n;
                if (EPI == 1) {
                    v0 += aux[off]; v1 += aux[off + 1];
                } else if (EPI == 2) {
                    float gate0 = aux[off], gate1 = aux[off + 1];
                    v0 *= gate0 / (1.0f + __expf(-gate0));
                    v1 *= gate1 / (1.0f + __expf(-gate1));
                }
                float2 o2; o2.x = v0; o2.y = v1;
                *(float2*)&C[off] = o2;
            }
        }
    }
}

template<int BM, int EPI>
__global__ void __launch_bounds__(256) gemm_tf32(
    const float* __restrict__ A, const float* __restrict__ B,
    const float* __restrict__ aux, float* __restrict__ C, int N, int K)
{
    __shared__ float As[2 * BM * 20];
    __shared__ float Bs[2 * 128 * 20];
    gemm_body<BM, EPI>(A, B, aux, C, N, K, As, Bs);
}

// batched QKV: grid.z selects weight/output
__global__ void __launch_bounds__(256) gemm_qkv(
    const float* __restrict__ A,
    const float* __restrict__ B0, const float* __restrict__ B1, const float* __restrict__ B2,
    float* __restrict__ C0, float* __restrict__ C1, float* __restrict__ C2, int K)
{
    __shared__ float As[2 * 64 * 20];
    __shared__ float Bs[2 * 128 * 20];
    const float* B = (blockIdx.z == 0) ? B0 : (blockIdx.z == 1) ? B1 : B2;
    float*       C = (blockIdx.z == 0) ? C0 : (blockIdx.z == 1) ? C1 : C2;
    gemm_body<64, 0>(A, B, nullptr, C, HID, K, As, Bs);
}

// ---------------- RoPE apply --------------------------------------------------
__global__ void rope_kernel(float* __restrict__ q, float* __restrict__ k) {
    int idx = blockIdx.x * blockDim.x + threadIdx.x;
    if (idx >= S_TOK * HEADS * 32) return;
    int d = idx & 31;
    int h = (idx >> 5) & 15;
    int s = idx >> 9;
    float c  = g_cos[s * HD + d];
    float sn = g_sin[s * HD + d];
    int base = s * HID + h * HD;
    float q0 = q[base + d], q1 = q[base + d + 32];
    q[base + d]      = q0 * c - q1 * sn;
    q[base + d + 32] = q1 * c + q0 * sn;
    float k0 = k[base + d], k1 = k[base + d + 32];
    k[base + d]      = k0 * c - k1 * sn;
    k[base + d + 32] = k1 * c + k0 * sn;
}

// ---------------- flash-style attention --------------------------------------
// grid (24 qtiles, 16 heads), 256 threads. 64 queries/CTA, 64-key tiles in smem.
// thread (q = tid>>2, kg = tid&3): scores for keys kg*16..+15, output dims kg*16..+15
__global__ void __launch_bounds__(256) attn_kernel(
    const float* __restrict__ q, const float* __restrict__ k,
    const float* __restrict__ v, float* __restrict__ o)
{
    __shared__ float4 Q4[64][16];
    __shared__ float4 K4[64][16];   // col swizzled by (row>>4)
    __shared__ float4 V4[64][16];

    int qt = blockIdx.x, h = blockIdx.y;
    int s0 = qt * 64;
    int key0 = (s0 < S0) ? 0 : S0;
    int nkt  = (s0 < S0) ? 16 : 8;

    int tid = threadIdx.x;
    int qq = tid >> 2, kg = tid & 3;

    // load Q tile
    for (int i = tid; i < 1024; i += 256) {
        int r = i >> 4, c = i & 15;
        Q4[r][c] = *(const float4*)&q[(size_t)(s0 + r) * HID + h * HD + c * 4];
    }

    float m_prev = -1e30f, lsum = 0.f;
    float oa[16];
    #pragma unroll
    for (int d = 0; d < 16; d++) oa[d] = 0.f;

    for (int kt = 0; kt < nkt; kt++) {
        __syncthreads();   // Q written / previous compute done
        for (int i = tid; i < 1024; i += 256) {
            int r = i >> 4, c = i & 15;
            size_t goff = (size_t)(key0 + kt * 64 + r) * HID + h * HD + c * 4;
            K4[r][c ^ (r >> 4)] = *(const float4*)&k[goff];
            V4[r][c]            = *(const float4*)&v[goff];
        }
        __syncthreads();

        // scores for 16 keys
        float s[16];
        #pragma unroll
        for (int i = 0; i < 16; i++) s[i] = 0.f;
        #pragma unroll
        for (int d4 = 0; d4 < 16; d4++) {
            float4 qv = Q4[qq][d4];
            #pragma unroll
            for (int kk = 0; kk < 16; kk++) {
                float4 kv = K4[kg * 16 + kk][d4 ^ kg];
                s[kk] += qv.x * kv.x + qv.y * kv.y + qv.z * kv.z + qv.w * kv.w;
            }
        }
        float mt = -1e30f;
        #pragma unroll
        for (int kk = 0; kk < 16; kk++) { s[kk] *= 0.125f; mt = fmaxf(mt, s[kk]); }
        mt = fmaxf(mt, __shfl_xor_sync(0xffffffffu, mt, 1));
        mt = fmaxf(mt, __shfl_xor_sync(0xffffffffu, mt, 2));
        float m_new = fmaxf(m_prev, mt);
        float alpha = __expf(m_prev - m_new);
        float ls = 0.f;
        #pragma unroll
        for (int kk = 0; kk < 16; kk++) { s[kk] = __expf(s[kk] - m_new); ls += s[kk]; }
        lsum = lsum * alpha + ls;
        #pragma unroll
        for (int d = 0; d < 16; d++) oa[d] *= alpha;
        m_prev = m_new;

        // O += P @ V  (P exchanged across quad via shfl)
        #pragma unroll
        for (int src = 0; src < 4; src++) {
            #pragma unroll
            for (int i = 0; i < 16; i++) {
                float pv = __shfl_sync(0xffffffffu, s[i], src, 4);
                int kk2 = src * 16 + i;
                float4 v0 = V4[kk2][kg * 4 + 0];
                float4 v1 = V4[kk2][kg * 4 + 1];
                float4 v2 = V4[kk2][kg * 4 + 2];
                float4 v3 = V4[kk2][kg * 4 + 3];
                oa[0]  += pv * v0.x; oa[1]  += pv * v0.y; oa[2]  += pv * v0.z; oa[3]  += pv * v0.w;
                oa[4]  += pv * v1.x; oa[5]  += pv * v1.y; oa[6]  += pv * v1.z; oa[7]  += pv * v1.w;
                oa[8]  += pv * v2.x; oa[9]  += pv * v2.y; oa[10] += pv * v2.z; oa[11] += pv * v2.w;
                oa[12] += pv * v3.x; oa[13] += pv * v3.y; oa[14] += pv * v3.z; oa[15] += pv * v3.w;
            }
        }
    }

    lsum += __shfl_xor_sync(0xffffffffu, lsum, 1);
    lsum += __shfl_xor_sync(0xffffffffu, lsum, 2);
    float inv = 1.0f / lsum;
    size_t obase = (size_t)(s0 + qq) * HID + h * HD + kg * 16;
    #pragma unroll
    for (int d4 = 0; d4 < 4; d4++) {
        float4 ov;
        ov.x = oa[d4 * 4 + 0] * inv; ov.y = oa[d4 * 4 + 1] * inv;
        ov.z = oa[d4 * 4 + 2] * inv; ov.w = oa[d4 * 4 + 3] * inv;
        *(float4*)&o[obase + d4 * 4] = ov;
    }
}

// ---------------- host orchestration ----------------------------------------
extern "C" void kernel_launch(void* const* d_in, const int* in_sizes, int n_in,
                              void* d_out, int out_size) {
    const float* img0        = (const float*)d_in[0];
    const float* img1        = (const float*)d_in[1];
    const float* conv_w      = (const float*)d_in[2];
    const float* ln_pre_w    = (const float*)d_in[3];
    const float* attn_norm_w = (const float*)d_in[4];
    const float* q_w         = (const float*)d_in[5];
    const float* k_w         = (const float*)d_in[6];
    const float* v_w         = (const float*)d_in[7];
    const float* o_w         = (const float*)d_in[8];
    const float* ffn_norm_w  = (const float*)d_in[9];
    const float* gate_w      = (const float*)d_in[10];
    const float* up_w        = (const float*)d_in[11];
    const float* down_w      = (const float*)d_in[12];
    float* out = (float*)d_out;

    float *p_xpatch, *p_x, *p_h2, *p_hn, *p_q, *p_k, *p_v, *p_ao, *p_t;
    cudaGetSymbolAddress((void**)&p_xpatch, g_xpatch);
    cudaGetSymbolAddress((void**)&p_x,  g_x);
    cudaGetSymbolAddress((void**)&p_h2, g_h2);
    cudaGetSymbolAddress((void**)&p_hn, g_hn);
    cudaGetSymbolAddress((void**)&p_q,  g_q);
    cudaGetSymbolAddress((void**)&p_k,  g_k);
    cudaGetSymbolAddress((void**)&p_v,  g_v);
    cudaGetSymbolAddress((void**)&p_ao, g_ao);
    cudaGetSymbolAddress((void**)&p_t,  g_t);

    dim3 grid_n1k(HID / 128, S_TOK / 64);     // (8, 24)  BM=64
    dim3 grid_qkv(HID / 128, S_TOK / 64, 3);  // (8, 24, 3)
    dim3 grid_n4k(INTER / 128, S_TOK / 128);  // (32, 12) BM=128

    // patch embed
    im2col_kernel<<<(S_TOK * KPATCH + 255) / 256, 256>>>(img0, img1);
    gemm_tf32<64, 0><<<grid_n1k, 256>>>(p_xpatch, conv_w, nullptr, p_h2, HID, KPATCH);

    rms_kernel<<<S_TOK, 256>>>(p_h2, ln_pre_w, p_x);
    rope_table_kernel<<<S_TOK, 64>>>();

    for (int l = 0; l < NLAYERS; l++) {
        const float* qw = q_w + (size_t)l * HID * HID;
        const float* kw = k_w + (size_t)l * HID * HID;
        const float* vw = v_w + (size_t)l * HID * HID;
        const float* ow = o_w + (size_t)l * HID * HID;
        const float* gw = gate_w + (size_t)l * INTER * HID;
        const float* uw = up_w   + (size_t)l * INTER * HID;
        const float* dw = down_w + (size_t)l * HID * INTER;

        rms_kernel<<<S_TOK, 256>>>(p_x, attn_norm_w + l * HID, p_hn);

        gemm_qkv<<<grid_qkv, 256>>>(p_hn, qw, kw, vw, p_q, p_k, p_v, HID);

        rope_kernel<<<(S_TOK * HEADS * 32 + 255) / 256, 256>>>(p_q, p_k);

        attn_kernel<<<dim3(S_TOK / 64, HEADS), 256>>>(p_q, p_k, p_v, p_ao);

        gemm_tf32<64, 1><<<grid_n1k, 256>>>(p_ao, ow, p_x, p_h2, HID, HID);

        rms_kernel<<<S_TOK, 256>>>(p_h2, ffn_norm_w + l * HID, p_hn);

        // gate then up (epilogue: silu(gate)*up, in-place on g_t)
        gemm_tf32<128, 0><<<grid_n4k, 256>>>(p_hn, gw, nullptr, p_t, INTER, HID);
        gemm_tf32<128, 2><<<grid_n4k, 256>>>(p_hn, uw, p_t, p_t, INTER, HID);

        float* dst = (l == NLAYERS - 1) ? out : p_x;
        gemm_tf32<64, 1><<<grid_n1k, 256>>>(p_t, dw, p_h2, dst, HID, INTER);
    }
}

// round 5
// speedup vs baseline: 2.7274x; 1.0492x over previous
#include <cuda_runtime.h>
#include <math.h>
#include <stdint.h>

// ---------------- problem constants ----------------------------------------
#define S_TOK 1536
#define S0    1024
#define HID   1024
#define HEADS 16
#define HD    64
#define INTER 4096
#define NLAYERS 4
#define KPATCH 768

// ---------------- scratch ---------------------------------------------------
__device__ float g_xpatch[S_TOK * KPATCH];
__device__ float g_x [S_TOK * HID];
__device__ float g_h2[S_TOK * HID];
__device__ float g_hn[S_TOK * HID];
__device__ float g_q [S_TOK * HID];
__device__ float g_k [S_TOK * HID];
__device__ float g_v [S_TOK * HID];
__device__ float g_ao[S_TOK * HID];
__device__ float g_t [S_TOK * INTER];
__device__ float g_cos[S_TOK * HD];
__device__ float g_sin[S_TOK * HD];
// tf32-pre-rounded weight copies
__device__ float g_wconv[HID * KPATCH];
__device__ float g_wq[NLAYERS * HID * HID];
__device__ float g_wk[NLAYERS * HID * HID];
__device__ float g_wv[NLAYERS * HID * HID];
__device__ float g_wo[NLAYERS * HID * HID];
__device__ float g_wg[NLAYERS * INTER * HID];
__device__ float g_wu[NLAYERS * INTER * HID];
__device__ float g_wd[NLAYERS * HID * INTER];

// ---------------- helpers ----------------------------------------------------
__device__ __forceinline__ float tf32r(float x) {
    uint32_t r;
    asm("cvt.rna.tf32.f32 %0, %1;" : "=r"(r) : "f"(x));
    return __uint_as_float(r);
}
__device__ __forceinline__ void mma_tf32(float c[4],
                                         uint32_t a0, uint32_t a1, uint32_t a2, uint32_t a3,
                                         uint32_t b0, uint32_t b1) {
    asm volatile(
        "mma.sync.aligned.m16n8k8.row.col.f32.tf32.tf32.f32 "
        "{%0,%1,%2,%3},{%4,%5,%6,%7},{%8,%9},{%0,%1,%2,%3};"
        : "+f"(c[0]), "+f"(c[1]), "+f"(c[2]), "+f"(c[3])
        : "r"(a0), "r"(a1), "r"(a2), "r"(a3), "r"(b0), "r"(b1));
}
__device__ __forceinline__ void cp16(void* smem_dst, const void* gsrc) {
    uint32_t d = (uint32_t)__cvta_generic_to_shared(smem_dst);
    asm volatile("cp.async.cg.shared.global [%0], [%1], 16;\n" :: "r"(d), "l"(gsrc));
}
#define CP_COMMIT() asm volatile("cp.async.commit_group;\n" ::: "memory")
#define CP_WAIT0()  asm volatile("cp.async.wait_group 0;\n" ::: "memory")
#define CP_WAIT1()  asm volatile("cp.async.wait_group 1;\n" ::: "memory")
#define CP_WAIT2()  asm volatile("cp.async.wait_group 2;\n" ::: "memory")

// ---------------- weight pre-round ------------------------------------------
__global__ void round_tf32_kernel(const float* __restrict__ x, float* __restrict__ y, int n4) {
    int i = blockIdx.x * blockDim.x + threadIdx.x;
    if (i >= n4) return;
    float4 v = ((const float4*)x)[i];
    v.x = tf32r(v.x); v.y = tf32r(v.y); v.z = tf32r(v.z); v.w = tf32r(v.w);
    ((float4*)y)[i] = v;
}

// ---------------- im2col (tf32-rounded) ---------------------------------------
__global__ void im2col_kernel(const float* __restrict__ img0,
                              const float* __restrict__ img1) {
    int idx = blockIdx.x * blockDim.x + threadIdx.x;
    if (idx >= S_TOK * KPATCH) return;
    int s = idx / KPATCH;
    int r = idx - s * KPATCH;
    int c  = r >> 8;
    int kh = (r >> 4) & 15;
    int kw = r & 15;
    float val;
    if (s < S0) {
        int ph = s >> 5, pw = s & 31;
        val = img0[c * 512 * 512 + (ph * 16 + kh) * 512 + (pw * 16 + kw)];
    } else {
        int sp = s - S0;
        int ph = sp >> 4, pw = sp & 15;
        val = img1[c * 512 * 256 + (ph * 16 + kh) * 256 + (pw * 16 + kw)];
    }
    g_xpatch[idx] = tf32r(val);
}

// ---------------- RoPE table ---------------------------------------------------
__global__ void rope_table_kernel() {
    int s = blockIdx.x;
    int d = threadIdx.x;  // 0..63
    int ph, pw;
    if (s < S0) { ph = s >> 5; pw = s & 31; }
    else        { int sp = s - S0; ph = sp >> 4; pw = sp & 15; }
    int j = d & 31;
    float e, base;
    if (j < 16) { e = (4.0f * j) / 64.0f;               base = (float)ph; }
    else        { e = (2.0f + 4.0f * (j - 16)) / 64.0f; base = (float)pw; }
    float f = base * expf(-e * 9.2103403719761836f);
    g_cos[s * HD + d] = cosf(f);
    g_sin[s * HD + d] = sinf(f);
}

// ---------------- RMSNorm (tf32-rounded output) ---------------------------------
__global__ void rms_kernel(const float* __restrict__ x,
                           const float* __restrict__ w,
                           float* __restrict__ y) {
    int s = blockIdx.x;
    int tid = threadIdx.x;  // 256
    const float* xr = x + s * HID;
    float ss = 0.f;
    #pragma unroll 4
    for (int i = tid; i < HID; i += 256) { float v = xr[i]; ss += v * v; }
    __shared__ float sh[8];
    #pragma unroll
    for (int o = 16; o > 0; o >>= 1) ss += __shfl_xor_sync(0xffffffffu, ss, o);
    if ((tid & 31) == 0) sh[tid >> 5] = ss;
    __syncthreads();
    if (tid < 8) {
        float v = sh[tid];
        #pragma unroll
        for (int o = 4; o > 0; o >>= 1) v += __shfl_xor_sync(0xffu, v, o);
        if (tid == 0) sh[0] = v;
    }
    __syncthreads();
    float r = rsqrtf(sh[0] * (1.0f / HID) + 1e-5f);
    for (int i = tid; i < HID; i += 256) y[s * HID + i] = tf32r(xr[i] * r * w[i]);
}

// ---------------- tf32 tensor-core GEMM (no in-loop cvt, 3-stage pipeline) ----
// C[M,N] = A[M,K] @ B[N,K]^T. Operands MUST be tf32-pre-rounded fp32.
// Tiles BM x 128 x 16, 256 threads (8 warps: 2m x 4n), 4x4 m16n8k8 per warp.
// EPI: 0=none, 1=+aux residual, 2=silu(aux)*acc (tf32-rounded store)
template<int BM, int EPI>
__device__ __forceinline__ void gemm_body(
    const float* __restrict__ A, const float* __restrict__ B,
    const float* __restrict__ aux, float* __restrict__ C,
    int N, int K, float* tiles)
{
    constexpr int MT = BM / 32;          // 16-row m-tiles per warp
    constexpr int ASTG = BM * 20;
    constexpr int BSTG = 128 * 20;
    constexpr int STG  = ASTG + BSTG;

    int tid = threadIdx.x;
    int warp = tid >> 5, lane = tid & 31;
    int gid = lane >> 2, tig = lane & 3;
    int wm = warp >> 2, wn = warp & 3;
    int m0 = blockIdx.y * BM, n0 = blockIdx.x * 128;

    float acc[MT][4][4];
    #pragma unroll
    for (int i = 0; i < MT; i++)
        #pragma unroll
        for (int j = 0; j < 4; j++)
            #pragma unroll
            for (int l = 0; l < 4; l++) acc[i][j][l] = 0.f;

    const int KT = K >> 4;
    constexpr int NLOAD = (BM + 128) * 4;

    auto load_stage = [&](int kt, int s) {
        int k0 = kt << 4;
        float* As = tiles + s * STG;
        float* Bs = As + ASTG;
        #pragma unroll
        for (int i = tid; i < NLOAD; i += 256) {
            if (i < BM * 4) {
                int r = i >> 2, c = (i & 3) << 2;
                cp16(&As[r * 20 + c], &A[(size_t)(m0 + r) * K + k0 + c]);
            } else {
                int i2 = i - BM * 4;
                int r = i2 >> 2, c = (i2 & 3) << 2;
                cp16(&Bs[r * 20 + c], &B[(size_t)(n0 + r) * K + k0 + c]);
            }
        }
        CP_COMMIT();
    };

    load_stage(0, 0);
    load_stage(1, 1);

    for (int kt = 0; kt < KT; kt++) {
        int s = kt % 3;
        if (kt + 2 < KT) { load_stage(kt + 2, (kt + 2) % 3); CP_WAIT2(); }
        else if (kt + 2 == KT) { CP_WAIT1(); }
        else { CP_WAIT0(); }
        __syncthreads();
        const float* Ab = tiles + s * STG;
        const float* Bb = Ab + ASTG;
        #pragma unroll
        for (int ks = 0; ks < 2; ks++) {
            int col = ks * 8;
            uint32_t af[MT][4], bf[4][2];
            #pragma unroll
            for (int i = 0; i < MT; i++) {
                int r0 = wm * (BM / 2) + i * 16 + gid;
                af[i][0] = __float_as_uint(Ab[r0 * 20 + col + tig]);
                af[i][1] = __float_as_uint(Ab[(r0 + 8) * 20 + col + tig]);
                af[i][2] = __float_as_uint(Ab[r0 * 20 + col + tig + 4]);
                af[i][3] = __float_as_uint(Ab[(r0 + 8) * 20 + col + tig + 4]);
            }
            #pragma unroll
            for (int j = 0; j < 4; j++) {
                int n = wn * 32 + j * 8 + gid;
                bf[j][0] = __float_as_uint(Bb[n * 20 + col + tig]);
                bf[j][1] = __float_as_uint(Bb[n * 20 + col + tig + 4]);
            }
            #pragma unroll
            for (int i = 0; i < MT; i++)
                #pragma unroll
                for (int j = 0; j < 4; j++)
                    mma_tf32(acc[i][j], af[i][0], af[i][1], af[i][2], af[i][3],
                             bf[j][0], bf[j][1]);
        }
        __syncthreads();
    }

    // epilogue
    #pragma unroll
    for (int i = 0; i < MT; i++) {
        #pragma unroll
        for (int j = 0; j < 4; j++) {
            int m = m0 + wm * (BM / 2) + i * 16 + gid;
            int n = n0 + wn * 32 + j * 8 + 2 * tig;
            #pragma unroll
            for (int half = 0; half < 2; half++) {
                int mm = m + half * 8;
                float v0 = acc[i][j][half * 2 + 0];
                float v1 = acc[i][j][half * 2 + 1];
                size_t off = (size_t)mm * N + n;
                if (EPI == 1) {
                    v0 += aux[off]; v1 += aux[off + 1];
                } else if (EPI == 2) {
                    float g0 = aux[off], g1 = aux[off + 1];
                    v0 = tf32r(v0 * g0 / (1.0f + __expf(-g0)));
                    v1 = tf32r(v1 * g1 / (1.0f + __expf(-g1)));
                }
                float2 o2; o2.x = v0; o2.y = v1;
                *(float2*)&C[off] = o2;
            }
        }
    }
}

template<int BM, int EPI>
__global__ void __launch_bounds__(256) gemm_tf32(
    const float* __restrict__ A, const float* __restrict__ B,
    const float* __restrict__ aux, float* __restrict__ C, int N, int K)
{
    extern __shared__ float tiles[];
    gemm_body<BM, EPI>(A, B, aux, C, N, K, tiles);
}

__global__ void __launch_bounds__(256) gemm_qkv(
    const float* __restrict__ A,
    const float* __restrict__ B0, const float* __restrict__ B1, const float* __restrict__ B2,
    float* __restrict__ C0, float* __restrict__ C1, float* __restrict__ C2, int K)
{
    extern __shared__ float tiles[];
    const float* B = (blockIdx.z == 0) ? B0 : (blockIdx.z == 1) ? B1 : B2;
    float*       C = (blockIdx.z == 0) ? C0 : (blockIdx.z == 1) ? C1 : C2;
    gemm_body<64, 0>(A, B, nullptr, C, HID, K, tiles);
}

// ---------------- RoPE apply ----------------------------------------------------
__global__ void rope_kernel(float* __restrict__ q, float* __restrict__ k) {
    int idx = blockIdx.x * blockDim.x + threadIdx.x;
    if (idx >= S_TOK * HEADS * 32) return;
    int d = idx & 31;
    int h = (idx >> 5) & 15;
    int s = idx >> 9;
    float c  = g_cos[s * HD + d];
    float sn = g_sin[s * HD + d];
    int base = s * HID + h * HD;
    float q0 = q[base + d], q1 = q[base + d + 32];
    q[base + d]      = q0 * c - q1 * sn;
    q[base + d + 32] = q1 * c + q0 * sn;
    float k0 = k[base + d], k1 = k[base + d + 32];
    k[base + d]      = k0 * c - k1 * sn;
    k[base + d + 32] = k1 * c + k0 * sn;
}

// ---------------- flash attention (output tf32-rounded) ---------------------------
__global__ void __launch_bounds__(256) attn_kernel(
    const float* __restrict__ q, const float* __restrict__ k,
    const float* __restrict__ v, float* __restrict__ o)
{
    __shared__ float4 Q4[64][16];
    __shared__ float4 K4[64][16];
    __shared__ float4 V4[64][16];

    int qt = blockIdx.x, h = blockIdx.y;
    int s0 = qt * 64;
    int key0 = (s0 < S0) ? 0 : S0;
    int nkt  = (s0 < S0) ? 16 : 8;

    int tid = threadIdx.x;
    int qq = tid >> 2, kg = tid & 3;

    for (int i = tid; i < 1024; i += 256) {
        int r = i >> 4, c = i & 15;
        Q4[r][c] = *(const float4*)&q[(size_t)(s0 + r) * HID + h * HD + c * 4];
    }

    float m_prev = -1e30f, lsum = 0.f;
    float oa[16];
    #pragma unroll
    for (int d = 0; d < 16; d++) oa[d] = 0.f;

    for (int kt = 0; kt < nkt; kt++) {
        __syncthreads();
        for (int i = tid; i < 1024; i += 256) {
            int r = i >> 4, c = i & 15;
            size_t goff = (size_t)(key0 + kt * 64 + r) * HID + h * HD + c * 4;
            K4[r][c ^ (r >> 4)] = *(const float4*)&k[goff];
            V4[r][c]            = *(const float4*)&v[goff];
        }
        __syncthreads();

        float s[16];
        #pragma unroll
        for (int i = 0; i < 16; i++) s[i] = 0.f;
        #pragma unroll
        for (int d4 = 0; d4 < 16; d4++) {
            float4 qv = Q4[qq][d4];
            #pragma unroll
            for (int kk = 0; kk < 16; kk++) {
                float4 kv = K4[kg * 16 + kk][d4 ^ kg];
                s[kk] += qv.x * kv.x + qv.y * kv.y + qv.z * kv.z + qv.w * kv.w;
            }
        }
        float mt = -1e30f;
        #pragma unroll
        for (int kk = 0; kk < 16; kk++) { s[kk] *= 0.125f; mt = fmaxf(mt, s[kk]); }
        mt = fmaxf(mt, __shfl_xor_sync(0xffffffffu, mt, 1));
        mt = fmaxf(mt, __shfl_xor_sync(0xffffffffu, mt, 2));
        float m_new = fmaxf(m_prev, mt);
        float alpha = __expf(m_prev - m_new);
        float ls = 0.f;
        #pragma unroll
        for (int kk = 0; kk < 16; kk++) { s[kk] = __expf(s[kk] - m_new); ls += s[kk]; }
        lsum = lsum * alpha + ls;
        #pragma unroll
        for (int d = 0; d < 16; d++) oa[d] *= alpha;
        m_prev = m_new;

        #pragma unroll
        for (int src = 0; src < 4; src++) {
            #pragma unroll
            for (int i = 0; i < 16; i++) {
                float pv = __shfl_sync(0xffffffffu, s[i], src, 4);
                int kk2 = src * 16 + i;
                float4 v0 = V4[kk2][kg * 4 + 0];
                float4 v1 = V4[kk2][kg * 4 + 1];
                float4 v2 = V4[kk2][kg * 4 + 2];
                float4 v3 = V4[kk2][kg * 4 + 3];
                oa[0]  += pv * v0.x; oa[1]  += pv * v0.y; oa[2]  += pv * v0.z; oa[3]  += pv * v0.w;
                oa[4]  += pv * v1.x; oa[5]  += pv * v1.y; oa[6]  += pv * v1.z; oa[7]  += pv * v1.w;
                oa[8]  += pv * v2.x; oa[9]  += pv * v2.y; oa[10] += pv * v2.z; oa[11] += pv * v2.w;
                oa[12] += pv * v3.x; oa[13] += pv * v3.y; oa[14] += pv * v3.z; oa[15] += pv * v3.w;
            }
        }
    }

    lsum += __shfl_xor_sync(0xffffffffu, lsum, 1);
    lsum += __shfl_xor_sync(0xffffffffu, lsum, 2);
    float inv = 1.0f / lsum;
    size_t obase = (size_t)(s0 + qq) * HID + h * HD + kg * 16;
    #pragma unroll
    for (int d4 = 0; d4 < 4; d4++) {
        float4 ov;
        ov.x = tf32r(oa[d4 * 4 + 0] * inv); ov.y = tf32r(oa[d4 * 4 + 1] * inv);
        ov.z = tf32r(oa[d4 * 4 + 2] * inv); ov.w = tf32r(oa[d4 * 4 + 3] * inv);
        *(float4*)&o[obase + d4 * 4] = ov;
    }
}

// ---------------- host orchestration ---------------------------------------------
extern "C" void kernel_launch(void* const* d_in, const int* in_sizes, int n_in,
                              void* d_out, int out_size) {
    const float* img0        = (const float*)d_in[0];
    const float* img1        = (const float*)d_in[1];
    const float* conv_w      = (const float*)d_in[2];
    const float* ln_pre_w    = (const float*)d_in[3];
    const float* attn_norm_w = (const float*)d_in[4];
    const float* q_w         = (const float*)d_in[5];
    const float* k_w         = (const float*)d_in[6];
    const float* v_w         = (const float*)d_in[7];
    const float* o_w         = (const float*)d_in[8];
    const float* ffn_norm_w  = (const float*)d_in[9];
    const float* gate_w      = (const float*)d_in[10];
    const float* up_w        = (const float*)d_in[11];
    const float* down_w      = (const float*)d_in[12];
    float* out = (float*)d_out;

    float *p_xpatch, *p_x, *p_h2, *p_hn, *p_q, *p_k, *p_v, *p_ao, *p_t;
    float *p_wconv, *p_wq, *p_wk, *p_wv, *p_wo, *p_wg, *p_wu, *p_wd;
    cudaGetSymbolAddress((void**)&p_xpatch, g_xpatch);
    cudaGetSymbolAddress((void**)&p_x,  g_x);
    cudaGetSymbolAddress((void**)&p_h2, g_h2);
    cudaGetSymbolAddress((void**)&p_hn, g_hn);
    cudaGetSymbolAddress((void**)&p_q,  g_q);
    cudaGetSymbolAddress((void**)&p_k,  g_k);
    cudaGetSymbolAddress((void**)&p_v,  g_v);
    cudaGetSymbolAddress((void**)&p_ao, g_ao);
    cudaGetSymbolAddress((void**)&p_t,  g_t);
    cudaGetSymbolAddress((void**)&p_wconv, g_wconv);
    cudaGetSymbolAddress((void**)&p_wq, g_wq);
    cudaGetSymbolAddress((void**)&p_wk, g_wk);
    cudaGetSymbolAddress((void**)&p_wv, g_wv);
    cudaGetSymbolAddress((void**)&p_wo, g_wo);
    cudaGetSymbolAddress((void**)&p_wg, g_wg);
    cudaGetSymbolAddress((void**)&p_wu, g_wu);
    cudaGetSymbolAddress((void**)&p_wd, g_wd);

    // dynamic smem: 3 stages of (BM+128)*20 floats
    const int SMEM64  = 3 * (64  + 128) * 20 * 4;   // 46080
    const int SMEM128 = 3 * (128 + 128) * 20 * 4;   // 61440
    cudaFuncSetAttribute(gemm_tf32<64, 0>,  cudaFuncAttributeMaxDynamicSharedMemorySize, SMEM64);
    cudaFuncSetAttribute(gemm_tf32<64, 1>,  cudaFuncAttributeMaxDynamicSharedMemorySize, SMEM64);
    cudaFuncSetAttribute(gemm_tf32<128, 0>, cudaFuncAttributeMaxDynamicSharedMemorySize, SMEM128);
    cudaFuncSetAttribute(gemm_tf32<128, 2>, cudaFuncAttributeMaxDynamicSharedMemorySize, SMEM128);
    cudaFuncSetAttribute(gemm_qkv,          cudaFuncAttributeMaxDynamicSharedMemorySize, SMEM64);

    // pre-round all weights to tf32 (removes cvt from GEMM hot loop)
    {
        auto rnd = [&](const float* src, float* dst, int n) {
            round_tf32_kernel<<<(n / 4 + 255) / 256, 256>>>(src, dst, n / 4);
        };
        rnd(conv_w, p_wconv, HID * KPATCH);
        rnd(q_w,    p_wq, NLAYERS * HID * HID);
        rnd(k_w,    p_wk, NLAYERS * HID * HID);
        rnd(v_w,    p_wv, NLAYERS * HID * HID);
        rnd(o_w,    p_wo, NLAYERS * HID * HID);
        rnd(gate_w, p_wg, NLAYERS * INTER * HID);
        rnd(up_w,   p_wu, NLAYERS * INTER * HID);
        rnd(down_w, p_wd, NLAYERS * HID * INTER);
    }

    dim3 grid_n1k(HID / 128, S_TOK / 64);       // (8, 24)   BM=64
    dim3 grid_qkv(HID / 128, S_TOK / 64, 3);    // (8, 24, 3)
    dim3 grid_n4k(INTER / 128, S_TOK / 128);    // (32, 12)  BM=128

    // patch embed
    im2col_kernel<<<(S_TOK * KPATCH + 255) / 256, 256>>>(img0, img1);
    gemm_tf32<64, 0><<<grid_n1k, 256, SMEM64>>>(p_xpatch, p_wconv, nullptr, p_h2, HID, KPATCH);

    rms_kernel<<<S_TOK, 256>>>(p_h2, ln_pre_w, p_x);
    rope_table_kernel<<<S_TOK, 64>>>();

    for (int l = 0; l < NLAYERS; l++) {
        const float* qw = p_wq + (size_t)l * HID * HID;
        const float* kw = p_wk + (size_t)l * HID * HID;
        const float* vw = p_wv + (size_t)l * HID * HID;
        const float* ow = p_wo + (size_t)l * HID * HID;
        const float* gw = p_wg + (size_t)l * INTER * HID;
        const float* uw = p_wu + (size_t)l * INTER * HID;
        const float* dw = p_wd + (size_t)l * HID * INTER;

        rms_kernel<<<S_TOK, 256>>>(p_x, attn_norm_w + l * HID, p_hn);

        gemm_qkv<<<grid_qkv, 256, SMEM64>>>(p_hn, qw, kw, vw, p_q, p_k, p_v, HID);

        rope_kernel<<<(S_TOK * HEADS * 32 + 255) / 256, 256>>>(p_q, p_k);

        attn_kernel<<<dim3(S_TOK / 64, HEADS), 256>>>(p_q, p_k, p_v, p_ao);

        gemm_tf32<64, 1><<<grid_n1k, 256, SMEM64>>>(p_ao, ow, p_x, p_h2, HID, HID);

        rms_kernel<<<S_TOK, 256>>>(p_h2, ffn_norm_w + l * HID, p_hn);

        gemm_tf32<128, 0><<<grid_n4k, 256, SMEM128>>>(p_hn, gw, nullptr, p_t, INTER, HID);
        gemm_tf32<128, 2><<<grid_n4k, 256, SMEM128>>>(p_hn, uw, p_t, p_t, INTER, HID);

        float* dst = (l == NLAYERS - 1) ? out : p_x;
        gemm_tf32<64, 1><<<grid_n1k, 256, SMEM64>>>(p_t, dw, p_h2, dst, HID, INTER);
    }
}

// round 6
// speedup vs baseline: 4.7580x; 1.7445x over previous
#include <cuda_runtime.h>
#include <math.h>
#include <stdint.h>

// ---------------- problem constants ----------------------------------------
#define S_TOK 1536
#define S0    1024
#define HID   1024
#define HEADS 16
#define HD    64
#define INTER 4096
#define NLAYERS 4
#define KPATCH 768

// ---------------- scratch ---------------------------------------------------
__device__ float g_xpatch[S_TOK * KPATCH];
__device__ float g_x [S_TOK * HID];
__device__ float g_h2[S_TOK * HID];
__device__ float g_hn[S_TOK * HID];
__device__ float g_q [S_TOK * HID];
__device__ float g_k [S_TOK * HID];
__device__ float g_v [S_TOK * HID];
__device__ float g_ao[S_TOK * HID];
__device__ float g_t [S_TOK * INTER];
__device__ float g_cos[S_TOK * HD];
__device__ float g_sin[S_TOK * HD];

// ---------------- helpers ----------------------------------------------------
__device__ __forceinline__ float tf32r(float x) {
    uint32_t r;
    asm("cvt.rna.tf32.f32 %0, %1;" : "=r"(r) : "f"(x));
    return __uint_as_float(r);
}
__device__ __forceinline__ uint32_t f2tf32(float x) {
    uint32_t r;
    asm("cvt.rna.tf32.f32 %0, %1;" : "=r"(r) : "f"(x));
    return r;
}
__device__ __forceinline__ void mma_tf32(float c[4],
                                         uint32_t a0, uint32_t a1, uint32_t a2, uint32_t a3,
                                         uint32_t b0, uint32_t b1) {
    asm volatile(
        "mma.sync.aligned.m16n8k8.row.col.f32.tf32.tf32.f32 "
        "{%0,%1,%2,%3},{%4,%5,%6,%7},{%8,%9},{%0,%1,%2,%3};"
        : "+f"(c[0]), "+f"(c[1]), "+f"(c[2]), "+f"(c[3])
        : "r"(a0), "r"(a1), "r"(a2), "r"(a3), "r"(b0), "r"(b1));
}
__device__ __forceinline__ void cp16(void* smem_dst, const void* gsrc) {
    uint32_t d = (uint32_t)__cvta_generic_to_shared(smem_dst);
    asm volatile("cp.async.cg.shared.global [%0], [%1], 16;\n" :: "r"(d), "l"(gsrc));
}
#define CP_COMMIT() asm volatile("cp.async.commit_group;\n" ::: "memory")
#define CP_WAIT0()  asm volatile("cp.async.wait_group 0;\n" ::: "memory")
#define CP_WAIT1()  asm volatile("cp.async.wait_group 1;\n" ::: "memory")
#define CP_WAIT2()  asm volatile("cp.async.wait_group 2;\n" ::: "memory")

// ---------------- im2col (tf32-rounded) ---------------------------------------
__global__ void im2col_kernel(const float* __restrict__ img0,
                              const float* __restrict__ img1) {
    int idx = blockIdx.x * blockDim.x + threadIdx.x;
    if (idx >= S_TOK * KPATCH) return;
    int s = idx / KPATCH;
    int r = idx - s * KPATCH;
    int c  = r >> 8;
    int kh = (r >> 4) & 15;
    int kw = r & 15;
    float val;
    if (s < S0) {
        int ph = s >> 5, pw = s & 31;
        val = img0[c * 512 * 512 + (ph * 16 + kh) * 512 + (pw * 16 + kw)];
    } else {
        int sp = s - S0;
        int ph = sp >> 4, pw = sp & 15;
        val = img1[c * 512 * 256 + (ph * 16 + kh) * 256 + (pw * 16 + kw)];
    }
    g_xpatch[idx] = tf32r(val);
}

// ---------------- RoPE table ---------------------------------------------------
__global__ void rope_table_kernel() {
    int s = blockIdx.x;
    int d = threadIdx.x;  // 0..63
    int ph, pw;
    if (s < S0) { ph = s >> 5; pw = s & 31; }
    else        { int sp = s - S0; ph = sp >> 4; pw = sp & 15; }
    int j = d & 31;
    float e, base;
    if (j < 16) { e = (4.0f * j) / 64.0f;               base = (float)ph; }
    else        { e = (2.0f + 4.0f * (j - 16)) / 64.0f; base = (float)pw; }
    float f = base * expf(-e * 9.2103403719761836f);
    g_cos[s * HD + d] = cosf(f);
    g_sin[s * HD + d] = sinf(f);
}

// ---------------- RMSNorm (tf32-rounded output) ---------------------------------
__global__ void rms_kernel(const float* __restrict__ x,
                           const float* __restrict__ w,
                           float* __restrict__ y) {
    int s = blockIdx.x;
    int tid = threadIdx.x;  // 256
    const float* xr = x + s * HID;
    float ss = 0.f;
    #pragma unroll 4
    for (int i = tid; i < HID; i += 256) { float v = xr[i]; ss += v * v; }
    __shared__ float sh[8];
    #pragma unroll
    for (int o = 16; o > 0; o >>= 1) ss += __shfl_xor_sync(0xffffffffu, ss, o);
    if ((tid & 31) == 0) sh[tid >> 5] = ss;
    __syncthreads();
    if (tid < 8) {
        float v = sh[tid];
        #pragma unroll
        for (int o = 4; o > 0; o >>= 1) v += __shfl_xor_sync(0xffu, v, o);
        if (tid == 0) sh[0] = v;
    }
    __syncthreads();
    float r = rsqrtf(sh[0] * (1.0f / HID) + 1e-5f);
    for (int i = tid; i < HID; i += 256) y[s * HID + i] = tf32r(xr[i] * r * w[i]);
}

// ---------------- tf32 tensor-core GEMM --------------------------------------
// C[M,N] = A[M,K] @ B[N,K]^T. A must be tf32-pre-rounded; B raw (cvt in loop).
// Tiles BM x 128 x 16, 256 threads (8 warps: 2m x 4n), 3-stage cp.async.
// EPI: 0=raw store, 1=+aux residual, 2=silu(aux)*acc tf32 store, 3=tf32 store
template<int BM, int EPI>
__device__ __forceinline__ void gemm_body(
    const float* __restrict__ A, const float* __restrict__ B,
    const float* __restrict__ aux, float* __restrict__ C,
    int N, int K, float* tiles)
{
    constexpr int MT = BM / 32;
    constexpr int ASTG = BM * 20;
    constexpr int BSTG = 128 * 20;
    constexpr int STG  = ASTG + BSTG;

    int tid = threadIdx.x;
    int warp = tid >> 5, lane = tid & 31;
    int gid = lane >> 2, tig = lane & 3;
    int wm = warp >> 2, wn = warp & 3;
    int m0 = blockIdx.y * BM, n0 = blockIdx.x * 128;

    float acc[MT][4][4];
    #pragma unroll
    for (int i = 0; i < MT; i++)
        #pragma unroll
        for (int j = 0; j < 4; j++)
            #pragma unroll
            for (int l = 0; l < 4; l++) acc[i][j][l] = 0.f;

    const int KT = K >> 4;
    constexpr int NLOAD = (BM + 128) * 4;

    auto load_stage = [&](int kt, int s) {
        int k0 = kt << 4;
        float* As = tiles + s * STG;
        float* Bs = As + ASTG;
        #pragma unroll
        for (int i = tid; i < NLOAD; i += 256) {
            if (i < BM * 4) {
                int r = i >> 2, c = (i & 3) << 2;
                cp16(&As[r * 20 + c], &A[(size_t)(m0 + r) * K + k0 + c]);
            } else {
                int i2 = i - BM * 4;
                int r = i2 >> 2, c = (i2 & 3) << 2;
                cp16(&Bs[r * 20 + c], &B[(size_t)(n0 + r) * K + k0 + c]);
            }
        }
        CP_COMMIT();
    };

    load_stage(0, 0);
    load_stage(1, 1);

    for (int kt = 0; kt < KT; kt++) {
        int s = kt % 3;
        if (kt + 2 < KT) { load_stage(kt + 2, (kt + 2) % 3); CP_WAIT2(); }
        else if (kt + 2 == KT) { CP_WAIT1(); }
        else { CP_WAIT0(); }
        __syncthreads();
        const float* Ab = tiles + s * STG;
        const float* Bb = Ab + ASTG;
        #pragma unroll
        for (int ks = 0; ks < 2; ks++) {
            int col = ks * 8;
            uint32_t af[MT][4], bf[4][2];
            #pragma unroll
            for (int i = 0; i < MT; i++) {
                int r0 = wm * (BM / 2) + i * 16 + gid;
                af[i][0] = __float_as_uint(Ab[r0 * 20 + col + tig]);
                af[i][1] = __float_as_uint(Ab[(r0 + 8) * 20 + col + tig]);
                af[i][2] = __float_as_uint(Ab[r0 * 20 + col + tig + 4]);
                af[i][3] = __float_as_uint(Ab[(r0 + 8) * 20 + col + tig + 4]);
            }
            #pragma unroll
            for (int j = 0; j < 4; j++) {
                int n = wn * 32 + j * 8 + gid;
                bf[j][0] = f2tf32(Bb[n * 20 + col + tig]);
                bf[j][1] = f2tf32(Bb[n * 20 + col + tig + 4]);
            }
            #pragma unroll
            for (int i = 0; i < MT; i++)
                #pragma unroll
                for (int j = 0; j < 4; j++)
                    mma_tf32(acc[i][j], af[i][0], af[i][1], af[i][2], af[i][3],
                             bf[j][0], bf[j][1]);
        }
        __syncthreads();
    }

    #pragma unroll
    for (int i = 0; i < MT; i++) {
        #pragma unroll
        for (int j = 0; j < 4; j++) {
            int m = m0 + wm * (BM / 2) + i * 16 + gid;
            int n = n0 + wn * 32 + j * 8 + 2 * tig;
            #pragma unroll
            for (int half = 0; half < 2; half++) {
                int mm = m + half * 8;
                float v0 = acc[i][j][half * 2 + 0];
                float v1 = acc[i][j][half * 2 + 1];
                size_t off = (size_t)mm * N + n;
                if (EPI == 1) {
                    v0 += aux[off]; v1 += aux[off + 1];
                } else if (EPI == 2) {
                    float g0 = aux[off], g1 = aux[off + 1];
                    v0 = tf32r(v0 * g0 / (1.0f + __expf(-g0)));
                    v1 = tf32r(v1 * g1 / (1.0f + __expf(-g1)));
                } else if (EPI == 3) {
                    v0 = tf32r(v0); v1 = tf32r(v1);
                }
                float2 o2; o2.x = v0; o2.y = v1;
                *(float2*)&C[off] = o2;
            }
        }
    }
}

template<int BM, int EPI>
__global__ void __launch_bounds__(256) gemm_tf32(
    const float* __restrict__ A, const float* __restrict__ B,
    const float* __restrict__ aux, float* __restrict__ C, int N, int K)
{
    extern __shared__ float tiles[];
    gemm_body<BM, EPI>(A, B, aux, C, N, K, tiles);
}

// QKV: grid.z selects weight/output; EPI=3 rounds outputs to tf32
__global__ void __launch_bounds__(256) gemm_qkv(
    const float* __restrict__ A,
    const float* __restrict__ B0, const float* __restrict__ B1, const float* __restrict__ B2,
    float* __restrict__ C0, float* __restrict__ C1, float* __restrict__ C2, int K)
{
    extern __shared__ float tiles[];
    const float* B = (blockIdx.z == 0) ? B0 : (blockIdx.z == 1) ? B1 : B2;
    float*       C = (blockIdx.z == 0) ? C0 : (blockIdx.z == 1) ? C1 : C2;
    gemm_body<64, 3>(A, B, nullptr, C, HID, K, tiles);
}

// ---------------- RoPE apply (tf32-rounded outputs) ----------------------------
__global__ void rope_kernel(float* __restrict__ q, float* __restrict__ k) {
    int idx = blockIdx.x * blockDim.x + threadIdx.x;
    if (idx >= S_TOK * HEADS * 32) return;
    int d = idx & 31;
    int h = (idx >> 5) & 15;
    int s = idx >> 9;
    float c  = g_cos[s * HD + d];
    float sn = g_sin[s * HD + d];
    int base = s * HID + h * HD;
    float q0 = q[base + d], q1 = q[base + d + 32];
    q[base + d]      = tf32r(q0 * c - q1 * sn);
    q[base + d + 32] = tf32r(q1 * c + q0 * sn);
    float k0 = k[base + d], k1 = k[base + d + 32];
    k[base + d]      = tf32r(k0 * c - k1 * sn);
    k[base + d + 32] = tf32r(k1 * c + k0 * sn);
}

// ---------------- tensor-core flash attention ----------------------------------
// grid (24 qtiles, 16 heads), 256 threads (8 warps = 4m x 2n).
// Per CTA: 64 queries, one head. S = Q@K^T via mma into smem; cooperative
// online softmax (4 threads per row); O += P@V via mma, P re-read from smem.
// Q,K,V must be tf32-pre-rounded. Output tf32-rounded.
#define AP 68   // smem row stride (floats)

__global__ void __launch_bounds__(256) attn_mma_kernel(
    const float* __restrict__ q, const float* __restrict__ k,
    const float* __restrict__ v, float* __restrict__ o)
{
    extern __shared__ float sm[];
    float* Qs = sm;               // 64 x AP
    float* Ks = Qs + 64 * AP;
    float* Vs = Ks + 64 * AP;
    float* Ss = Vs + 64 * AP;
    float* Al = Ss + 64 * AP;     // 64 alphas
    float* Ll = Al + 64;          // 64 row sums

    int qt = blockIdx.x, h = blockIdx.y;
    int s0 = qt * 64;
    int key0 = (s0 < S0) ? 0 : S0;
    int nkt  = (s0 < S0) ? 16 : 8;

    int tid = threadIdx.x;
    int warp = tid >> 5, lane = tid & 31;
    int gid = lane >> 2, tig = lane & 3;
    int wm = warp >> 1, wn = warp & 1;   // 4 x 2 warps: 16-row x 32-col tiles
    int qq = tid >> 2, kg = tid & 3;     // softmax role: row qq, col-quarter kg

    // load Q tile (stays resident)
    for (int i = tid; i < 1024; i += 256) {
        int r = i >> 4, c = i & 15;
        cp16(&Qs[r * AP + c * 4], &q[(size_t)(s0 + r) * HID + h * HD + c * 4]);
    }
    CP_COMMIT();

    float m_prev = -1e30f, lsum = 0.f;
    float oacc[4][4];
    #pragma unroll
    for (int j = 0; j < 4; j++)
        #pragma unroll
        for (int l = 0; l < 4; l++) oacc[j][l] = 0.f;

    int arow0 = wm * 16 + gid;           // MMA row pair: arow0, arow0+8

    for (int kt = 0; kt < nkt; kt++) {
        // load K,V tile
        for (int i = tid; i < 2048; i += 256) {
            int r = (i >> 4) & 63, c = i & 15;
            size_t g = (size_t)(key0 + kt * 64 + r) * HID + h * HD + c * 4;
            if (i < 1024) cp16(&Ks[r * AP + c * 4], &k[g]);
            else          cp16(&Vs[r * AP + c * 4], &v[g]);
        }
        CP_COMMIT();
        CP_WAIT0();
        __syncthreads();

        // S = Q @ K^T (warp tile: rows wm*16..+15, cols wn*32..+31)
        float sc[4][4];
        #pragma unroll
        for (int j = 0; j < 4; j++)
            #pragma unroll
            for (int l = 0; l < 4; l++) sc[j][l] = 0.f;
        #pragma unroll
        for (int ks = 0; ks < 8; ks++) {
            int col = ks * 8;
            uint32_t a0 = __float_as_uint(Qs[arow0 * AP + col + tig]);
            uint32_t a1 = __float_as_uint(Qs[(arow0 + 8) * AP + col + tig]);
            uint32_t a2 = __float_as_uint(Qs[arow0 * AP + col + tig + 4]);
            uint32_t a3 = __float_as_uint(Qs[(arow0 + 8) * AP + col + tig + 4]);
            #pragma unroll
            for (int j = 0; j < 4; j++) {
                int n = wn * 32 + j * 8 + gid;
                uint32_t b0 = __float_as_uint(Ks[n * AP + col + tig]);
                uint32_t b1 = __float_as_uint(Ks[n * AP + col + tig + 4]);
                mma_tf32(sc[j], a0, a1, a2, a3, b0, b1);
            }
        }
        // write scaled scores to smem
        #pragma unroll
        for (int j = 0; j < 4; j++) {
            int cn = wn * 32 + j * 8 + 2 * tig;
            Ss[arow0 * AP + cn]           = sc[j][0] * 0.125f;
            Ss[arow0 * AP + cn + 1]       = sc[j][1] * 0.125f;
            Ss[(arow0 + 8) * AP + cn]     = sc[j][2] * 0.125f;
            Ss[(arow0 + 8) * AP + cn + 1] = sc[j][3] * 0.125f;
        }
        __syncthreads();

        // online softmax: row qq, columns kg*16..+15
        {
            float e[16];
            int base = qq * AP + kg * 16;
            float mloc = -1e30f;
            #pragma unroll
            for (int i = 0; i < 16; i++) { e[i] = Ss[base + i]; mloc = fmaxf(mloc, e[i]); }
            mloc = fmaxf(mloc, __shfl_xor_sync(0xffffffffu, mloc, 1));
            mloc = fmaxf(mloc, __shfl_xor_sync(0xffffffffu, mloc, 2));
            float m_new = fmaxf(m_prev, mloc);
            float alpha = __expf(m_prev - m_new);
            float lrow = 0.f;
            #pragma unroll
            for (int i = 0; i < 16; i++) {
                e[i] = __expf(e[i] - m_new);
                lrow += e[i];
                Ss[base + i] = e[i];
            }
            lrow += __shfl_xor_sync(0xffffffffu, lrow, 1);
            lrow += __shfl_xor_sync(0xffffffffu, lrow, 2);
            lsum = lsum * alpha + lrow;
            m_prev = m_new;
            if (kg == 0) Al[qq] = alpha;
        }
        __syncthreads();

        // rescale O accumulators
        float a_r0 = Al[arow0], a_r1 = Al[arow0 + 8];
        #pragma unroll
        for (int j = 0; j < 4; j++) {
            oacc[j][0] *= a_r0; oacc[j][1] *= a_r0;
            oacc[j][2] *= a_r1; oacc[j][3] *= a_r1;
        }

        // O += P @ V (A = P from Ss with cvt; B = V[k][d] raw)
        #pragma unroll
        for (int ks = 0; ks < 8; ks++) {
            int kc = ks * 8;
            uint32_t a0 = f2tf32(Ss[arow0 * AP + kc + tig]);
            uint32_t a1 = f2tf32(Ss[(arow0 + 8) * AP + kc + tig]);
            uint32_t a2 = f2tf32(Ss[arow0 * AP + kc + tig + 4]);
            uint32_t a3 = f2tf32(Ss[(arow0 + 8) * AP + kc + tig + 4]);
            #pragma unroll
            for (int j = 0; j < 4; j++) {
                int n = wn * 32 + j * 8 + gid;
                uint32_t b0 = __float_as_uint(Vs[(kc + tig) * AP + n]);
                uint32_t b1 = __float_as_uint(Vs[(kc + tig + 4) * AP + n]);
                mma_tf32(oacc[j], a0, a1, a2, a3, b0, b1);
            }
        }
        __syncthreads();   // S/K/V reused next iteration
    }

    if (kg == 0) Ll[qq] = lsum;
    __syncthreads();
    float inv0 = 1.0f / Ll[arow0];
    float inv1 = 1.0f / Ll[arow0 + 8];
    #pragma unroll
    for (int j = 0; j < 4; j++) {
        int cn = wn * 32 + j * 8 + 2 * tig;
        size_t o0 = (size_t)(s0 + arow0) * HID + h * HD + cn;
        size_t o1 = (size_t)(s0 + arow0 + 8) * HID + h * HD + cn;
        o[o0]     = tf32r(oacc[j][0] * inv0);
        o[o0 + 1] = tf32r(oacc[j][1] * inv0);
        o[o1]     = tf32r(oacc[j][2] * inv1);
        o[o1 + 1] = tf32r(oacc[j][3] * inv1);
    }
}

// ---------------- host orchestration ---------------------------------------------
extern "C" void kernel_launch(void* const* d_in, const int* in_sizes, int n_in,
                              void* d_out, int out_size) {
    const float* img0        = (const float*)d_in[0];
    const float* img1        = (const float*)d_in[1];
    const float* conv_w      = (const float*)d_in[2];
    const float* ln_pre_w    = (const float*)d_in[3];
    const float* attn_norm_w = (const float*)d_in[4];
    const float* q_w         = (const float*)d_in[5];
    const float* k_w         = (const float*)d_in[6];
    const float* v_w         = (const float*)d_in[7];
    const float* o_w         = (const float*)d_in[8];
    const float* ffn_norm_w  = (const float*)d_in[9];
    const float* gate_w      = (const float*)d_in[10];
    const float* up_w        = (const float*)d_in[11];
    const float* down_w      = (const float*)d_in[12];
    float* out = (float*)d_out;

    float *p_xpatch, *p_x, *p_h2, *p_hn, *p_q, *p_k, *p_v, *p_ao, *p_t;
    cudaGetSymbolAddress((void**)&p_xpatch, g_xpatch);
    cudaGetSymbolAddress((void**)&p_x,  g_x);
    cudaGetSymbolAddress((void**)&p_h2, g_h2);
    cudaGetSymbolAddress((void**)&p_hn, g_hn);
    cudaGetSymbolAddress((void**)&p_q,  g_q);
    cudaGetSymbolAddress((void**)&p_k,  g_k);
    cudaGetSymbolAddress((void**)&p_v,  g_v);
    cudaGetSymbolAddress((void**)&p_ao, g_ao);
    cudaGetSymbolAddress((void**)&p_t,  g_t);

    const int SMEM64  = 3 * (64  + 128) * 20 * 4;   // 46080
    const int SMEM128 = 3 * (128 + 128) * 20 * 4;   // 61440
    const int ASMEM   = (4 * 64 * AP + 128) * 4;    // 70144
    cudaFuncSetAttribute(gemm_tf32<64, 1>,  cudaFuncAttributeMaxDynamicSharedMemorySize, SMEM64);
    cudaFuncSetAttribute(gemm_tf32<64, 0>,  cudaFuncAttributeMaxDynamicSharedMemorySize, SMEM64);
    cudaFuncSetAttribute(gemm_tf32<128, 0>, cudaFuncAttributeMaxDynamicSharedMemorySize, SMEM128);
    cudaFuncSetAttribute(gemm_tf32<128, 2>, cudaFuncAttributeMaxDynamicSharedMemorySize, SMEM128);
    cudaFuncSetAttribute(gemm_qkv,          cudaFuncAttributeMaxDynamicSharedMemorySize, SMEM64);
    cudaFuncSetAttribute(attn_mma_kernel,   cudaFuncAttributeMaxDynamicSharedMemorySize, ASMEM);

    dim3 grid_n1k(HID / 128, S_TOK / 64);       // (8, 24)   BM=64
    dim3 grid_qkv(HID / 128, S_TOK / 64, 3);    // (8, 24, 3)
    dim3 grid_n4k(INTER / 128, S_TOK / 128);    // (32, 12)  BM=128

    // patch embed
    im2col_kernel<<<(S_TOK * KPATCH + 255) / 256, 256>>>(img0, img1);
    gemm_tf32<64, 0><<<grid_n1k, 256, SMEM64>>>(p_xpatch, conv_w, nullptr, p_h2, HID, KPATCH);

    rms_kernel<<<S_TOK, 256>>>(p_h2, ln_pre_w, p_x);
    rope_table_kernel<<<S_TOK, 64>>>();

    for (int l = 0; l < NLAYERS; l++) {
        const float* qw = q_w + (size_t)l * HID * HID;
        const float* kw = k_w + (size_t)l * HID * HID;
        const float* vw = v_w + (size_t)l * HID * HID;
        const float* ow = o_w + (size_t)l * HID * HID;
        const float* gw = gate_w + (size_t)l * INTER * HID;
        const float* uw = up_w   + (size_t)l * INTER * HID;
        const float* dw = down_w + (size_t)l * HID * INTER;

        rms_kernel<<<S_TOK, 256>>>(p_x, attn_norm_w + l * HID, p_hn);

        gemm_qkv<<<grid_qkv, 256, SMEM64>>>(p_hn, qw, kw, vw, p_q, p_k, p_v, HID);

        rope_kernel<<<(S_TOK * HEADS * 32 + 255) / 256, 256>>>(p_q, p_k);

        attn_mma_kernel<<<dim3(S_TOK / 64, HEADS), 256, ASMEM>>>(p_q, p_k, p_v, p_ao);

        gemm_tf32<64, 1><<<grid_n1k, 256, SMEM64>>>(p_ao, ow, p_x, p_h2, HID, HID);

        rms_kernel<<<S_TOK, 256>>>(p_h2, ffn_norm_w + l * HID, p_hn);

        gemm_tf32<128, 0><<<grid_n4k, 256, SMEM128>>>(p_hn, gw, nullptr, p_t, INTER, HID);
        gemm_tf32<128, 2><<<grid_n4k, 256, SMEM128>>>(p_hn, uw, p_t, p_t, INTER, HID);

        float* dst = (l == NLAYERS - 1) ? out : p_x;
        gemm_tf32<64, 1><<<grid_n1k, 256, SMEM64>>>(p_t, dw, p_h2, dst, HID, INTER);
    }
}

// round 7
// speedup vs baseline: 5.6677x; 1.1912x over previous
#include <cuda_runtime.h>
#include <math.h>
#include <stdint.h>

// ---------------- problem constants ----------------------------------------
#define S_TOK 1536
#define S0    1024
#define HID   1024
#define HEADS 16
#define HD    64
#define INTER 4096
#define NLAYERS 4
#define KPATCH 768

// ---------------- scratch ---------------------------------------------------
__device__ float g_xpatch[S_TOK * KPATCH];
__device__ float g_x [S_TOK * HID];
__device__ float g_h2[S_TOK * HID];
__device__ float g_hn[S_TOK * HID];
__device__ float g_q [S_TOK * HID];
__device__ float g_k [S_TOK * HID];
__device__ float g_v [S_TOK * HID];
__device__ float g_ao[S_TOK * HID];
__device__ float g_t [S_TOK * INTER];
__device__ float g_cos[S_TOK * HD];
__device__ float g_sin[S_TOK * HD];

// ---------------- helpers ----------------------------------------------------
__device__ __forceinline__ uint32_t smem_u32(const void* p) {
    return (uint32_t)__cvta_generic_to_shared(p);
}
__device__ __forceinline__ float tf32r(float x) {
    uint32_t r;
    asm("cvt.rna.tf32.f32 %0, %1;" : "=r"(r) : "f"(x));
    return __uint_as_float(r);
}
__device__ __forceinline__ uint32_t f2tf32(float x) {
    uint32_t r;
    asm("cvt.rna.tf32.f32 %0, %1;" : "=r"(r) : "f"(x));
    return r;
}
__device__ __forceinline__ uint32_t cvt_bits(uint32_t b) {
    uint32_t r;
    asm("cvt.rna.tf32.f32 %0, %1;" : "=r"(r) : "f"(__uint_as_float(b)));
    return r;
}
__device__ __forceinline__ void mma_tf32(float c[4],
                                         uint32_t a0, uint32_t a1, uint32_t a2, uint32_t a3,
                                         uint32_t b0, uint32_t b1) {
    asm volatile(
        "mma.sync.aligned.m16n8k8.row.col.f32.tf32.tf32.f32 "
        "{%0,%1,%2,%3},{%4,%5,%6,%7},{%8,%9},{%0,%1,%2,%3};"
        : "+f"(c[0]), "+f"(c[1]), "+f"(c[2]), "+f"(c[3])
        : "r"(a0), "r"(a1), "r"(a2), "r"(a3), "r"(b0), "r"(b1));
}
__device__ __forceinline__ void ldm_x4(uint32_t& r0, uint32_t& r1, uint32_t& r2, uint32_t& r3,
                                       uint32_t addr) {
    asm volatile("ldmatrix.sync.aligned.m8n8.x4.shared.b16 {%0,%1,%2,%3}, [%4];"
                 : "=r"(r0), "=r"(r1), "=r"(r2), "=r"(r3) : "r"(addr));
}
__device__ __forceinline__ void cp16(void* smem_dst, const void* gsrc) {
    uint32_t d = (uint32_t)__cvta_generic_to_shared(smem_dst);
    asm volatile("cp.async.cg.shared.global [%0], [%1], 16;\n" :: "r"(d), "l"(gsrc));
}
#define CP_COMMIT() asm volatile("cp.async.commit_group;\n" ::: "memory")
#define CP_WAIT0()  asm volatile("cp.async.wait_group 0;\n" ::: "memory")
#define CP_WAIT1()  asm volatile("cp.async.wait_group 1;\n" ::: "memory")
#define CP_WAIT2()  asm volatile("cp.async.wait_group 2;\n" ::: "memory")

// ---------------- im2col (tf32-rounded) ---------------------------------------
__global__ void im2col_kernel(const float* __restrict__ img0,
                              const float* __restrict__ img1) {
    int idx = blockIdx.x * blockDim.x + threadIdx.x;
    if (idx >= S_TOK * KPATCH) return;
    int s = idx / KPATCH;
    int r = idx - s * KPATCH;
    int c  = r >> 8;
    int kh = (r >> 4) & 15;
    int kw = r & 15;
    float val;
    if (s < S0) {
        int ph = s >> 5, pw = s & 31;
        val = img0[c * 512 * 512 + (ph * 16 + kh) * 512 + (pw * 16 + kw)];
    } else {
        int sp = s - S0;
        int ph = sp >> 4, pw = sp & 15;
        val = img1[c * 512 * 256 + (ph * 16 + kh) * 256 + (pw * 16 + kw)];
    }
    g_xpatch[idx] = tf32r(val);
}

// ---------------- RoPE table ---------------------------------------------------
__global__ void rope_table_kernel() {
    int s = blockIdx.x;
    int d = threadIdx.x;  // 0..63
    int ph, pw;
    if (s < S0) { ph = s >> 5; pw = s & 31; }
    else        { int sp = s - S0; ph = sp >> 4; pw = sp & 15; }
    int j = d & 31;
    float e, base;
    if (j < 16) { e = (4.0f * j) / 64.0f;               base = (float)ph; }
    else        { e = (2.0f + 4.0f * (j - 16)) / 64.0f; base = (float)pw; }
    float f = base * expf(-e * 9.2103403719761836f);
    g_cos[s * HD + d] = cosf(f);
    g_sin[s * HD + d] = sinf(f);
}

// ---------------- RMSNorm (tf32-rounded output) ---------------------------------
__global__ void rms_kernel(const float* __restrict__ x,
                           const float* __restrict__ w,
                           float* __restrict__ y) {
    int s = blockIdx.x;
    int tid = threadIdx.x;  // 256
    const float* xr = x + s * HID;
    float ss = 0.f;
    #pragma unroll 4
    for (int i = tid; i < HID; i += 256) { float v = xr[i]; ss += v * v; }
    __shared__ float sh[8];
    #pragma unroll
    for (int o = 16; o > 0; o >>= 1) ss += __shfl_xor_sync(0xffffffffu, ss, o);
    if ((tid & 31) == 0) sh[tid >> 5] = ss;
    __syncthreads();
    if (tid < 8) {
        float v = sh[tid];
        #pragma unroll
        for (int o = 4; o > 0; o >>= 1) v += __shfl_xor_sync(0xffu, v, o);
        if (tid == 0) sh[0] = v;
    }
    __syncthreads();
    float r = rsqrtf(sh[0] * (1.0f / HID) + 1e-5f);
    for (int i = tid; i < HID; i += 256) y[s * HID + i] = tf32r(xr[i] * r * w[i]);
}

// ---------------- tf32 tensor-core GEMM (ldmatrix operands, BK=32) -------------
// C[M,N] = A[M,K] @ B[N,K]^T. A tf32-pre-rounded (raw bits); B raw (cvt post-ldm).
// BM x 128 x 32 tiles, 256 threads (8 warps: 2m x 4n), 3-stage cp.async.
// EPI: 0=raw store, 1=+aux residual, 2=silu(aux)*acc tf32 store, 3=tf32 store
#define SROW 36   // smem row stride in floats (32 data + 4 pad)

template<int BM, int EPI>
__device__ __forceinline__ void gemm_body(
    const float* __restrict__ A, const float* __restrict__ B,
    const float* __restrict__ aux, float* __restrict__ C,
    int N, int K, float* tiles)
{
    constexpr int MT = BM / 32;
    constexpr int ASTG = BM * SROW;
    constexpr int BSTG = 128 * SROW;
    constexpr int STG  = ASTG + BSTG;

    int tid = threadIdx.x;
    int warp = tid >> 5, lane = tid & 31;
    int gid = lane >> 2, tig = lane & 3;
    int g8 = lane >> 3, r8 = lane & 7;
    int wm = warp >> 2, wn = warp & 3;
    int m0 = blockIdx.y * BM, n0 = blockIdx.x * 128;

    float acc[MT][4][4];
    #pragma unroll
    for (int i = 0; i < MT; i++)
        #pragma unroll
        for (int j = 0; j < 4; j++)
            #pragma unroll
            for (int l = 0; l < 4; l++) acc[i][j][l] = 0.f;

    const int KT = K >> 5;          // BK=32
    constexpr int NCH = (BM + 128) * 8;   // float4 chunks per stage

    auto load_stage = [&](int kt, int s) {
        int k0 = kt << 5;
        float* As = tiles + s * STG;
        float* Bs = As + ASTG;
        #pragma unroll
        for (int i = tid; i < NCH; i += 256) {
            int r = i >> 3, c = (i & 7) << 2;
            if (r < BM) cp16(&As[r * SROW + c], &A[(size_t)(m0 + r) * K + k0 + c]);
            else {
                int rb = r - BM;
                cp16(&Bs[rb * SROW + c], &B[(size_t)(n0 + rb) * K + k0 + c]);
            }
        }
        CP_COMMIT();
    };

    // per-thread ldmatrix row offsets (within a stage, in bytes)
    // A m-tile i: row = wm*(BM/2) + i*16 + (g8&1)*8 + r8, col byte off = (g8>>1)*16
    // B pair jj:  row = wn*32 + jj*16 + (g8>>1)*8 + r8,  col byte off = (g8&1)*16
    uint32_t a_off[MT], b_off[2];
    #pragma unroll
    for (int i = 0; i < MT; i++)
        a_off[i] = (uint32_t)((wm * (BM / 2) + i * 16 + (g8 & 1) * 8 + r8) * SROW * 4
                              + (g8 >> 1) * 16);
    #pragma unroll
    for (int jj = 0; jj < 2; jj++)
        b_off[jj] = (uint32_t)(ASTG * 4 + (wn * 32 + jj * 16 + (g8 >> 1) * 8 + r8) * SROW * 4
                               + (g8 & 1) * 16);

    load_stage(0, 0);
    load_stage(1, 1);

    for (int kt = 0; kt < KT; kt++) {
        int s = kt % 3;
        if (kt + 2 < KT) { load_stage(kt + 2, (kt + 2) % 3); CP_WAIT2(); }
        else if (kt + 2 == KT) { CP_WAIT1(); }
        else { CP_WAIT0(); }
        __syncthreads();
        uint32_t base = smem_u32(tiles + s * STG);
        #pragma unroll
        for (int ks = 0; ks < 4; ks++) {
            uint32_t kofs = base + ks * 32;
            uint32_t af[MT][4];
            #pragma unroll
            for (int i = 0; i < MT; i++)
                ldm_x4(af[i][0], af[i][1], af[i][2], af[i][3], kofs + a_off[i]);
            uint32_t bf[4][2];
            #pragma unroll
            for (int jj = 0; jj < 2; jj++) {
                uint32_t b0, b1, b2, b3;
                ldm_x4(b0, b1, b2, b3, kofs + b_off[jj]);
                bf[2 * jj + 0][0] = cvt_bits(b0);
                bf[2 * jj + 0][1] = cvt_bits(b1);
                bf[2 * jj + 1][0] = cvt_bits(b2);
                bf[2 * jj + 1][1] = cvt_bits(b3);
            }
            #pragma unroll
            for (int i = 0; i < MT; i++)
                #pragma unroll
                for (int j = 0; j < 4; j++)
                    mma_tf32(acc[i][j], af[i][0], af[i][1], af[i][2], af[i][3],
                             bf[j][0], bf[j][1]);
        }
        __syncthreads();
    }

    #pragma unroll
    for (int i = 0; i < MT; i++) {
        #pragma unroll
        for (int j = 0; j < 4; j++) {
            int m = m0 + wm * (BM / 2) + i * 16 + gid;
            int n = n0 + wn * 32 + j * 8 + 2 * tig;
            #pragma unroll
            for (int half = 0; half < 2; half++) {
                int mm = m + half * 8;
                float v0 = acc[i][j][half * 2 + 0];
                float v1 = acc[i][j][half * 2 + 1];
                size_t off = (size_t)mm * N + n;
                if (EPI == 1) {
                    v0 += aux[off]; v1 += aux[off + 1];
                } else if (EPI == 2) {
                    float g0 = aux[off], g1 = aux[off + 1];
                    v0 = tf32r(v0 * g0 / (1.0f + __expf(-g0)));
                    v1 = tf32r(v1 * g1 / (1.0f + __expf(-g1)));
                } else if (EPI == 3) {
                    v0 = tf32r(v0); v1 = tf32r(v1);
                }
                float2 o2; o2.x = v0; o2.y = v1;
                *(float2*)&C[off] = o2;
            }
        }
    }
}

template<int BM, int EPI>
__global__ void __launch_bounds__(256) gemm_tf32(
    const float* __restrict__ A, const float* __restrict__ B,
    const float* __restrict__ aux, float* __restrict__ C, int N, int K)
{
    extern __shared__ float tiles[];
    gemm_body<BM, EPI>(A, B, aux, C, N, K, tiles);
}

// QKV: grid.z selects weight/output; EPI=3 rounds outputs to tf32
__global__ void __launch_bounds__(256) gemm_qkv(
    const float* __restrict__ A,
    const float* __restrict__ B0, const float* __restrict__ B1, const float* __restrict__ B2,
    float* __restrict__ C0, float* __restrict__ C1, float* __restrict__ C2, int K)
{
    extern __shared__ float tiles[];
    const float* B = (blockIdx.z == 0) ? B0 : (blockIdx.z == 1) ? B1 : B2;
    float*       C = (blockIdx.z == 0) ? C0 : (blockIdx.z == 1) ? C1 : C2;
    gemm_body<64, 3>(A, B, nullptr, C, HID, K, tiles);
}

// ---------------- RoPE apply (tf32-rounded outputs) ----------------------------
__global__ void rope_kernel(float* __restrict__ q, float* __restrict__ k) {
    int idx = blockIdx.x * blockDim.x + threadIdx.x;
    if (idx >= S_TOK * HEADS * 32) return;
    int d = idx & 31;
    int h = (idx >> 5) & 15;
    int s = idx >> 9;
    float c  = g_cos[s * HD + d];
    float sn = g_sin[s * HD + d];
    int base = s * HID + h * HD;
    float q0 = q[base + d], q1 = q[base + d + 32];
    q[base + d]      = tf32r(q0 * c - q1 * sn);
    q[base + d + 32] = tf32r(q1 * c + q0 * sn);
    float k0 = k[base + d], k1 = k[base + d + 32];
    k[base + d]      = tf32r(k0 * c - k1 * sn);
    k[base + d + 32] = tf32r(k1 * c + k0 * sn);
}

// ---------------- tensor-core flash attention ----------------------------------
#define AP 68   // smem row stride (floats)

__global__ void __launch_bounds__(256) attn_mma_kernel(
    const float* __restrict__ q, const float* __restrict__ k,
    const float* __restrict__ v, float* __restrict__ o)
{
    extern __shared__ float sm[];
    float* Qs = sm;               // 64 x AP
    float* Ks = Qs + 64 * AP;
    float* Vs = Ks + 64 * AP;
    float* Ss = Vs + 64 * AP;
    float* Al = Ss + 64 * AP;     // 64 alphas
    float* Ll = Al + 64;          // 64 row sums

    int qt = blockIdx.x, h = blockIdx.y;
    int s0 = qt * 64;
    int key0 = (s0 < S0) ? 0 : S0;
    int nkt  = (s0 < S0) ? 16 : 8;

    int tid = threadIdx.x;
    int warp = tid >> 5, lane = tid & 31;
    int gid = lane >> 2, tig = lane & 3;
    int wm = warp >> 1, wn = warp & 1;
    int qq = tid >> 2, kg = tid & 3;

    for (int i = tid; i < 1024; i += 256) {
        int r = i >> 4, c = i & 15;
        cp16(&Qs[r * AP + c * 4], &q[(size_t)(s0 + r) * HID + h * HD + c * 4]);
    }
    CP_COMMIT();

    float m_prev = -1e30f, lsum = 0.f;
    float oacc[4][4];
    #pragma unroll
    for (int j = 0; j < 4; j++)
        #pragma unroll
        for (int l = 0; l < 4; l++) oacc[j][l] = 0.f;

    int arow0 = wm * 16 + gid;

    for (int kt = 0; kt < nkt; kt++) {
        for (int i = tid; i < 2048; i += 256) {
            int r = (i >> 4) & 63, c = i & 15;
            size_t g = (size_t)(key0 + kt * 64 + r) * HID + h * HD + c * 4;
            if (i < 1024) cp16(&Ks[r * AP + c * 4], &k[g]);
            else          cp16(&Vs[r * AP + c * 4], &v[g]);
        }
        CP_COMMIT();
        CP_WAIT0();
        __syncthreads();

        float sc[4][4];
        #pragma unroll
        for (int j = 0; j < 4; j++)
            #pragma unroll
            for (int l = 0; l < 4; l++) sc[j][l] = 0.f;
        #pragma unroll
        for (int ks = 0; ks < 8; ks++) {
            int col = ks * 8;
            uint32_t a0 = __float_as_uint(Qs[arow0 * AP + col + tig]);
            uint32_t a1 = __float_as_uint(Qs[(arow0 + 8) * AP + col + tig]);
            uint32_t a2 = __float_as_uint(Qs[arow0 * AP + col + tig + 4]);
            uint32_t a3 = __float_as_uint(Qs[(arow0 + 8) * AP + col + tig + 4]);
            #pragma unroll
            for (int j = 0; j < 4; j++) {
                int n = wn * 32 + j * 8 + gid;
                uint32_t b0 = __float_as_uint(Ks[n * AP + col + tig]);
                uint32_t b1 = __float_as_uint(Ks[n * AP + col + tig + 4]);
                mma_tf32(sc[j], a0, a1, a2, a3, b0, b1);
            }
        }
        #pragma unroll
        for (int j = 0; j < 4; j++) {
            int cn = wn * 32 + j * 8 + 2 * tig;
            Ss[arow0 * AP + cn]           = sc[j][0] * 0.125f;
            Ss[arow0 * AP + cn + 1]       = sc[j][1] * 0.125f;
            Ss[(arow0 + 8) * AP + cn]     = sc[j][2] * 0.125f;
            Ss[(arow0 + 8) * AP + cn + 1] = sc[j][3] * 0.125f;
        }
        __syncthreads();

        {
            float e[16];
            int base = qq * AP + kg * 16;
            float mloc = -1e30f;
            #pragma unroll
            for (int i = 0; i < 16; i++) { e[i] = Ss[base + i]; mloc = fmaxf(mloc, e[i]); }
            mloc = fmaxf(mloc, __shfl_xor_sync(0xffffffffu, mloc, 1));
            mloc = fmaxf(mloc, __shfl_xor_sync(0xffffffffu, mloc, 2));
            float m_new = fmaxf(m_prev, mloc);
            float alpha = __expf(m_prev - m_new);
            float lrow = 0.f;
            #pragma unroll
            for (int i = 0; i < 16; i++) {
                e[i] = __expf(e[i] - m_new);
                lrow += e[i];
                Ss[base + i] = e[i];
            }
            lrow += __shfl_xor_sync(0xffffffffu, lrow, 1);
            lrow += __shfl_xor_sync(0xffffffffu, lrow, 2);
            lsum = lsum * alpha + lrow;
            m_prev = m_new;
            if (kg == 0) Al[qq] = alpha;
        }
        __syncthreads();

        float a_r0 = Al[arow0], a_r1 = Al[arow0 + 8];
        #pragma unroll
        for (int j = 0; j < 4; j++) {
            oacc[j][0] *= a_r0; oacc[j][1] *= a_r0;
            oacc[j][2] *= a_r1; oacc[j][3] *= a_r1;
        }

        #pragma unroll
        for (int ks = 0; ks < 8; ks++) {
            int kc = ks * 8;
            uint32_t a0 = f2tf32(Ss[arow0 * AP + kc + tig]);
            uint32_t a1 = f2tf32(Ss[(arow0 + 8) * AP + kc + tig]);
            uint32_t a2 = f2tf32(Ss[arow0 * AP + kc + tig + 4]);
            uint32_t a3 = f2tf32(Ss[(arow0 + 8) * AP + kc + tig + 4]);
            #pragma unroll
            for (int j = 0; j < 4; j++) {
                int n = wn * 32 + j * 8 + gid;
                uint32_t b0 = __float_as_uint(Vs[(kc + tig) * AP + n]);
                uint32_t b1 = __float_as_uint(Vs[(kc + tig + 4) * AP + n]);
                mma_tf32(oacc[j], a0, a1, a2, a3, b0, b1);
            }
        }
        __syncthreads();
    }

    if (kg == 0) Ll[qq] = lsum;
    __syncthreads();
    float inv0 = 1.0f / Ll[arow0];
    float inv1 = 1.0f / Ll[arow0 + 8];
    #pragma unroll
    for (int j = 0; j < 4; j++) {
        int cn = wn * 32 + j * 8 + 2 * tig;
        size_t o0 = (size_t)(s0 + arow0) * HID + h * HD + cn;
        size_t o1 = (size_t)(s0 + arow0 + 8) * HID + h * HD + cn;
        o[o0]     = tf32r(oacc[j][0] * inv0);
        o[o0 + 1] = tf32r(oacc[j][1] * inv0);
        o[o1]     = tf32r(oacc[j][2] * inv1);
        o[o1 + 1] = tf32r(oacc[j][3] * inv1);
    }
}

// ---------------- host orchestration ---------------------------------------------
extern "C" void kernel_launch(void* const* d_in, const int* in_sizes, int n_in,
                              void* d_out, int out_size) {
    const float* img0        = (const float*)d_in[0];
    const float* img1        = (const float*)d_in[1];
    const float* conv_w      = (const float*)d_in[2];
    const float* ln_pre_w    = (const float*)d_in[3];
    const float* attn_norm_w = (const float*)d_in[4];
    const float* q_w         = (const float*)d_in[5];
    const float* k_w         = (const float*)d_in[6];
    const float* v_w         = (const float*)d_in[7];
    const float* o_w         = (const float*)d_in[8];
    const float* ffn_norm_w  = (const float*)d_in[9];
    const float* gate_w      = (const float*)d_in[10];
    const float* up_w        = (const float*)d_in[11];
    const float* down_w      = (const float*)d_in[12];
    float* out = (float*)d_out;

    float *p_xpatch, *p_x, *p_h2, *p_hn, *p_q, *p_k, *p_v, *p_ao, *p_t;
    cudaGetSymbolAddress((void**)&p_xpatch, g_xpatch);
    cudaGetSymbolAddress((void**)&p_x,  g_x);
    cudaGetSymbolAddress((void**)&p_h2, g_h2);
    cudaGetSymbolAddress((void**)&p_hn, g_hn);
    cudaGetSymbolAddress((void**)&p_q,  g_q);
    cudaGetSymbolAddress((void**)&p_k,  g_k);
    cudaGetSymbolAddress((void**)&p_v,  g_v);
    cudaGetSymbolAddress((void**)&p_ao, g_ao);
    cudaGetSymbolAddress((void**)&p_t,  g_t);

    const int SMEM64  = 3 * (64  + 128) * SROW * 4;   //  82944
    const int SMEM128 = 3 * (128 + 128) * SROW * 4;   // 110592
    const int ASMEM   = (4 * 64 * AP + 128) * 4;      //  70144
    cudaFuncSetAttribute(gemm_tf32<64, 1>,  cudaFuncAttributeMaxDynamicSharedMemorySize, SMEM64);
    cudaFuncSetAttribute(gemm_tf32<64, 0>,  cudaFuncAttributeMaxDynamicSharedMemorySize, SMEM64);
    cudaFuncSetAttribute(gemm_tf32<128, 0>, cudaFuncAttributeMaxDynamicSharedMemorySize, SMEM128);
    cudaFuncSetAttribute(gemm_tf32<128, 2>, cudaFuncAttributeMaxDynamicSharedMemorySize, SMEM128);
    cudaFuncSetAttribute(gemm_qkv,          cudaFuncAttributeMaxDynamicSharedMemorySize, SMEM64);
    cudaFuncSetAttribute(attn_mma_kernel,   cudaFuncAttributeMaxDynamicSharedMemorySize, ASMEM);

    dim3 grid_n1k(HID / 128, S_TOK / 64);       // (8, 24)   BM=64
    dim3 grid_qkv(HID / 128, S_TOK / 64, 3);    // (8, 24, 3)
    dim3 grid_n4k(INTER / 128, S_TOK / 128);    // (32, 12)  BM=128

    // patch embed
    im2col_kernel<<<(S_TOK * KPATCH + 255) / 256, 256>>>(img0, img1);
    gemm_tf32<64, 0><<<grid_n1k, 256, SMEM64>>>(p_xpatch, conv_w, nullptr, p_h2, HID, KPATCH);

    rms_kernel<<<S_TOK, 256>>>(p_h2, ln_pre_w, p_x);
    rope_table_kernel<<<S_TOK, 64>>>();

    for (int l = 0; l < NLAYERS; l++) {
        const float* qw = q_w + (size_t)l * HID * HID;
        const float* kw = k_w + (size_t)l * HID * HID;
        const float* vw = v_w + (size_t)l * HID * HID;
        const float* ow = o_w + (size_t)l * HID * HID;
        const float* gw = gate_w + (size_t)l * INTER * HID;
        const float* uw = up_w   + (size_t)l * INTER * HID;
        const float* dw = down_w + (size_t)l * HID * INTER;

        rms_kernel<<<S_TOK, 256>>>(p_x, attn_norm_w + l * HID, p_hn);

        gemm_qkv<<<grid_qkv, 256, SMEM64>>>(p_hn, qw, kw, vw, p_q, p_k, p_v, HID);

        rope_kernel<<<(S_TOK * HEADS * 32 + 255) / 256, 256>>>(p_q, p_k);

        attn_mma_kernel<<<dim3(S_TOK / 64, HEADS), 256, ASMEM>>>(p_q, p_k, p_v, p_ao);

        gemm_tf32<64, 1><<<grid_n1k, 256, SMEM64>>>(p_ao, ow, p_x, p_h2, HID, HID);

        rms_kernel<<<S_TOK, 256>>>(p_h2, ffn_norm_w + l * HID, p_hn);

        gemm_tf32<128, 0><<<grid_n4k, 256, SMEM128>>>(p_hn, gw, nullptr, p_t, INTER, HID);
        gemm_tf32<128, 2><<<grid_n4k, 256, SMEM128>>>(p_hn, uw, p_t, p_t, INTER, HID);

        float* dst = (l == NLAYERS - 1) ? out : p_x;
        gemm_tf32<64, 1><<<grid_n1k, 256, SMEM64>>>(p_t, dw, p_h2, dst, HID, INTER);
    }
}

// round 8
// speedup vs baseline: 9.8995x; 1.7467x over previous
#include <cuda_runtime.h>
#include <cuda_fp16.h>
#include <math.h>
#include <stdint.h>

// ---------------- problem constants ----------------------------------------
#define S_TOK 1536
#define S0    1024
#define HID   1024
#define HEADS 16
#define HD    64
#define INTER 4096
#define NLAYERS 4
#define KPATCH 768

// ---------------- scratch ---------------------------------------------------
// fp32 residual stream
__device__ float g_x [S_TOK * HID];
__device__ float g_h2[S_TOK * HID];
__device__ float g_cos[S_TOK * HD];
__device__ float g_sin[S_TOK * HD];
// fp16 activations
__device__ __half a_xpatch[S_TOK * KPATCH];
__device__ __half a_hn[S_TOK * HID];
__device__ __half a_q [S_TOK * HID];
__device__ __half a_k [S_TOK * HID];
__device__ __half a_v [S_TOK * HID];
__device__ __half a_ao[S_TOK * HID];
__device__ __half a_t [S_TOK * INTER];
// fp16 weights (converted once per launch)
__device__ __half h_wconv[HID * KPATCH];
__device__ __half h_wq[NLAYERS * HID * HID];
__device__ __half h_wk[NLAYERS * HID * HID];
__device__ __half h_wv[NLAYERS * HID * HID];
__device__ __half h_wo[NLAYERS * HID * HID];
__device__ __half h_wg[NLAYERS * INTER * HID];
__device__ __half h_wu[NLAYERS * INTER * HID];
__device__ __half h_wd[NLAYERS * HID * INTER];

// ---------------- helpers ----------------------------------------------------
__device__ __forceinline__ uint32_t smem_u32(const void* p) {
    return (uint32_t)__cvta_generic_to_shared(p);
}
__device__ __forceinline__ void mma_f16(float c[4], const uint32_t a[4],
                                        uint32_t b0, uint32_t b1) {
    asm volatile(
        "mma.sync.aligned.m16n8k16.row.col.f32.f16.f16.f32 "
        "{%0,%1,%2,%3},{%4,%5,%6,%7},{%8,%9},{%0,%1,%2,%3};"
        : "+f"(c[0]), "+f"(c[1]), "+f"(c[2]), "+f"(c[3])
        : "r"(a[0]), "r"(a[1]), "r"(a[2]), "r"(a[3]), "r"(b0), "r"(b1));
}
__device__ __forceinline__ void ldm_x4(uint32_t& r0, uint32_t& r1, uint32_t& r2, uint32_t& r3,
                                       uint32_t addr) {
    asm volatile("ldmatrix.sync.aligned.m8n8.x4.shared.b16 {%0,%1,%2,%3}, [%4];"
                 : "=r"(r0), "=r"(r1), "=r"(r2), "=r"(r3) : "r"(addr));
}
__device__ __forceinline__ void ldm_x4t(uint32_t& r0, uint32_t& r1, uint32_t& r2, uint32_t& r3,
                                        uint32_t addr) {
    asm volatile("ldmatrix.sync.aligned.m8n8.x4.trans.shared.b16 {%0,%1,%2,%3}, [%4];"
                 : "=r"(r0), "=r"(r1), "=r"(r2), "=r"(r3) : "r"(addr));
}
__device__ __forceinline__ void cp16(void* smem_dst, const void* gsrc) {
    uint32_t d = (uint32_t)__cvta_generic_to_shared(smem_dst);
    asm volatile("cp.async.cg.shared.global [%0], [%1], 16;\n" :: "r"(d), "l"(gsrc));
}
#define CP_COMMIT() asm volatile("cp.async.commit_group;\n" ::: "memory")
#define CP_WAIT0()  asm volatile("cp.async.wait_group 0;\n" ::: "memory")
#define CP_WAIT1()  asm volatile("cp.async.wait_group 1;\n" ::: "memory")
#define CP_WAIT2()  asm volatile("cp.async.wait_group 2;\n" ::: "memory")

// ---------------- weight fp32 -> fp16 ----------------------------------------
__global__ void f2h_kernel(const float* __restrict__ x, __half* __restrict__ y, int n4) {
    int i = blockIdx.x * blockDim.x + threadIdx.x;
    if (i >= n4) return;
    float4 v = ((const float4*)x)[i];
    __half2* y2 = (__half2*)y;
    y2[2 * i + 0] = __floats2half2_rn(v.x, v.y);
    y2[2 * i + 1] = __floats2half2_rn(v.z, v.w);
}

// ---------------- im2col (fp16 out) -------------------------------------------
__global__ void im2col_kernel(const float* __restrict__ img0,
                              const float* __restrict__ img1) {
    int idx = blockIdx.x * blockDim.x + threadIdx.x;
    if (idx >= S_TOK * KPATCH) return;
    int s = idx / KPATCH;
    int r = idx - s * KPATCH;
    int c  = r >> 8;
    int kh = (r >> 4) & 15;
    int kw = r & 15;
    float val;
    if (s < S0) {
        int ph = s >> 5, pw = s & 31;
        val = img0[c * 512 * 512 + (ph * 16 + kh) * 512 + (pw * 16 + kw)];
    } else {
        int sp = s - S0;
        int ph = sp >> 4, pw = sp & 15;
        val = img1[c * 512 * 256 + (ph * 16 + kh) * 256 + (pw * 16 + kw)];
    }
    a_xpatch[idx] = __float2half(val);
}

// ---------------- RoPE table ---------------------------------------------------
__global__ void rope_table_kernel() {
    int s = blockIdx.x;
    int d = threadIdx.x;  // 0..63
    int ph, pw;
    if (s < S0) { ph = s >> 5; pw = s & 31; }
    else        { int sp = s - S0; ph = sp >> 4; pw = sp & 15; }
    int j = d & 31;
    float e, base;
    if (j < 16) { e = (4.0f * j) / 64.0f;               base = (float)ph; }
    else        { e = (2.0f + 4.0f * (j - 16)) / 64.0f; base = (float)pw; }
    float f = base * expf(-e * 9.2103403719761836f);
    g_cos[s * HD + d] = cosf(f);
    g_sin[s * HD + d] = sinf(f);
}

// ---------------- RMSNorm: fp32 in, fp32 or fp16 out ---------------------------
template<bool OUT_HALF>
__global__ void rms_kernel(const float* __restrict__ x,
                           const float* __restrict__ w,
                           void* __restrict__ yv) {
    int s = blockIdx.x;
    int tid = threadIdx.x;  // 256
    const float* xr = x + s * HID;
    float ss = 0.f;
    #pragma unroll 4
    for (int i = tid; i < HID; i += 256) { float v = xr[i]; ss += v * v; }
    __shared__ float sh[8];
    #pragma unroll
    for (int o = 16; o > 0; o >>= 1) ss += __shfl_xor_sync(0xffffffffu, ss, o);
    if ((tid & 31) == 0) sh[tid >> 5] = ss;
    __syncthreads();
    if (tid < 8) {
        float v = sh[tid];
        #pragma unroll
        for (int o = 4; o > 0; o >>= 1) v += __shfl_xor_sync(0xffu, v, o);
        if (tid == 0) sh[0] = v;
    }
    __syncthreads();
    float r = rsqrtf(sh[0] * (1.0f / HID) + 1e-5f);
    if (OUT_HALF) {
        __half* y = (__half*)yv;
        for (int i = tid; i < HID; i += 256) y[s * HID + i] = __float2half(xr[i] * r * w[i]);
    } else {
        float* y = (float*)yv;
        for (int i = tid; i < HID; i += 256) y[s * HID + i] = xr[i] * r * w[i];
    }
}

// ---------------- fp16 tensor-core GEMM (m16n8k16, ldmatrix, BK=64) ------------
// C[M,N] = A[M,K] @ B[N,K]^T, A/B fp16. 256 threads (2m x 4n warps), 3-stage.
// EPI: 0=plain, 1=+aux(fp32 residual), 2=silu(aux half)*acc
// OUT_HALF: C is __half else float.
#define SROWH 72   // halves per smem row (64 data + 8 pad)

template<int BM, int EPI, bool OUT_HALF>
__device__ __forceinline__ void gemm_body(
    const __half* __restrict__ A, const __half* __restrict__ B,
    const void* __restrict__ auxp, void* __restrict__ Cp,
    int N, int K, __half* tiles)
{
    constexpr int MT = BM / 32;
    constexpr int ASTG = BM * SROWH;
    constexpr int BSTG = 128 * SROWH;
    constexpr int STG  = ASTG + BSTG;

    int tid = threadIdx.x;
    int warp = tid >> 5, lane = tid & 31;
    int gid = lane >> 2, tig = lane & 3;
    int g8 = lane >> 3, r8 = lane & 7;
    int wm = warp >> 2, wn = warp & 3;
    int m0 = blockIdx.y * BM, n0 = blockIdx.x * 128;

    float acc[MT][4][4];
    #pragma unroll
    for (int i = 0; i < MT; i++)
        #pragma unroll
        for (int j = 0; j < 4; j++)
            #pragma unroll
            for (int l = 0; l < 4; l++) acc[i][j][l] = 0.f;

    const int KT = K >> 6;                 // BK=64 halves
    constexpr int NCH = (BM + 128) * 8;    // 16B chunks per stage

    auto load_stage = [&](int kt, int s) {
        int k0 = kt << 6;
        __half* As = tiles + s * STG;
        __half* Bs = As + ASTG;
        #pragma unroll
        for (int i = tid; i < NCH; i += 256) {
            int r = i >> 3, c = (i & 7) << 3;   // c in halves
            if (r < BM) cp16(&As[r * SROWH + c], &A[(size_t)(m0 + r) * K + k0 + c]);
            else {
                int rb = r - BM;
                cp16(&Bs[rb * SROWH + c], &B[(size_t)(n0 + rb) * K + k0 + c]);
            }
        }
        CP_COMMIT();
    };

    uint32_t a_off[MT], b_off[2];
    #pragma unroll
    for (int i = 0; i < MT; i++)
        a_off[i] = (uint32_t)(((wm * (BM / 2) + i * 16 + (g8 & 1) * 8 + r8) * SROWH) * 2
                              + (g8 >> 1) * 16);
    #pragma unroll
    for (int jj = 0; jj < 2; jj++)
        b_off[jj] = (uint32_t)(ASTG * 2 + ((wn * 32 + jj * 16 + (g8 >> 1) * 8 + r8) * SROWH) * 2
                               + (g8 & 1) * 16);

    load_stage(0, 0);
    load_stage(1, 1);

    for (int kt = 0; kt < KT; kt++) {
        int s = kt % 3;
        if (kt + 2 < KT) { load_stage(kt + 2, (kt + 2) % 3); CP_WAIT2(); }
        else if (kt + 2 == KT) { CP_WAIT1(); }
        else { CP_WAIT0(); }
        __syncthreads();
        uint32_t base = smem_u32(tiles + s * STG);
        #pragma unroll
        for (int ks = 0; ks < 4; ks++) {       // 4 x k16 = 64
            uint32_t kofs = base + ks * 32;    // 16 halves = 32B
            uint32_t af[MT][4];
            #pragma unroll
            for (int i = 0; i < MT; i++)
                ldm_x4(af[i][0], af[i][1], af[i][2], af[i][3], kofs + a_off[i]);
            uint32_t bf[4][2];
            #pragma unroll
            for (int jj = 0; jj < 2; jj++) {
                uint32_t m0r, m1r, m2r, m3r;
                ldm_x4(m0r, m1r, m2r, m3r, kofs + b_off[jj]);
                bf[2 * jj + 0][0] = m0r; bf[2 * jj + 0][1] = m1r;
                bf[2 * jj + 1][0] = m2r; bf[2 * jj + 1][1] = m3r;
            }
            #pragma unroll
            for (int i = 0; i < MT; i++)
                #pragma unroll
                for (int j = 0; j < 4; j++)
                    mma_f16(acc[i][j], af[i], bf[j][0], bf[j][1]);
        }
        __syncthreads();
    }

    const float* auxf = (const float*)auxp;
    const __half* auxh = (const __half*)auxp;
    #pragma unroll
    for (int i = 0; i < MT; i++) {
        #pragma unroll
        for (int j = 0; j < 4; j++) {
            int m = m0 + wm * (BM / 2) + i * 16 + gid;
            int n = n0 + wn * 32 + j * 8 + 2 * tig;
            #pragma unroll
            for (int hh = 0; hh < 2; hh++) {
                int mm = m + hh * 8;
                float v0 = acc[i][j][hh * 2 + 0];
                float v1 = acc[i][j][hh * 2 + 1];
                size_t off = (size_t)mm * N + n;
                if (EPI == 1) {
                    v0 += auxf[off]; v1 += auxf[off + 1];
                } else if (EPI == 2) {
                    float g0 = __half2float(auxh[off]);
                    float g1 = __half2float(auxh[off + 1]);
                    v0 = v0 * g0 / (1.0f + __expf(-g0));
                    v1 = v1 * g1 / (1.0f + __expf(-g1));
                }
                if (OUT_HALF) {
                    *(__half2*)&((__half*)Cp)[off] = __floats2half2_rn(v0, v1);
                } else {
                    float2 o2; o2.x = v0; o2.y = v1;
                    *(float2*)&((float*)Cp)[off] = o2;
                }
            }
        }
    }
}

template<int BM, int EPI, bool OUT_HALF>
__global__ void __launch_bounds__(256) gemm_f16(
    const __half* __restrict__ A, const __half* __restrict__ B,
    const void* __restrict__ aux, void* __restrict__ C, int N, int K)
{
    extern __shared__ __half tiles[];
    gemm_body<BM, EPI, OUT_HALF>(A, B, aux, C, N, K, tiles);
}

__global__ void __launch_bounds__(256) gemm_qkv(
    const __half* __restrict__ A,
    const __half* __restrict__ B0, const __half* __restrict__ B1, const __half* __restrict__ B2,
    __half* __restrict__ C0, __half* __restrict__ C1, __half* __restrict__ C2, int K)
{
    extern __shared__ __half tiles[];
    const __half* B = (blockIdx.z == 0) ? B0 : (blockIdx.z == 1) ? B1 : B2;
    __half*       C = (blockIdx.z == 0) ? C0 : (blockIdx.z == 1) ? C1 : C2;
    gemm_body<64, 0, true>(A, B, nullptr, C, HID, K, tiles);
}

// ---------------- RoPE apply (fp16 in/out) --------------------------------------
__global__ void rope_kernel(__half* __restrict__ q, __half* __restrict__ k) {
    int idx = blockIdx.x * blockDim.x + threadIdx.x;
    if (idx >= S_TOK * HEADS * 32) return;
    int d = idx & 31;
    int h = (idx >> 5) & 15;
    int s = idx >> 9;
    float c  = g_cos[s * HD + d];
    float sn = g_sin[s * HD + d];
    int base = s * HID + h * HD;
    float q0 = __half2float(q[base + d]), q1 = __half2float(q[base + d + 32]);
    q[base + d]      = __float2half(q0 * c - q1 * sn);
    q[base + d + 32] = __float2half(q1 * c + q0 * sn);
    float k0 = __half2float(k[base + d]), k1 = __half2float(k[base + d + 32]);
    k[base + d]      = __float2half(k0 * c - k1 * sn);
    k[base + d + 32] = __float2half(k1 * c + k0 * sn);
}

// ---------------- fp16 tensor-core flash attention --------------------------------
// grid (24 qtiles, 16 heads), 256 threads (8 warps = 4m x 2n).
// S = Q@K^T via m16n8k16 into fp32 smem; cooperative online softmax; P (half)
// re-read via ldmatrix; PV with V via ldmatrix.trans.
#define SP 68   // score row stride (floats)

__global__ void __launch_bounds__(256) attn_mma_kernel(
    const __half* __restrict__ q, const __half* __restrict__ k,
    const __half* __restrict__ v, __half* __restrict__ o)
{
    extern __shared__ char smraw[];
    __half* Qs = (__half*)smraw;          // 64 x SROWH
    __half* Ks = Qs + 64 * SROWH;
    __half* Vs = Ks + 64 * SROWH;
    __half* Ps = Vs + 64 * SROWH;
    float*  Ss = (float*)(Ps + 64 * SROWH);   // 64 x SP
    float*  Al = Ss + 64 * SP;
    float*  Ll = Al + 64;

    int qt = blockIdx.x, h = blockIdx.y;
    int s0 = qt * 64;
    int key0 = (s0 < S0) ? 0 : S0;
    int nkt  = (s0 < S0) ? 16 : 8;

    int tid = threadIdx.x;
    int warp = tid >> 5, lane = tid & 31;
    int gid = lane >> 2, tig = lane & 3;
    int g8 = lane >> 3, r8 = lane & 7;
    int wm = warp >> 1, wn = warp & 1;
    int qq = tid >> 2, kg = tid & 3;

    // load Q (resident): 64 rows x 64 halves
    for (int i = tid; i < 512; i += 256) {
        int r = i >> 3, c = (i & 7) << 3;
        cp16(&Qs[r * SROWH + c], &q[(size_t)(s0 + r) * HID + h * HD + c]);
    }
    CP_COMMIT();

    float m_prev = -1e30f, lsum = 0.f;
    float oacc[4][4];
    #pragma unroll
    for (int j = 0; j < 4; j++)
        #pragma unroll
        for (int l = 0; l < 4; l++) oacc[j][l] = 0.f;

    int arow0 = wm * 16 + gid;   // C-fragment rows: arow0, arow0+8

    // ldmatrix byte offsets
    uint32_t qa_off = (uint32_t)(((wm * 16 + (g8 & 1) * 8 + r8) * SROWH) * 2 + (g8 >> 1) * 16);
    uint32_t kb_off[2];
    #pragma unroll
    for (int jj = 0; jj < 2; jj++)
        kb_off[jj] = (uint32_t)(((wn * 32 + jj * 16 + (g8 >> 1) * 8 + r8) * SROWH) * 2
                                + (g8 & 1) * 16);

    uint32_t qbase = smem_u32(Qs);
    uint32_t kbase = smem_u32(Ks);
    uint32_t vbase = smem_u32(Vs);
    uint32_t pbase = smem_u32(Ps);

    for (int kt = 0; kt < nkt; kt++) {
        for (int i = tid; i < 1024; i += 256) {
            int half_sel = i >> 9;          // 0 = K, 1 = V
            int i2 = i & 511;
            int r = i2 >> 3, c = (i2 & 7) << 3;
            size_t g = (size_t)(key0 + kt * 64 + r) * HID + h * HD + c;
            if (half_sel == 0) cp16(&Ks[r * SROWH + c], &k[g]);
            else               cp16(&Vs[r * SROWH + c], &v[g]);
        }
        CP_COMMIT();
        CP_WAIT0();
        __syncthreads();

        // S = Q @ K^T : warp tile 16q x 32keys
        float sc[4][4];
        #pragma unroll
        for (int j = 0; j < 4; j++)
            #pragma unroll
            for (int l = 0; l < 4; l++) sc[j][l] = 0.f;
        #pragma unroll
        for (int ks = 0; ks < 4; ks++) {    // d = 4 x 16
            uint32_t kofs = ks * 32;
            uint32_t aq[4];
            ldm_x4(aq[0], aq[1], aq[2], aq[3], qbase + kofs + qa_off);
            uint32_t bf[4][2];
            #pragma unroll
            for (int jj = 0; jj < 2; jj++) {
                uint32_t m0r, m1r, m2r, m3r;
                ldm_x4(m0r, m1r, m2r, m3r, kbase + kofs + kb_off[jj]);
                bf[2 * jj + 0][0] = m0r; bf[2 * jj + 0][1] = m1r;
                bf[2 * jj + 1][0] = m2r; bf[2 * jj + 1][1] = m3r;
            }
            #pragma unroll
            for (int j = 0; j < 4; j++)
                mma_f16(sc[j], aq, bf[j][0], bf[j][1]);
        }
        #pragma unroll
        for (int j = 0; j < 4; j++) {
            int cn = wn * 32 + j * 8 + 2 * tig;
            Ss[arow0 * SP + cn]           = sc[j][0] * 0.125f;
            Ss[arow0 * SP + cn + 1]       = sc[j][1] * 0.125f;
            Ss[(arow0 + 8) * SP + cn]     = sc[j][2] * 0.125f;
            Ss[(arow0 + 8) * SP + cn + 1] = sc[j][3] * 0.125f;
        }
        __syncthreads();

        // online softmax: row qq, cols kg*16..+15 ; write P as half
        {
            float e[16];
            int base = qq * SP + kg * 16;
            float mloc = -1e30f;
            #pragma unroll
            for (int i = 0; i < 16; i++) { e[i] = Ss[base + i]; mloc = fmaxf(mloc, e[i]); }
            mloc = fmaxf(mloc, __shfl_xor_sync(0xffffffffu, mloc, 1));
            mloc = fmaxf(mloc, __shfl_xor_sync(0xffffffffu, mloc, 2));
            float m_new = fmaxf(m_prev, mloc);
            float alpha = __expf(m_prev - m_new);
            float lrow = 0.f;
            int pb = qq * SROWH + kg * 16;
            #pragma unroll
            for (int i = 0; i < 16; i += 2) {
                float e0 = __expf(e[i]     - m_new);
                float e1 = __expf(e[i + 1] - m_new);
                lrow += e0 + e1;
                *(__half2*)&Ps[pb + i] = __floats2half2_rn(e0, e1);
            }
            lrow += __shfl_xor_sync(0xffffffffu, lrow, 1);
            lrow += __shfl_xor_sync(0xffffffffu, lrow, 2);
            lsum = lsum * alpha + lrow;
            m_prev = m_new;
            if (kg == 0) Al[qq] = alpha;
        }
        __syncthreads();

        // rescale O
        float a_r0 = Al[arow0], a_r1 = Al[arow0 + 8];
        #pragma unroll
        for (int j = 0; j < 4; j++) {
            oacc[j][0] *= a_r0; oacc[j][1] *= a_r0;
            oacc[j][2] *= a_r1; oacc[j][3] *= a_r1;
        }

        // O += P @ V : A = P (ldmatrix), B = V (ldmatrix.trans)
        #pragma unroll
        for (int ks = 0; ks < 4; ks++) {    // keys = 4 x 16
            uint32_t ap[4];
            ldm_x4(ap[0], ap[1], ap[2], ap[3], pbase + ks * 32 + qa_off);
            uint32_t vf[4][2];
            #pragma unroll
            for (int jj = 0; jj < 2; jj++) {
                // V rows = key (ks*16 + ...), cols = d (wn*32 + jj*16 ...)
                uint32_t addr = vbase
                    + (uint32_t)(((ks * 16 + (g8 & 1) * 8 + r8) * SROWH) * 2
                                 + (wn * 32 + jj * 16) * 2 + (g8 >> 1) * 16);
                uint32_t m0r, m1r, m2r, m3r;
                ldm_x4t(m0r, m1r, m2r, m3r, addr);
                vf[2 * jj + 0][0] = m0r; vf[2 * jj + 0][1] = m1r;
                vf[2 * jj + 1][0] = m2r; vf[2 * jj + 1][1] = m3r;
            }
            #pragma unroll
            for (int j = 0; j < 4; j++)
                mma_f16(oacc[j], ap, vf[j][0], vf[j][1]);
        }
        __syncthreads();
    }

    if (kg == 0) Ll[qq] = lsum;
    __syncthreads();
    float inv0 = 1.0f / Ll[arow0];
    float inv1 = 1.0f / Ll[arow0 + 8];
    #pragma unroll
    for (int j = 0; j < 4; j++) {
        int cn = wn * 32 + j * 8 + 2 * tig;
        size_t o0 = (size_t)(s0 + arow0) * HID + h * HD + cn;
        size_t o1 = (size_t)(s0 + arow0 + 8) * HID + h * HD + cn;
        *(__half2*)&o[o0] = __floats2half2_rn(oacc[j][0] * inv0, oacc[j][1] * inv0);
        *(__half2*)&o[o1] = __floats2half2_rn(oacc[j][2] * inv1, oacc[j][3] * inv1);
    }
}

// ---------------- host orchestration ---------------------------------------------
extern "C" void kernel_launch(void* const* d_in, const int* in_sizes, int n_in,
                              void* d_out, int out_size) {
    const float* img0        = (const float*)d_in[0];
    const float* img1        = (const float*)d_in[1];
    const float* conv_w      = (const float*)d_in[2];
    const float* ln_pre_w    = (const float*)d_in[3];
    const float* attn_norm_w = (const float*)d_in[4];
    const float* q_w         = (const float*)d_in[5];
    const float* k_w         = (const float*)d_in[6];
    const float* v_w         = (const float*)d_in[7];
    const float* o_w         = (const float*)d_in[8];
    const float* ffn_norm_w  = (const float*)d_in[9];
    const float* gate_w      = (const float*)d_in[10];
    const float* up_w        = (const float*)d_in[11];
    const float* down_w      = (const float*)d_in[12];
    float* out = (float*)d_out;

    float *p_x, *p_h2;
    __half *p_xpatch, *p_hn, *p_q, *p_k, *p_v, *p_ao, *p_t;
    __half *p_wconv, *p_wq, *p_wk, *p_wv, *p_wo, *p_wg, *p_wu, *p_wd;
    cudaGetSymbolAddress((void**)&p_x,  g_x);
    cudaGetSymbolAddress((void**)&p_h2, g_h2);
    cudaGetSymbolAddress((void**)&p_xpatch, a_xpatch);
    cudaGetSymbolAddress((void**)&p_hn, a_hn);
    cudaGetSymbolAddress((void**)&p_q,  a_q);
    cudaGetSymbolAddress((void**)&p_k,  a_k);
    cudaGetSymbolAddress((void**)&p_v,  a_v);
    cudaGetSymbolAddress((void**)&p_ao, a_ao);
    cudaGetSymbolAddress((void**)&p_t,  a_t);
    cudaGetSymbolAddress((void**)&p_wconv, h_wconv);
    cudaGetSymbolAddress((void**)&p_wq, h_wq);
    cudaGetSymbolAddress((void**)&p_wk, h_wk);
    cudaGetSymbolAddress((void**)&p_wv, h_wv);
    cudaGetSymbolAddress((void**)&p_wo, h_wo);
    cudaGetSymbolAddress((void**)&p_wg, h_wg);
    cudaGetSymbolAddress((void**)&p_wu, h_wu);
    cudaGetSymbolAddress((void**)&p_wd, h_wd);

    const int SMEM64  = 3 * (64  + 128) * SROWH * 2;   // 82944
    const int SMEM128 = 3 * (128 + 128) * SROWH * 2;   // 110592
    const int ASMEM   = 4 * 64 * SROWH * 2 + 64 * SP * 4 + 2 * 64 * 4;  // 54784
    cudaFuncSetAttribute((const void*)gemm_f16<64, 0, false>, cudaFuncAttributeMaxDynamicSharedMemorySize, SMEM64);
    cudaFuncSetAttribute((const void*)gemm_f16<64, 1, false>, cudaFuncAttributeMaxDynamicSharedMemorySize, SMEM64);
    cudaFuncSetAttribute((const void*)gemm_f16<128, 0, true>, cudaFuncAttributeMaxDynamicSharedMemorySize, SMEM128);
    cudaFuncSetAttribute((const void*)gemm_f16<128, 2, true>, cudaFuncAttributeMaxDynamicSharedMemorySize, SMEM128);
    cudaFuncSetAttribute((const void*)gemm_qkv,               cudaFuncAttributeMaxDynamicSharedMemorySize, SMEM64);
    cudaFuncSetAttribute((const void*)attn_mma_kernel,        cudaFuncAttributeMaxDynamicSharedMemorySize, ASMEM);

    // convert all weights fp32 -> fp16 (once per launch; deterministic)
    {
        auto cvt = [&](const float* src, __half* dst, int n) {
            f2h_kernel<<<(n / 4 + 255) / 256, 256>>>(src, dst, n / 4);
        };
        cvt(conv_w, p_wconv, HID * KPATCH);
        cvt(q_w,    p_wq, NLAYERS * HID * HID);
        cvt(k_w,    p_wk, NLAYERS * HID * HID);
        cvt(v_w,    p_wv, NLAYERS * HID * HID);
        cvt(o_w,    p_wo, NLAYERS * HID * HID);
        cvt(gate_w, p_wg, NLAYERS * INTER * HID);
        cvt(up_w,   p_wu, NLAYERS * INTER * HID);
        cvt(down_w, p_wd, NLAYERS * HID * INTER);
    }

    dim3 grid_n1k(HID / 128, S_TOK / 64);       // (8, 24)   BM=64
    dim3 grid_qkv(HID / 128, S_TOK / 64, 3);    // (8, 24, 3)
    dim3 grid_n4k(INTER / 128, S_TOK / 128);    // (32, 12)  BM=128

    // patch embed (fp32 output to residual stream)
    im2col_kernel<<<(S_TOK * KPATCH + 255) / 256, 256>>>(img0, img1);
    gemm_f16<64, 0, false><<<grid_n1k, 256, SMEM64>>>(p_xpatch, p_wconv, nullptr, p_h2, HID, KPATCH);

    rms_kernel<false><<<S_TOK, 256>>>(p_h2, ln_pre_w, p_x);
    rope_table_kernel<<<S_TOK, 64>>>();

    for (int l = 0; l < NLAYERS; l++) {
        const __half* qw = p_wq + (size_t)l * HID * HID;
        const __half* kw = p_wk + (size_t)l * HID * HID;
        const __half* vw = p_wv + (size_t)l * HID * HID;
        const __half* ow = p_wo + (size_t)l * HID * HID;
        const __half* gw = p_wg + (size_t)l * INTER * HID;
        const __half* uw = p_wu + (size_t)l * INTER * HID;
        const __half* dw = p_wd + (size_t)l * HID * INTER;

        rms_kernel<true><<<S_TOK, 256>>>(p_x, attn_norm_w + l * HID, p_hn);

        gemm_qkv<<<grid_qkv, 256, SMEM64>>>(p_hn, qw, kw, vw, p_q, p_k, p_v, HID);

        rope_kernel<<<(S_TOK * HEADS * 32 + 255) / 256, 256>>>(p_q, p_k);

        attn_mma_kernel<<<dim3(S_TOK / 64, HEADS), 256, ASMEM>>>(p_q, p_k, p_v, p_ao);

        // O-proj + residual -> fp32 h2
        gemm_f16<64, 1, false><<<grid_n1k, 256, SMEM64>>>(p_ao, ow, p_x, p_h2, HID, HID);

        rms_kernel<true><<<S_TOK, 256>>>(p_h2, ffn_norm_w + l * HID, p_hn);

        // gate (plain half), then up with silu(gate)*up epilogue (in-place t)
        gemm_f16<128, 0, true><<<grid_n4k, 256, SMEM128>>>(p_hn, gw, nullptr, p_t, INTER, HID);
        gemm_f16<128, 2, true><<<grid_n4k, 256, SMEM128>>>(p_hn, uw, p_t, p_t, INTER, HID);

        // down + residual -> fp32 (last layer straight to d_out)
        float* dst = (l == NLAYERS - 1) ? out : p_x;
        gemm_f16<64, 1, false><<<grid_n1k, 256, SMEM64>>>(p_t, dw, p_h2, dst, HID, INTER);
    }
}

// round 9
// speedup vs baseline: 9.9478x; 1.0049x over previous
#include <cuda_runtime.h>
#include <cuda_fp16.h>
#include <math.h>
#include <stdint.h>

// ---------------- problem constants ----------------------------------------
#define S_TOK 1536
#define S0    1024
#define HID   1024
#define HEADS 16
#define HD    64
#define INTER 4096
#define NLAYERS 4
#define KPATCH 768

// ---------------- scratch ---------------------------------------------------
__device__ float g_x [S_TOK * HID];
__device__ float g_h2[S_TOK * HID];
__device__ float g_cos[S_TOK * HD];
__device__ float g_sin[S_TOK * HD];
__device__ __half a_xpatch[S_TOK * KPATCH];
__device__ __half a_hn[S_TOK * HID];
__device__ __half a_q [S_TOK * HID];
__device__ __half a_k [S_TOK * HID];
__device__ __half a_v [S_TOK * HID];
__device__ __half a_ao[S_TOK * HID];
__device__ __half a_t [S_TOK * INTER];
__device__ __half h_wconv[HID * KPATCH];
__device__ __half h_wq[NLAYERS * HID * HID];
__device__ __half h_wk[NLAYERS * HID * HID];
__device__ __half h_wv[NLAYERS * HID * HID];
__device__ __half h_wo[NLAYERS * HID * HID];
__device__ __half h_wg[NLAYERS * INTER * HID];
__device__ __half h_wu[NLAYERS * INTER * HID];
__device__ __half h_wd[NLAYERS * HID * INTER];

// ---------------- helpers ----------------------------------------------------
__device__ __forceinline__ uint32_t smem_u32(const void* p) {
    return (uint32_t)__cvta_generic_to_shared(p);
}
__device__ __forceinline__ void mma_f16(float c[4], const uint32_t a[4],
                                        uint32_t b0, uint32_t b1) {
    asm volatile(
        "mma.sync.aligned.m16n8k16.row.col.f32.f16.f16.f32 "
        "{%0,%1,%2,%3},{%4,%5,%6,%7},{%8,%9},{%0,%1,%2,%3};"
        : "+f"(c[0]), "+f"(c[1]), "+f"(c[2]), "+f"(c[3])
        : "r"(a[0]), "r"(a[1]), "r"(a[2]), "r"(a[3]), "r"(b0), "r"(b1));
}
__device__ __forceinline__ void ldm_x4(uint32_t& r0, uint32_t& r1, uint32_t& r2, uint32_t& r3,
                                       uint32_t addr) {
    asm volatile("ldmatrix.sync.aligned.m8n8.x4.shared.b16 {%0,%1,%2,%3}, [%4];"
                 : "=r"(r0), "=r"(r1), "=r"(r2), "=r"(r3) : "r"(addr));
}
__device__ __forceinline__ void ldm_x4t(uint32_t& r0, uint32_t& r1, uint32_t& r2, uint32_t& r3,
                                        uint32_t addr) {
    asm volatile("ldmatrix.sync.aligned.m8n8.x4.trans.shared.b16 {%0,%1,%2,%3}, [%4];"
                 : "=r"(r0), "=r"(r1), "=r"(r2), "=r"(r3) : "r"(addr));
}
__device__ __forceinline__ void cp16(void* smem_dst, const void* gsrc) {
    uint32_t d = (uint32_t)__cvta_generic_to_shared(smem_dst);
    asm volatile("cp.async.cg.shared.global [%0], [%1], 16;\n" :: "r"(d), "l"(gsrc));
}
#define CP_COMMIT() asm volatile("cp.async.commit_group;\n" ::: "memory")
#define CP_WAIT0()  asm volatile("cp.async.wait_group 0;\n" ::: "memory")
#define CP_WAIT1()  asm volatile("cp.async.wait_group 1;\n" ::: "memory")

// ---------------- weight fp32 -> fp16 (16B stores) -----------------------------
__global__ void f2h_kernel(const float* __restrict__ x, __half* __restrict__ y, int n8) {
    int i = blockIdx.x * blockDim.x + threadIdx.x;
    if (i >= n8) return;
    float4 v0 = ((const float4*)x)[2 * i + 0];
    float4 v1 = ((const float4*)x)[2 * i + 1];
    __half2 h0 = __floats2half2_rn(v0.x, v0.y);
    __half2 h1 = __floats2half2_rn(v0.z, v0.w);
    __half2 h2 = __floats2half2_rn(v1.x, v1.y);
    __half2 h3 = __floats2half2_rn(v1.z, v1.w);
    uint4 u;
    u.x = *(uint32_t*)&h0; u.y = *(uint32_t*)&h1;
    u.z = *(uint32_t*)&h2; u.w = *(uint32_t*)&h3;
    ((uint4*)y)[i] = u;
}

// ---------------- im2col (fp16 out) -------------------------------------------
__global__ void im2col_kernel(const float* __restrict__ img0,
                              const float* __restrict__ img1) {
    int idx = blockIdx.x * blockDim.x + threadIdx.x;
    if (idx >= S_TOK * KPATCH) return;
    int s = idx / KPATCH;
    int r = idx - s * KPATCH;
    int c  = r >> 8;
    int kh = (r >> 4) & 15;
    int kw = r & 15;
    float val;
    if (s < S0) {
        int ph = s >> 5, pw = s & 31;
        val = img0[c * 512 * 512 + (ph * 16 + kh) * 512 + (pw * 16 + kw)];
    } else {
        int sp = s - S0;
        int ph = sp >> 4, pw = sp & 15;
        val = img1[c * 512 * 256 + (ph * 16 + kh) * 256 + (pw * 16 + kw)];
    }
    a_xpatch[idx] = __float2half(val);
}

// ---------------- RoPE table ---------------------------------------------------
__global__ void rope_table_kernel() {
    int s = blockIdx.x;
    int d = threadIdx.x;  // 0..63
    int ph, pw;
    if (s < S0) { ph = s >> 5; pw = s & 31; }
    else        { int sp = s - S0; ph = sp >> 4; pw = sp & 15; }
    int j = d & 31;
    float e, base;
    if (j < 16) { e = (4.0f * j) / 64.0f;               base = (float)ph; }
    else        { e = (2.0f + 4.0f * (j - 16)) / 64.0f; base = (float)pw; }
    float f = base * expf(-e * 9.2103403719761836f);
    g_cos[s * HD + d] = cosf(f);
    g_sin[s * HD + d] = sinf(f);
}

// ---------------- RMSNorm: fp32 in, fp32 or fp16 out ---------------------------
template<bool OUT_HALF>
__global__ void rms_kernel(const float* __restrict__ x,
                           const float* __restrict__ w,
                           void* __restrict__ yv) {
    int s = blockIdx.x;
    int tid = threadIdx.x;  // 256
    const float* xr = x + s * HID;
    float ss = 0.f;
    #pragma unroll 4
    for (int i = tid; i < HID; i += 256) { float v = xr[i]; ss += v * v; }
    __shared__ float sh[8];
    #pragma unroll
    for (int o = 16; o > 0; o >>= 1) ss += __shfl_xor_sync(0xffffffffu, ss, o);
    if ((tid & 31) == 0) sh[tid >> 5] = ss;
    __syncthreads();
    if (tid < 8) {
        float v = sh[tid];
        #pragma unroll
        for (int o = 4; o > 0; o >>= 1) v += __shfl_xor_sync(0xffu, v, o);
        if (tid == 0) sh[0] = v;
    }
    __syncthreads();
    float r = rsqrtf(sh[0] * (1.0f / HID) + 1e-5f);
    if (OUT_HALF) {
        __half* y = (__half*)yv;
        for (int i = tid; i < HID; i += 256) y[s * HID + i] = __float2half(xr[i] * r * w[i]);
    } else {
        float* y = (float*)yv;
        for (int i = tid; i < HID; i += 256) y[s * HID + i] = xr[i] * r * w[i];
    }
}

// ---------------- fp16 GEMM (m16n8k16, ldmatrix, BK=64, single-barrier) --------
// C[M,N] = A[M,K] @ B[N,K]^T. 64x128 tile, 256 threads (2m x 4n warps), 3-stage.
// EPI: 0=plain, 1=+aux(fp32 residual)   OUT_HALF: C half else float
#define SROWH 72   // halves per smem row (64 data + 8 pad)

template<int EPI, bool OUT_HALF>
__device__ __forceinline__ void gemm_body(
    const __half* __restrict__ A, const __half* __restrict__ B,
    const void* __restrict__ auxp, void* __restrict__ Cp,
    int N, int K, __half* tiles)
{
    constexpr int BM = 64;
    constexpr int MT = 2;
    constexpr int ASTG = BM * SROWH;
    constexpr int BSTG = 128 * SROWH;
    constexpr int STG  = ASTG + BSTG;

    int tid = threadIdx.x;
    int warp = tid >> 5, lane = tid & 31;
    int gid = lane >> 2, tig = lane & 3;
    int g8 = lane >> 3, r8 = lane & 7;
    int wm = warp >> 2, wn = warp & 3;
    int m0 = blockIdx.y * BM, n0 = blockIdx.x * 128;

    float acc[MT][4][4];
    #pragma unroll
    for (int i = 0; i < MT; i++)
        #pragma unroll
        for (int j = 0; j < 4; j++)
            #pragma unroll
            for (int l = 0; l < 4; l++) acc[i][j][l] = 0.f;

    const int KT = K >> 6;                 // BK=64 halves
    constexpr int NCH = (BM + 128) * 8;

    auto load_stage = [&](int kt, int s) {
        int k0 = kt << 6;
        __half* As = tiles + s * STG;
        __half* Bs = As + ASTG;
        #pragma unroll
        for (int i = tid; i < NCH; i += 256) {
            int r = i >> 3, c = (i & 7) << 3;
            if (r < BM) cp16(&As[r * SROWH + c], &A[(size_t)(m0 + r) * K + k0 + c]);
            else {
                int rb = r - BM;
                cp16(&Bs[rb * SROWH + c], &B[(size_t)(n0 + rb) * K + k0 + c]);
            }
        }
        CP_COMMIT();
    };

    uint32_t a_off[MT], b_off[2];
    #pragma unroll
    for (int i = 0; i < MT; i++)
        a_off[i] = (uint32_t)(((wm * 32 + i * 16 + (g8 & 1) * 8 + r8) * SROWH) * 2
                              + (g8 >> 1) * 16);
    #pragma unroll
    for (int jj = 0; jj < 2; jj++)
        b_off[jj] = (uint32_t)(ASTG * 2 + ((wn * 32 + jj * 16 + (g8 >> 1) * 8 + r8) * SROWH) * 2
                               + (g8 & 1) * 16);

    load_stage(0, 0);
    load_stage(1, 1);

    for (int kt = 0; kt < KT; kt++) {
        int s = kt % 3;
        if (kt + 1 < KT) CP_WAIT1(); else CP_WAIT0();
        __syncthreads();
        if (kt + 2 < KT) load_stage(kt + 2, (kt + 2) % 3);
        uint32_t base = smem_u32(tiles + s * STG);
        #pragma unroll
        for (int ks = 0; ks < 4; ks++) {
            uint32_t kofs = base + ks * 32;
            uint32_t af[MT][4];
            #pragma unroll
            for (int i = 0; i < MT; i++)
                ldm_x4(af[i][0], af[i][1], af[i][2], af[i][3], kofs + a_off[i]);
            uint32_t bf[4][2];
            #pragma unroll
            for (int jj = 0; jj < 2; jj++) {
                uint32_t m0r, m1r, m2r, m3r;
                ldm_x4(m0r, m1r, m2r, m3r, kofs + b_off[jj]);
                bf[2 * jj + 0][0] = m0r; bf[2 * jj + 0][1] = m1r;
                bf[2 * jj + 1][0] = m2r; bf[2 * jj + 1][1] = m3r;
            }
            #pragma unroll
            for (int i = 0; i < MT; i++)
                #pragma unroll
                for (int j = 0; j < 4; j++)
                    mma_f16(acc[i][j], af[i], bf[j][0], bf[j][1]);
        }
    }

    const float* auxf = (const float*)auxp;
    #pragma unroll
    for (int i = 0; i < MT; i++) {
        #pragma unroll
        for (int j = 0; j < 4; j++) {
            int m = m0 + wm * 32 + i * 16 + gid;
            int n = n0 + wn * 32 + j * 8 + 2 * tig;
            #pragma unroll
            for (int hh = 0; hh < 2; hh++) {
                int mm = m + hh * 8;
                float v0 = acc[i][j][hh * 2 + 0];
                float v1 = acc[i][j][hh * 2 + 1];
                size_t off = (size_t)mm * N + n;
                if (EPI == 1) { v0 += auxf[off]; v1 += auxf[off + 1]; }
                if (OUT_HALF) {
                    *(__half2*)&((__half*)Cp)[off] = __floats2half2_rn(v0, v1);
                } else {
                    float2 o2; o2.x = v0; o2.y = v1;
                    *(float2*)&((float*)Cp)[off] = o2;
                }
            }
        }
    }
}

template<int EPI, bool OUT_HALF>
__global__ void __launch_bounds__(256) gemm_f16(
    const __half* __restrict__ A, const __half* __restrict__ B,
    const void* __restrict__ aux, void* __restrict__ C, int N, int K)
{
    extern __shared__ __half tiles[];
    gemm_body<EPI, OUT_HALF>(A, B, aux, C, N, K, tiles);
}

__global__ void __launch_bounds__(256) gemm_qkv(
    const __half* __restrict__ A,
    const __half* __restrict__ B0, const __half* __restrict__ B1, const __half* __restrict__ B2,
    __half* __restrict__ C0, __half* __restrict__ C1, __half* __restrict__ C2, int K)
{
    extern __shared__ __half tiles[];
    const __half* B = (blockIdx.z == 0) ? B0 : (blockIdx.z == 1) ? B1 : B2;
    __half*       C = (blockIdx.z == 0) ? C0 : (blockIdx.z == 1) ? C1 : C2;
    gemm_body<0, true>(A, B, nullptr, C, HID, K, tiles);
}

// ---------------- fused gate||up GEMM with SiLU ---------------------------------
// t[M,N] = silu(A@G^T) * (A@U^T). 64x128x32 tiles, 3-stage, single-barrier.
#define SROW2 40   // halves per row (32 data + 8 pad)

__global__ void __launch_bounds__(256) gemm_gateup(
    const __half* __restrict__ A, const __half* __restrict__ G,
    const __half* __restrict__ U, __half* __restrict__ C, int N, int K)
{
    extern __shared__ __half tiles[];
    constexpr int BM = 64;
    constexpr int ASTG = BM * SROW2;
    constexpr int BSTG = 128 * SROW2;
    constexpr int STG  = ASTG + 2 * BSTG;

    int tid = threadIdx.x;
    int warp = tid >> 5, lane = tid & 31;
    int gid = lane >> 2, tig = lane & 3;
    int g8 = lane >> 3, r8 = lane & 7;
    int wm = warp >> 2, wn = warp & 3;
    int m0 = blockIdx.y * BM, n0 = blockIdx.x * 128;

    float accg[2][4][4], accu[2][4][4];
    #pragma unroll
    for (int i = 0; i < 2; i++)
        #pragma unroll
        for (int j = 0; j < 4; j++)
            #pragma unroll
            for (int l = 0; l < 4; l++) { accg[i][j][l] = 0.f; accu[i][j][l] = 0.f; }

    const int KT = K >> 5;                   // BK=32
    constexpr int NCH = (BM + 256) * 4;      // 16B chunks (32 halves = 4 chunks/row)

    auto load_stage = [&](int kt, int s) {
        int k0 = kt << 5;
        __half* As = tiles + s * STG;
        __half* Gs = As + ASTG;
        __half* Us = Gs + BSTG;
        #pragma unroll
        for (int i = tid; i < NCH; i += 256) {
            int r = i >> 2, c = (i & 3) << 3;
            if (r < BM) cp16(&As[r * SROW2 + c], &A[(size_t)(m0 + r) * K + k0 + c]);
            else if (r < BM + 128) {
                int rb = r - BM;
                cp16(&Gs[rb * SROW2 + c], &G[(size_t)(n0 + rb) * K + k0 + c]);
            } else {
                int rb = r - BM - 128;
                cp16(&Us[rb * SROW2 + c], &U[(size_t)(n0 + rb) * K + k0 + c]);
            }
        }
        CP_COMMIT();
    };

    uint32_t a_off[2], g_off[2], u_off[2];
    #pragma unroll
    for (int i = 0; i < 2; i++)
        a_off[i] = (uint32_t)(((wm * 32 + i * 16 + (g8 & 1) * 8 + r8) * SROW2) * 2
                              + (g8 >> 1) * 16);
    #pragma unroll
    for (int jj = 0; jj < 2; jj++) {
        uint32_t row = (uint32_t)(wn * 32 + jj * 16 + (g8 >> 1) * 8 + r8);
        g_off[jj] = (uint32_t)(ASTG * 2 + (row * SROW2) * 2 + (g8 & 1) * 16);
        u_off[jj] = g_off[jj] + BSTG * 2;
    }

    load_stage(0, 0);
    load_stage(1, 1);

    for (int kt = 0; kt < KT; kt++) {
        int s = kt % 3;
        if (kt + 1 < KT) CP_WAIT1(); else CP_WAIT0();
        __syncthreads();
        if (kt + 2 < KT) load_stage(kt + 2, (kt + 2) % 3);
        uint32_t base = smem_u32(tiles + s * STG);
        #pragma unroll
        for (int ks = 0; ks < 2; ks++) {
            uint32_t kofs = base + ks * 32;
            uint32_t af[2][4];
            #pragma unroll
            for (int i = 0; i < 2; i++)
                ldm_x4(af[i][0], af[i][1], af[i][2], af[i][3], kofs + a_off[i]);
            uint32_t gf[4][2], uf[4][2];
            #pragma unroll
            for (int jj = 0; jj < 2; jj++) {
                uint32_t m0r, m1r, m2r, m3r;
                ldm_x4(m0r, m1r, m2r, m3r, kofs + g_off[jj]);
                gf[2 * jj + 0][0] = m0r; gf[2 * jj + 0][1] = m1r;
                gf[2 * jj + 1][0] = m2r; gf[2 * jj + 1][1] = m3r;
                ldm_x4(m0r, m1r, m2r, m3r, kofs + u_off[jj]);
                uf[2 * jj + 0][0] = m0r; uf[2 * jj + 0][1] = m1r;
                uf[2 * jj + 1][0] = m2r; uf[2 * jj + 1][1] = m3r;
            }
            #pragma unroll
            for (int i = 0; i < 2; i++)
                #pragma unroll
                for (int j = 0; j < 4; j++) {
                    mma_f16(accg[i][j], af[i], gf[j][0], gf[j][1]);
                    mma_f16(accu[i][j], af[i], uf[j][0], uf[j][1]);
                }
        }
    }

    #pragma unroll
    for (int i = 0; i < 2; i++) {
        #pragma unroll
        for (int j = 0; j < 4; j++) {
            int m = m0 + wm * 32 + i * 16 + gid;
            int n = n0 + wn * 32 + j * 8 + 2 * tig;
            #pragma unroll
            for (int hh = 0; hh < 2; hh++) {
                int mm = m + hh * 8;
                float gg0 = accg[i][j][hh * 2 + 0], gg1 = accg[i][j][hh * 2 + 1];
                float v0 = accu[i][j][hh * 2 + 0] * gg0 / (1.0f + __expf(-gg0));
                float v1 = accu[i][j][hh * 2 + 1] * gg1 / (1.0f + __expf(-gg1));
                size_t off = (size_t)mm * N + n;
                *(__half2*)&C[off] = __floats2half2_rn(v0, v1);
            }
        }
    }
}

// ---------------- RoPE apply (scale 0.125 folded into q) ------------------------
__global__ void rope_kernel(__half* __restrict__ q, __half* __restrict__ k) {
    int idx = blockIdx.x * blockDim.x + threadIdx.x;
    if (idx >= S_TOK * HEADS * 32) return;
    int d = idx & 31;
    int h = (idx >> 5) & 15;
    int s = idx >> 9;
    float c  = g_cos[s * HD + d];
    float sn = g_sin[s * HD + d];
    int base = s * HID + h * HD;
    float q0 = __half2float(q[base + d]), q1 = __half2float(q[base + d + 32]);
    q[base + d]      = __float2half((q0 * c - q1 * sn) * 0.125f);
    q[base + d + 32] = __float2half((q1 * c + q0 * sn) * 0.125f);
    float k0 = __half2float(k[base + d]), k1 = __half2float(k[base + d + 32]);
    k[base + d]      = __float2half(k0 * c - k1 * sn);
    k[base + d + 32] = __float2half(k1 * c + k0 * sn);
}

// ---------------- fp16 flash attention (double-buffered K/V) --------------------
#define SP 68   // score row stride (floats)

__global__ void __launch_bounds__(256) attn_mma_kernel(
    const __half* __restrict__ q, const __half* __restrict__ k,
    const __half* __restrict__ v, __half* __restrict__ o)
{
    extern __shared__ char smraw[];
    __half* Qs = (__half*)smraw;                 // 64 x SROWH
    __half* Kb = Qs + 64 * SROWH;                // 2 buffers
    __half* Vb = Kb + 2 * 64 * SROWH;            // 2 buffers
    __half* Ps = Vb + 2 * 64 * SROWH;
    float*  Ss = (float*)(Ps + 64 * SROWH);      // 64 x SP
    float*  Al = Ss + 64 * SP;
    float*  Ll = Al + 64;

    int qt = blockIdx.x, h = blockIdx.y;
    int s0 = qt * 64;
    int key0 = (s0 < S0) ? 0 : S0;
    int nkt  = (s0 < S0) ? 16 : 8;

    int tid = threadIdx.x;
    int warp = tid >> 5, lane = tid & 31;
    int gid = lane >> 2, tig = lane & 3;
    int g8 = lane >> 3, r8 = lane & 7;
    int wm = warp >> 1, wn = warp & 1;
    int qq = tid >> 2, kg = tid & 3;

    auto load_tile = [&](int kt) {
        __half* Kd = Kb + (kt & 1) * 64 * SROWH;
        __half* Vd = Vb + (kt & 1) * 64 * SROWH;
        for (int i = tid; i < 1024; i += 256) {
            int sel = i >> 9;
            int i2 = i & 511;
            int r = i2 >> 3, c = (i2 & 7) << 3;
            size_t g = (size_t)(key0 + kt * 64 + r) * HID + h * HD + c;
            if (sel == 0) cp16(&Kd[r * SROWH + c], &k[g]);
            else          cp16(&Vd[r * SROWH + c], &v[g]);
        }
        CP_COMMIT();
    };

    // Q tile (resident)
    for (int i = tid; i < 512; i += 256) {
        int r = i >> 3, c = (i & 7) << 3;
        cp16(&Qs[r * SROWH + c], &q[(size_t)(s0 + r) * HID + h * HD + c]);
    }
    CP_COMMIT();
    load_tile(0);

    float m_prev = -1e30f, lsum = 0.f;
    float oacc[4][4];
    #pragma unroll
    for (int j = 0; j < 4; j++)
        #pragma unroll
        for (int l = 0; l < 4; l++) oacc[j][l] = 0.f;

    int arow0 = wm * 16 + gid;

    uint32_t qa_off = (uint32_t)(((wm * 16 + (g8 & 1) * 8 + r8) * SROWH) * 2 + (g8 >> 1) * 16);
    uint32_t kb_off[2];
    #pragma unroll
    for (int jj = 0; jj < 2; jj++)
        kb_off[jj] = (uint32_t)(((wn * 32 + jj * 16 + (g8 >> 1) * 8 + r8) * SROWH) * 2
                                + (g8 & 1) * 16);

    uint32_t qbase = smem_u32(Qs);
    uint32_t pbase = smem_u32(Ps);

    for (int kt = 0; kt < nkt; kt++) {
        CP_WAIT0();
        __syncthreads();
        if (kt + 1 < nkt) load_tile(kt + 1);

        uint32_t kbase = smem_u32(Kb + (kt & 1) * 64 * SROWH);
        uint32_t vbase = smem_u32(Vb + (kt & 1) * 64 * SROWH);

        // S = Qs @ K^T (q pre-scaled by 0.125)
        float sc[4][4];
        #pragma unroll
        for (int j = 0; j < 4; j++)
            #pragma unroll
            for (int l = 0; l < 4; l++) sc[j][l] = 0.f;
        #pragma unroll
        for (int ks = 0; ks < 4; ks++) {
            uint32_t kofs = ks * 32;
            uint32_t aq[4];
            ldm_x4(aq[0], aq[1], aq[2], aq[3], qbase + kofs + qa_off);
            uint32_t bf[4][2];
            #pragma unroll
            for (int jj = 0; jj < 2; jj++) {
                uint32_t m0r, m1r, m2r, m3r;
                ldm_x4(m0r, m1r, m2r, m3r, kbase + kofs + kb_off[jj]);
                bf[2 * jj + 0][0] = m0r; bf[2 * jj + 0][1] = m1r;
                bf[2 * jj + 1][0] = m2r; bf[2 * jj + 1][1] = m3r;
            }
            #pragma unroll
            for (int j = 0; j < 4; j++)
                mma_f16(sc[j], aq, bf[j][0], bf[j][1]);
        }
        #pragma unroll
        for (int j = 0; j < 4; j++) {
            int cn = wn * 32 + j * 8 + 2 * tig;
            Ss[arow0 * SP + cn]           = sc[j][0];
            Ss[arow0 * SP + cn + 1]       = sc[j][1];
            Ss[(arow0 + 8) * SP + cn]     = sc[j][2];
            Ss[(arow0 + 8) * SP + cn + 1] = sc[j][3];
        }
        __syncthreads();

        // online softmax (row qq, col chunk kg)
        {
            float e[16];
            int base = qq * SP + kg * 16;
            float mloc = -1e30f;
            #pragma unroll
            for (int i = 0; i < 16; i++) { e[i] = Ss[base + i]; mloc = fmaxf(mloc, e[i]); }
            mloc = fmaxf(mloc, __shfl_xor_sync(0xffffffffu, mloc, 1));
            mloc = fmaxf(mloc, __shfl_xor_sync(0xffffffffu, mloc, 2));
            float m_new = fmaxf(m_prev, mloc);
            float alpha = __expf(m_prev - m_new);
            float lrow = 0.f;
            int pb = qq * SROWH + kg * 16;
            #pragma unroll
            for (int i = 0; i < 16; i += 2) {
                float e0 = __expf(e[i]     - m_new);
                float e1 = __expf(e[i + 1] - m_new);
                lrow += e0 + e1;
                *(__half2*)&Ps[pb + i] = __floats2half2_rn(e0, e1);
            }
            lrow += __shfl_xor_sync(0xffffffffu, lrow, 1);
            lrow += __shfl_xor_sync(0xffffffffu, lrow, 2);
            lsum = lsum * alpha + lrow;
            m_prev = m_new;
            if (kg == 0) Al[qq] = alpha;
        }
        __syncthreads();

        float a_r0 = Al[arow0], a_r1 = Al[arow0 + 8];
        #pragma unroll
        for (int j = 0; j < 4; j++) {
            oacc[j][0] *= a_r0; oacc[j][1] *= a_r0;
            oacc[j][2] *= a_r1; oacc[j][3] *= a_r1;
        }

        // O += P @ V
        #pragma unroll
        for (int ks = 0; ks < 4; ks++) {
            uint32_t ap[4];
            ldm_x4(ap[0], ap[1], ap[2], ap[3], pbase + ks * 32 + qa_off);
            uint32_t vf[4][2];
            #pragma unroll
            for (int jj = 0; jj < 2; jj++) {
                uint32_t addr = vbase
                    + (uint32_t)(((ks * 16 + (g8 & 1) * 8 + r8) * SROWH) * 2
                                 + (wn * 32 + jj * 16) * 2 + (g8 >> 1) * 16);
                uint32_t m0r, m1r, m2r, m3r;
                ldm_x4t(m0r, m1r, m2r, m3r, addr);
                vf[2 * jj + 0][0] = m0r; vf[2 * jj + 0][1] = m1r;
                vf[2 * jj + 1][0] = m2r; vf[2 * jj + 1][1] = m3r;
            }
            #pragma unroll
            for (int j = 0; j < 4; j++)
                mma_f16(oacc[j], ap, vf[j][0], vf[j][1]);
        }
        __syncthreads();
    }

    if (kg == 0) Ll[qq] = lsum;
    __syncthreads();
    float inv0 = 1.0f / Ll[arow0];
    float inv1 = 1.0f / Ll[arow0 + 8];
    #pragma unroll
    for (int j = 0; j < 4; j++) {
        int cn = wn * 32 + j * 8 + 2 * tig;
        size_t o0 = (size_t)(s0 + arow0) * HID + h * HD + cn;
        size_t o1 = (size_t)(s0 + arow0 + 8) * HID + h * HD + cn;
        *(__half2*)&o[o0] = __floats2half2_rn(oacc[j][0] * inv0, oacc[j][1] * inv0);
        *(__half2*)&o[o1] = __floats2half2_rn(oacc[j][2] * inv1, oacc[j][3] * inv1);
    }
}

// ---------------- host orchestration ---------------------------------------------
extern "C" void kernel_launch(void* const* d_in, const int* in_sizes, int n_in,
                              void* d_out, int out_size) {
    const float* img0        = (const float*)d_in[0];
    const float* img1        = (const float*)d_in[1];
    const float* conv_w      = (const float*)d_in[2];
    const float* ln_pre_w    = (const float*)d_in[3];
    const float* attn_norm_w = (const float*)d_in[4];
    const float* q_w         = (const float*)d_in[5];
    const float* k_w         = (const float*)d_in[6];
    const float* v_w         = (const float*)d_in[7];
    const float* o_w         = (const float*)d_in[8];
    const float* ffn_norm_w  = (const float*)d_in[9];
    const float* gate_w      = (const float*)d_in[10];
    const float* up_w        = (const float*)d_in[11];
    const float* down_w      = (const float*)d_in[12];
    float* out = (float*)d_out;

    float *p_x, *p_h2;
    __half *p_xpatch, *p_hn, *p_q, *p_k, *p_v, *p_ao, *p_t;
    __half *p_wconv, *p_wq, *p_wk, *p_wv, *p_wo, *p_wg, *p_wu, *p_wd;
    cudaGetSymbolAddress((void**)&p_x,  g_x);
    cudaGetSymbolAddress((void**)&p_h2, g_h2);
    cudaGetSymbolAddress((void**)&p_xpatch, a_xpatch);
    cudaGetSymbolAddress((void**)&p_hn, a_hn);
    cudaGetSymbolAddress((void**)&p_q,  a_q);
    cudaGetSymbolAddress((void**)&p_k,  a_k);
    cudaGetSymbolAddress((void**)&p_v,  a_v);
    cudaGetSymbolAddress((void**)&p_ao, a_ao);
    cudaGetSymbolAddress((void**)&p_t,  a_t);
    cudaGetSymbolAddress((void**)&p_wconv, h_wconv);
    cudaGetSymbolAddress((void**)&p_wq, h_wq);
    cudaGetSymbolAddress((void**)&p_wk, h_wk);
    cudaGetSymbolAddress((void**)&p_wv, h_wv);
    cudaGetSymbolAddress((void**)&p_wo, h_wo);
    cudaGetSymbolAddress((void**)&p_wg, h_wg);
    cudaGetSymbolAddress((void**)&p_wu, h_wu);
    cudaGetSymbolAddress((void**)&p_wd, h_wd);

    const int SMEM64  = 3 * (64 + 128) * SROWH * 2;                 //  82944
    const int SMEMGU  = 3 * (64 + 256) * SROW2 * 2;                 //  76800
    const int ASMEM   = 6 * 64 * SROWH * 2 + 64 * SP * 4 + 2 * 64 * 4;  // 73216
    cudaFuncSetAttribute((const void*)gemm_f16<0, false>, cudaFuncAttributeMaxDynamicSharedMemorySize, SMEM64);
    cudaFuncSetAttribute((const void*)gemm_f16<1, false>, cudaFuncAttributeMaxDynamicSharedMemorySize, SMEM64);
    cudaFuncSetAttribute((const void*)gemm_qkv,           cudaFuncAttributeMaxDynamicSharedMemorySize, SMEM64);
    cudaFuncSetAttribute((const void*)gemm_gateup,        cudaFuncAttributeMaxDynamicSharedMemorySize, SMEMGU);
    cudaFuncSetAttribute((const void*)attn_mma_kernel,    cudaFuncAttributeMaxDynamicSharedMemorySize, ASMEM);

    // weight conversion fp32 -> fp16
    {
        auto cvt = [&](const float* src, __half* dst, int n) {
            f2h_kernel<<<(n / 8 + 255) / 256, 256>>>(src, dst, n / 8);
        };
        cvt(conv_w, p_wconv, HID * KPATCH);
        cvt(q_w,    p_wq, NLAYERS * HID * HID);
        cvt(k_w,    p_wk, NLAYERS * HID * HID);
        cvt(v_w,    p_wv, NLAYERS * HID * HID);
        cvt(o_w,    p_wo, NLAYERS * HID * HID);
        cvt(gate_w, p_wg, NLAYERS * INTER * HID);
        cvt(up_w,   p_wu, NLAYERS * INTER * HID);
        cvt(down_w, p_wd, NLAYERS * HID * INTER);
    }

    dim3 grid_n1k(HID / 128, S_TOK / 64);       // (8, 24)
    dim3 grid_qkv(HID / 128, S_TOK / 64, 3);    // (8, 24, 3)
    dim3 grid_gu (INTER / 128, S_TOK / 64);     // (32, 24)

    im2col_kernel<<<(S_TOK * KPATCH + 255) / 256, 256>>>(img0, img1);
    gemm_f16<0, false><<<grid_n1k, 256, SMEM64>>>(p_xpatch, p_wconv, nullptr, p_h2, HID, KPATCH);

    rms_kernel<false><<<S_TOK, 256>>>(p_h2, ln_pre_w, p_x);
    rope_table_kernel<<<S_TOK, 64>>>();

    for (int l = 0; l < NLAYERS; l++) {
        const __half* qw = p_wq + (size_t)l * HID * HID;
        const __half* kw = p_wk + (size_t)l * HID * HID;
        const __half* vw = p_wv + (size_t)l * HID * HID;
        const __half* ow = p_wo + (size_t)l * HID * HID;
        const __half* gw = p_wg + (size_t)l * INTER * HID;
        const __half* uw = p_wu + (size_t)l * INTER * HID;
        const __half* dw = p_wd + (size_t)l * HID * INTER;

        rms_kernel<true><<<S_TOK, 256>>>(p_x, attn_norm_w + l * HID, p_hn);

        gemm_qkv<<<grid_qkv, 256, SMEM64>>>(p_hn, qw, kw, vw, p_q, p_k, p_v, HID);

        rope_kernel<<<(S_TOK * HEADS * 32 + 255) / 256, 256>>>(p_q, p_k);

        attn_mma_kernel<<<dim3(S_TOK / 64, HEADS), 256, ASMEM>>>(p_q, p_k, p_v, p_ao);

        gemm_f16<1, false><<<grid_n1k, 256, SMEM64>>>(p_ao, ow, p_x, p_h2, HID, HID);

        rms_kernel<true><<<S_TOK, 256>>>(p_h2, ffn_norm_w + l * HID, p_hn);

        gemm_gateup<<<grid_gu, 256, SMEMGU>>>(p_hn, gw, uw, p_t, INTER, HID);

        float* dst = (l == NLAYERS - 1) ? out : p_x;
        gemm_f16<1, false><<<grid_n1k, 256, SMEM64>>>(p_t, dw, p_h2, dst, HID, INTER);
    }
}

// round 10
// speedup vs baseline: 10.1078x; 1.0161x over previous
#include <cuda_runtime.h>
#include <cuda_fp16.h>
#include <math.h>
#include <stdint.h>

// ---------------- problem constants ----------------------------------------
#define S_TOK 1536
#define S0    1024
#define HID   1024
#define HEADS 16
#define HD    64
#define INTER 4096
#define NLAYERS 4
#define KPATCH 768

// ---------------- scratch ---------------------------------------------------
__device__ float g_x [S_TOK * HID];
__device__ float g_h2[S_TOK * HID];
__device__ float g_cos[S_TOK * HD];
__device__ float g_sin[S_TOK * HD];
__device__ __half a_xpatch[S_TOK * KPATCH];
__device__ __half a_hn[S_TOK * HID];
__device__ __half a_q [S_TOK * HID];
__device__ __half a_k [S_TOK * HID];
__device__ __half a_v [S_TOK * HID];
__device__ __half a_ao[S_TOK * HID];
__device__ __half a_t [S_TOK * INTER];
__device__ __half h_wconv[HID * KPATCH];
__device__ __half h_wq[NLAYERS * HID * HID];
__device__ __half h_wk[NLAYERS * HID * HID];
__device__ __half h_wv[NLAYERS * HID * HID];
__device__ __half h_wo[NLAYERS * HID * HID];
__device__ __half h_wg[NLAYERS * INTER * HID];
__device__ __half h_wu[NLAYERS * INTER * HID];
__device__ __half h_wd[NLAYERS * HID * INTER];

// ---------------- helpers ----------------------------------------------------
__device__ __forceinline__ uint32_t smem_u32(const void* p) {
    return (uint32_t)__cvta_generic_to_shared(p);
}
__device__ __forceinline__ void mma_f16(float c[4], const uint32_t a[4],
                                        uint32_t b0, uint32_t b1) {
    asm volatile(
        "mma.sync.aligned.m16n8k16.row.col.f32.f16.f16.f32 "
        "{%0,%1,%2,%3},{%4,%5,%6,%7},{%8,%9},{%0,%1,%2,%3};"
        : "+f"(c[0]), "+f"(c[1]), "+f"(c[2]), "+f"(c[3])
        : "r"(a[0]), "r"(a[1]), "r"(a[2]), "r"(a[3]), "r"(b0), "r"(b1));
}
__device__ __forceinline__ void ldm_x4(uint32_t& r0, uint32_t& r1, uint32_t& r2, uint32_t& r3,
                                       uint32_t addr) {
    asm volatile("ldmatrix.sync.aligned.m8n8.x4.shared.b16 {%0,%1,%2,%3}, [%4];"
                 : "=r"(r0), "=r"(r1), "=r"(r2), "=r"(r3) : "r"(addr));
}
__device__ __forceinline__ void ldm_x4t(uint32_t& r0, uint32_t& r1, uint32_t& r2, uint32_t& r3,
                                        uint32_t addr) {
    asm volatile("ldmatrix.sync.aligned.m8n8.x4.trans.shared.b16 {%0,%1,%2,%3}, [%4];"
                 : "=r"(r0), "=r"(r1), "=r"(r2), "=r"(r3) : "r"(addr));
}
__device__ __forceinline__ void cp16(void* smem_dst, const void* gsrc) {
    uint32_t d = (uint32_t)__cvta_generic_to_shared(smem_dst);
    asm volatile("cp.async.cg.shared.global [%0], [%1], 16;\n" :: "r"(d), "l"(gsrc));
}
#define CP_COMMIT() asm volatile("cp.async.commit_group;\n" ::: "memory")
#define CP_WAIT0()  asm volatile("cp.async.wait_group 0;\n" ::: "memory")
#define CP_WAIT1()  asm volatile("cp.async.wait_group 1;\n" ::: "memory")

// ---------------- weight fp32 -> fp16 (16 floats/thread, 64B loads) ------------
__global__ void f2h_kernel(const float* __restrict__ x, __half* __restrict__ y, int n16) {
    int i = blockIdx.x * blockDim.x + threadIdx.x;
    if (i >= n16) return;
    const float4* x4 = (const float4*)x;
    float4 v0 = x4[4 * i + 0];
    float4 v1 = x4[4 * i + 1];
    float4 v2 = x4[4 * i + 2];
    float4 v3 = x4[4 * i + 3];
    __half2 h0 = __floats2half2_rn(v0.x, v0.y), h1 = __floats2half2_rn(v0.z, v0.w);
    __half2 h2 = __floats2half2_rn(v1.x, v1.y), h3 = __floats2half2_rn(v1.z, v1.w);
    __half2 h4 = __floats2half2_rn(v2.x, v2.y), h5 = __floats2half2_rn(v2.z, v2.w);
    __half2 h6 = __floats2half2_rn(v3.x, v3.y), h7 = __floats2half2_rn(v3.z, v3.w);
    uint4 ua, ub;
    ua.x = *(uint32_t*)&h0; ua.y = *(uint32_t*)&h1;
    ua.z = *(uint32_t*)&h2; ua.w = *(uint32_t*)&h3;
    ub.x = *(uint32_t*)&h4; ub.y = *(uint32_t*)&h5;
    ub.z = *(uint32_t*)&h6; ub.w = *(uint32_t*)&h7;
    ((uint4*)y)[2 * i + 0] = ua;
    ((uint4*)y)[2 * i + 1] = ub;
}

// ---------------- im2col (fp16 out) -------------------------------------------
__global__ void im2col_kernel(const float* __restrict__ img0,
                              const float* __restrict__ img1) {
    int idx = blockIdx.x * blockDim.x + threadIdx.x;
    if (idx >= S_TOK * KPATCH) return;
    int s = idx / KPATCH;
    int r = idx - s * KPATCH;
    int c  = r >> 8;
    int kh = (r >> 4) & 15;
    int kw = r & 15;
    float val;
    if (s < S0) {
        int ph = s >> 5, pw = s & 31;
        val = img0[c * 512 * 512 + (ph * 16 + kh) * 512 + (pw * 16 + kw)];
    } else {
        int sp = s - S0;
        int ph = sp >> 4, pw = sp & 15;
        val = img1[c * 512 * 256 + (ph * 16 + kh) * 256 + (pw * 16 + kw)];
    }
    a_xpatch[idx] = __float2half(val);
}

// ---------------- RoPE table ---------------------------------------------------
__global__ void rope_table_kernel() {
    int s = blockIdx.x;
    int d = threadIdx.x;  // 0..63
    int ph, pw;
    if (s < S0) { ph = s >> 5; pw = s & 31; }
    else        { int sp = s - S0; ph = sp >> 4; pw = sp & 15; }
    int j = d & 31;
    float e, base;
    if (j < 16) { e = (4.0f * j) / 64.0f;               base = (float)ph; }
    else        { e = (2.0f + 4.0f * (j - 16)) / 64.0f; base = (float)pw; }
    float f = base * expf(-e * 9.2103403719761836f);
    g_cos[s * HD + d] = cosf(f);
    g_sin[s * HD + d] = sinf(f);
}

// ---------------- RMSNorm: fp32 in, fp32 or fp16 out ---------------------------
template<bool OUT_HALF>
__global__ void rms_kernel(const float* __restrict__ x,
                           const float* __restrict__ w,
                           void* __restrict__ yv) {
    int s = blockIdx.x;
    int tid = threadIdx.x;  // 256
    const float* xr = x + s * HID;
    float ss = 0.f;
    #pragma unroll 4
    for (int i = tid; i < HID; i += 256) { float v = xr[i]; ss += v * v; }
    __shared__ float sh[8];
    #pragma unroll
    for (int o = 16; o > 0; o >>= 1) ss += __shfl_xor_sync(0xffffffffu, ss, o);
    if ((tid & 31) == 0) sh[tid >> 5] = ss;
    __syncthreads();
    if (tid < 8) {
        float v = sh[tid];
        #pragma unroll
        for (int o = 4; o > 0; o >>= 1) v += __shfl_xor_sync(0xffu, v, o);
        if (tid == 0) sh[0] = v;
    }
    __syncthreads();
    float r = rsqrtf(sh[0] * (1.0f / HID) + 1e-5f);
    if (OUT_HALF) {
        __half* y = (__half*)yv;
        for (int i = tid; i < HID; i += 256) y[s * HID + i] = __float2half(xr[i] * r * w[i]);
    } else {
        float* y = (float*)yv;
        for (int i = tid; i < HID; i += 256) y[s * HID + i] = xr[i] * r * w[i];
    }
}

// ---------------- fp16 GEMM (m16n8k16, ldmatrix, BK=64, single-barrier) --------
#define SROWH 72   // halves per smem row (64 data + 8 pad)

template<int EPI, bool OUT_HALF>
__device__ __forceinline__ void gemm_body(
    const __half* __restrict__ A, const __half* __restrict__ B,
    const void* __restrict__ auxp, void* __restrict__ Cp,
    int N, int K, __half* tiles)
{
    constexpr int BM = 64;
    constexpr int MT = 2;
    constexpr int ASTG = BM * SROWH;
    constexpr int BSTG = 128 * SROWH;
    constexpr int STG  = ASTG + BSTG;

    int tid = threadIdx.x;
    int warp = tid >> 5, lane = tid & 31;
    int gid = lane >> 2, tig = lane & 3;
    int g8 = lane >> 3, r8 = lane & 7;
    int wm = warp >> 2, wn = warp & 3;
    int m0 = blockIdx.y * BM, n0 = blockIdx.x * 128;

    float acc[MT][4][4];
    #pragma unroll
    for (int i = 0; i < MT; i++)
        #pragma unroll
        for (int j = 0; j < 4; j++)
            #pragma unroll
            for (int l = 0; l < 4; l++) acc[i][j][l] = 0.f;

    const int KT = K >> 6;
    constexpr int NCH = (BM + 128) * 8;

    auto load_stage = [&](int kt, int s) {
        int k0 = kt << 6;
        __half* As = tiles + s * STG;
        __half* Bs = As + ASTG;
        #pragma unroll
        for (int i = tid; i < NCH; i += 256) {
            int r = i >> 3, c = (i & 7) << 3;
            if (r < BM) cp16(&As[r * SROWH + c], &A[(size_t)(m0 + r) * K + k0 + c]);
            else {
                int rb = r - BM;
                cp16(&Bs[rb * SROWH + c], &B[(size_t)(n0 + rb) * K + k0 + c]);
            }
        }
        CP_COMMIT();
    };

    uint32_t a_off[MT], b_off[2];
    #pragma unroll
    for (int i = 0; i < MT; i++)
        a_off[i] = (uint32_t)(((wm * 32 + i * 16 + (g8 & 1) * 8 + r8) * SROWH) * 2
                              + (g8 >> 1) * 16);
    #pragma unroll
    for (int jj = 0; jj < 2; jj++)
        b_off[jj] = (uint32_t)(ASTG * 2 + ((wn * 32 + jj * 16 + (g8 >> 1) * 8 + r8) * SROWH) * 2
                               + (g8 & 1) * 16);

    load_stage(0, 0);
    load_stage(1, 1);

    for (int kt = 0; kt < KT; kt++) {
        int s = kt % 3;
        if (kt + 1 < KT) CP_WAIT1(); else CP_WAIT0();
        __syncthreads();
        if (kt + 2 < KT) load_stage(kt + 2, (kt + 2) % 3);
        uint32_t base = smem_u32(tiles + s * STG);
        #pragma unroll
        for (int ks = 0; ks < 4; ks++) {
            uint32_t kofs = base + ks * 32;
            uint32_t af[MT][4];
            #pragma unroll
            for (int i = 0; i < MT; i++)
                ldm_x4(af[i][0], af[i][1], af[i][2], af[i][3], kofs + a_off[i]);
            uint32_t bf[4][2];
            #pragma unroll
            for (int jj = 0; jj < 2; jj++) {
                uint32_t m0r, m1r, m2r, m3r;
                ldm_x4(m0r, m1r, m2r, m3r, kofs + b_off[jj]);
                bf[2 * jj + 0][0] = m0r; bf[2 * jj + 0][1] = m1r;
                bf[2 * jj + 1][0] = m2r; bf[2 * jj + 1][1] = m3r;
            }
            #pragma unroll
            for (int i = 0; i < MT; i++)
                #pragma unroll
                for (int j = 0; j < 4; j++)
                    mma_f16(acc[i][j], af[i], bf[j][0], bf[j][1]);
        }
    }

    const float* auxf = (const float*)auxp;
    #pragma unroll
    for (int i = 0; i < MT; i++) {
        #pragma unroll
        for (int j = 0; j < 4; j++) {
            int m = m0 + wm * 32 + i * 16 + gid;
            int n = n0 + wn * 32 + j * 8 + 2 * tig;
            #pragma unroll
            for (int hh = 0; hh < 2; hh++) {
                int mm = m + hh * 8;
                float v0 = acc[i][j][hh * 2 + 0];
                float v1 = acc[i][j][hh * 2 + 1];
                size_t off = (size_t)mm * N + n;
                if (EPI == 1) { v0 += auxf[off]; v1 += auxf[off + 1]; }
                if (OUT_HALF) {
                    *(__half2*)&((__half*)Cp)[off] = __floats2half2_rn(v0, v1);
                } else {
                    float2 o2; o2.x = v0; o2.y = v1;
                    *(float2*)&((float*)Cp)[off] = o2;
                }
            }
        }
    }
}

template<int EPI, bool OUT_HALF>
__global__ void __launch_bounds__(256) gemm_f16(
    const __half* __restrict__ A, const __half* __restrict__ B,
    const void* __restrict__ aux, void* __restrict__ C, int N, int K)
{
    extern __shared__ __half tiles[];
    gemm_body<EPI, OUT_HALF>(A, B, aux, C, N, K, tiles);
}

__global__ void __launch_bounds__(256) gemm_qkv(
    const __half* __restrict__ A,
    const __half* __restrict__ B0, const __half* __restrict__ B1, const __half* __restrict__ B2,
    __half* __restrict__ C0, __half* __restrict__ C1, __half* __restrict__ C2, int K)
{
    extern __shared__ __half tiles[];
    const __half* B = (blockIdx.z == 0) ? B0 : (blockIdx.z == 1) ? B1 : B2;
    __half*       C = (blockIdx.z == 0) ? C0 : (blockIdx.z == 1) ? C1 : C2;
    gemm_body<0, true>(A, B, nullptr, C, HID, K, tiles);
}

// ---------------- fused gate||up GEMM with SiLU ---------------------------------
#define SROW2 40   // halves per row (32 data + 8 pad)

__global__ void __launch_bounds__(256) gemm_gateup(
    const __half* __restrict__ A, const __half* __restrict__ G,
    const __half* __restrict__ U, __half* __restrict__ C, int N, int K)
{
    extern __shared__ __half tiles[];
    constexpr int BM = 64;
    constexpr int ASTG = BM * SROW2;
    constexpr int BSTG = 128 * SROW2;
    constexpr int STG  = ASTG + 2 * BSTG;

    int tid = threadIdx.x;
    int warp = tid >> 5, lane = tid & 31;
    int gid = lane >> 2, tig = lane & 3;
    int g8 = lane >> 3, r8 = lane & 7;
    int wm = warp >> 2, wn = warp & 3;
    int m0 = blockIdx.y * BM, n0 = blockIdx.x * 128;

    float accg[2][4][4], accu[2][4][4];
    #pragma unroll
    for (int i = 0; i < 2; i++)
        #pragma unroll
        for (int j = 0; j < 4; j++)
            #pragma unroll
            for (int l = 0; l < 4; l++) { accg[i][j][l] = 0.f; accu[i][j][l] = 0.f; }

    const int KT = K >> 5;
    constexpr int NCH = (BM + 256) * 4;

    auto load_stage = [&](int kt, int s) {
        int k0 = kt << 5;
        __half* As = tiles + s * STG;
        __half* Gs = As + ASTG;
        __half* Us = Gs + BSTG;
        #pragma unroll
        for (int i = tid; i < NCH; i += 256) {
            int r = i >> 2, c = (i & 3) << 3;
            if (r < BM) cp16(&As[r * SROW2 + c], &A[(size_t)(m0 + r) * K + k0 + c]);
            else if (r < BM + 128) {
                int rb = r - BM;
                cp16(&Gs[rb * SROW2 + c], &G[(size_t)(n0 + rb) * K + k0 + c]);
            } else {
                int rb = r - BM - 128;
                cp16(&Us[rb * SROW2 + c], &U[(size_t)(n0 + rb) * K + k0 + c]);
            }
        }
        CP_COMMIT();
    };

    uint32_t a_off[2], g_off[2], u_off[2];
    #pragma unroll
    for (int i = 0; i < 2; i++)
        a_off[i] = (uint32_t)(((wm * 32 + i * 16 + (g8 & 1) * 8 + r8) * SROW2) * 2
                              + (g8 >> 1) * 16);
    #pragma unroll
    for (int jj = 0; jj < 2; jj++) {
        uint32_t row = (uint32_t)(wn * 32 + jj * 16 + (g8 >> 1) * 8 + r8);
        g_off[jj] = (uint32_t)(ASTG * 2 + (row * SROW2) * 2 + (g8 & 1) * 16);
        u_off[jj] = g_off[jj] + BSTG * 2;
    }

    load_stage(0, 0);
    load_stage(1, 1);

    for (int kt = 0; kt < KT; kt++) {
        int s = kt % 3;
        if (kt + 1 < KT) CP_WAIT1(); else CP_WAIT0();
        __syncthreads();
        if (kt + 2 < KT) load_stage(kt + 2, (kt + 2) % 3);
        uint32_t base = smem_u32(tiles + s * STG);
        #pragma unroll
        for (int ks = 0; ks < 2; ks++) {
            uint32_t kofs = base + ks * 32;
            uint32_t af[2][4];
            #pragma unroll
            for (int i = 0; i < 2; i++)
                ldm_x4(af[i][0], af[i][1], af[i][2], af[i][3], kofs + a_off[i]);
            uint32_t gf[4][2], uf[4][2];
            #pragma unroll
            for (int jj = 0; jj < 2; jj++) {
                uint32_t m0r, m1r, m2r, m3r;
                ldm_x4(m0r, m1r, m2r, m3r, kofs + g_off[jj]);
                gf[2 * jj + 0][0] = m0r; gf[2 * jj + 0][1] = m1r;
                gf[2 * jj + 1][0] = m2r; gf[2 * jj + 1][1] = m3r;
                ldm_x4(m0r, m1r, m2r, m3r, kofs + u_off[jj]);
                uf[2 * jj + 0][0] = m0r; uf[2 * jj + 0][1] = m1r;
                uf[2 * jj + 1][0] = m2r; uf[2 * jj + 1][1] = m3r;
            }
            #pragma unroll
            for (int i = 0; i < 2; i++)
                #pragma unroll
                for (int j = 0; j < 4; j++) {
                    mma_f16(accg[i][j], af[i], gf[j][0], gf[j][1]);
                    mma_f16(accu[i][j], af[i], uf[j][0], uf[j][1]);
                }
        }
    }

    #pragma unroll
    for (int i = 0; i < 2; i++) {
        #pragma unroll
        for (int j = 0; j < 4; j++) {
            int m = m0 + wm * 32 + i * 16 + gid;
            int n = n0 + wn * 32 + j * 8 + 2 * tig;
            #pragma unroll
            for (int hh = 0; hh < 2; hh++) {
                int mm = m + hh * 8;
                float gg0 = accg[i][j][hh * 2 + 0], gg1 = accg[i][j][hh * 2 + 1];
                float v0 = accu[i][j][hh * 2 + 0] * gg0 / (1.0f + __expf(-gg0));
                float v1 = accu[i][j][hh * 2 + 1] * gg1 / (1.0f + __expf(-gg1));
                size_t off = (size_t)mm * N + n;
                *(__half2*)&C[off] = __floats2half2_rn(v0, v1);
            }
        }
    }
}

// ---------------- RoPE apply (scale 0.125 folded into q) ------------------------
__global__ void rope_kernel(__half* __restrict__ q, __half* __restrict__ k) {
    int idx = blockIdx.x * blockDim.x + threadIdx.x;
    if (idx >= S_TOK * HEADS * 32) return;
    int d = idx & 31;
    int h = (idx >> 5) & 15;
    int s = idx >> 9;
    float c  = g_cos[s * HD + d];
    float sn = g_sin[s * HD + d];
    int base = s * HID + h * HD;
    float q0 = __half2float(q[base + d]), q1 = __half2float(q[base + d + 32]);
    q[base + d]      = __float2half((q0 * c - q1 * sn) * 0.125f);
    q[base + d + 32] = __float2half((q1 * c + q0 * sn) * 0.125f);
    float k0 = __half2float(k[base + d]), k1 = __half2float(k[base + d + 32]);
    k[base + d]      = __float2half(k0 * c - k1 * sn);
    k[base + d + 32] = __float2half(k1 * c + k0 * sn);
}

// ---------------- fp16 flash attention (double-buffered K/V) --------------------
#define SP 68   // score row stride (floats)

__global__ void __launch_bounds__(256) attn_mma_kernel(
    const __half* __restrict__ q, const __half* __restrict__ k,
    const __half* __restrict__ v, __half* __restrict__ o)
{
    extern __shared__ char smraw[];
    __half* Qs = (__half*)smraw;
    __half* Kb = Qs + 64 * SROWH;
    __half* Vb = Kb + 2 * 64 * SROWH;
    __half* Ps = Vb + 2 * 64 * SROWH;
    float*  Ss = (float*)(Ps + 64 * SROWH);
    float*  Al = Ss + 64 * SP;
    float*  Ll = Al + 64;

    int qt = blockIdx.x, h = blockIdx.y;
    int s0 = qt * 64;
    int key0 = (s0 < S0) ? 0 : S0;
    int nkt  = (s0 < S0) ? 16 : 8;

    int tid = threadIdx.x;
    int warp = tid >> 5, lane = tid & 31;
    int gid = lane >> 2, tig = lane & 3;
    int g8 = lane >> 3, r8 = lane & 7;
    int wm = warp >> 1, wn = warp & 1;
    int qq = tid >> 2, kg = tid & 3;

    auto load_tile = [&](int kt) {
        __half* Kd = Kb + (kt & 1) * 64 * SROWH;
        __half* Vd = Vb + (kt & 1) * 64 * SROWH;
        for (int i = tid; i < 1024; i += 256) {
            int sel = i >> 9;
            int i2 = i & 511;
            int r = i2 >> 3, c = (i2 & 7) << 3;
            size_t g = (size_t)(key0 + kt * 64 + r) * HID + h * HD + c;
            if (sel == 0) cp16(&Kd[r * SROWH + c], &k[g]);
            else          cp16(&Vd[r * SROWH + c], &v[g]);
        }
        CP_COMMIT();
    };

    for (int i = tid; i < 512; i += 256) {
        int r = i >> 3, c = (i & 7) << 3;
        cp16(&Qs[r * SROWH + c], &q[(size_t)(s0 + r) * HID + h * HD + c]);
    }
    CP_COMMIT();
    load_tile(0);

    float m_prev = -1e30f, lsum = 0.f;
    float oacc[4][4];
    #pragma unroll
    for (int j = 0; j < 4; j++)
        #pragma unroll
        for (int l = 0; l < 4; l++) oacc[j][l] = 0.f;

    int arow0 = wm * 16 + gid;

    uint32_t qa_off = (uint32_t)(((wm * 16 + (g8 & 1) * 8 + r8) * SROWH) * 2 + (g8 >> 1) * 16);
    uint32_t kb_off[2];
    #pragma unroll
    for (int jj = 0; jj < 2; jj++)
        kb_off[jj] = (uint32_t)(((wn * 32 + jj * 16 + (g8 >> 1) * 8 + r8) * SROWH) * 2
                                + (g8 & 1) * 16);

    uint32_t qbase = smem_u32(Qs);
    uint32_t pbase = smem_u32(Ps);

    for (int kt = 0; kt < nkt; kt++) {
        CP_WAIT0();
        __syncthreads();
        if (kt + 1 < nkt) load_tile(kt + 1);

        uint32_t kbase = smem_u32(Kb + (kt & 1) * 64 * SROWH);
        uint32_t vbase = smem_u32(Vb + (kt & 1) * 64 * SROWH);

        float sc[4][4];
        #pragma unroll
        for (int j = 0; j < 4; j++)
            #pragma unroll
            for (int l = 0; l < 4; l++) sc[j][l] = 0.f;
        #pragma unroll
        for (int ks = 0; ks < 4; ks++) {
            uint32_t kofs = ks * 32;
            uint32_t aq[4];
            ldm_x4(aq[0], aq[1], aq[2], aq[3], qbase + kofs + qa_off);
            uint32_t bf[4][2];
            #pragma unroll
            for (int jj = 0; jj < 2; jj++) {
                uint32_t m0r, m1r, m2r, m3r;
                ldm_x4(m0r, m1r, m2r, m3r, kbase + kofs + kb_off[jj]);
                bf[2 * jj + 0][0] = m0r; bf[2 * jj + 0][1] = m1r;
                bf[2 * jj + 1][0] = m2r; bf[2 * jj + 1][1] = m3r;
            }
            #pragma unroll
            for (int j = 0; j < 4; j++)
                mma_f16(sc[j], aq, bf[j][0], bf[j][1]);
        }
        #pragma unroll
        for (int j = 0; j < 4; j++) {
            int cn = wn * 32 + j * 8 + 2 * tig;
            Ss[arow0 * SP + cn]           = sc[j][0];
            Ss[arow0 * SP + cn + 1]       = sc[j][1];
            Ss[(arow0 + 8) * SP + cn]     = sc[j][2];
            Ss[(arow0 + 8) * SP + cn + 1] = sc[j][3];
        }
        __syncthreads();

        {
            float e[16];
            int base = qq * SP + kg * 16;
            float mloc = -1e30f;
            #pragma unroll
            for (int i = 0; i < 16; i++) { e[i] = Ss[base + i]; mloc = fmaxf(mloc, e[i]); }
            mloc = fmaxf(mloc, __shfl_xor_sync(0xffffffffu, mloc, 1));
            mloc = fmaxf(mloc, __shfl_xor_sync(0xffffffffu, mloc, 2));
            float m_new = fmaxf(m_prev, mloc);
            float alpha = __expf(m_prev - m_new);
            float lrow = 0.f;
            int pb = qq * SROWH + kg * 16;
            #pragma unroll
            for (int i = 0; i < 16; i += 2) {
                float e0 = __expf(e[i]     - m_new);
                float e1 = __expf(e[i + 1] - m_new);
                lrow += e0 + e1;
                *(__half2*)&Ps[pb + i] = __floats2half2_rn(e0, e1);
            }
            lrow += __shfl_xor_sync(0xffffffffu, lrow, 1);
            lrow += __shfl_xor_sync(0xffffffffu, lrow, 2);
            lsum = lsum * alpha + lrow;
            m_prev = m_new;
            if (kg == 0) Al[qq] = alpha;
        }
        __syncthreads();

        float a_r0 = Al[arow0], a_r1 = Al[arow0 + 8];
        #pragma unroll
        for (int j = 0; j < 4; j++) {
            oacc[j][0] *= a_r0; oacc[j][1] *= a_r0;
            oacc[j][2] *= a_r1; oacc[j][3] *= a_r1;
        }

        #pragma unroll
        for (int ks = 0; ks < 4; ks++) {
            uint32_t ap[4];
            ldm_x4(ap[0], ap[1], ap[2], ap[3], pbase + ks * 32 + qa_off);
            uint32_t vf[4][2];
            #pragma unroll
            for (int jj = 0; jj < 2; jj++) {
                uint32_t addr = vbase
                    + (uint32_t)(((ks * 16 + (g8 & 1) * 8 + r8) * SROWH) * 2
                                 + (wn * 32 + jj * 16) * 2 + (g8 >> 1) * 16);
                uint32_t m0r, m1r, m2r, m3r;
                ldm_x4t(m0r, m1r, m2r, m3r, addr);
                vf[2 * jj + 0][0] = m0r; vf[2 * jj + 0][1] = m1r;
                vf[2 * jj + 1][0] = m2r; vf[2 * jj + 1][1] = m3r;
            }
            #pragma unroll
            for (int j = 0; j < 4; j++)
                mma_f16(oacc[j], ap, vf[j][0], vf[j][1]);
        }
        __syncthreads();
    }

    if (kg == 0) Ll[qq] = lsum;
    __syncthreads();
    float inv0 = 1.0f / Ll[arow0];
    float inv1 = 1.0f / Ll[arow0 + 8];
    #pragma unroll
    for (int j = 0; j < 4; j++) {
        int cn = wn * 32 + j * 8 + 2 * tig;
        size_t o0 = (size_t)(s0 + arow0) * HID + h * HD + cn;
        size_t o1 = (size_t)(s0 + arow0 + 8) * HID + h * HD + cn;
        *(__half2*)&o[o0] = __floats2half2_rn(oacc[j][0] * inv0, oacc[j][1] * inv0);
        *(__half2*)&o[o1] = __floats2half2_rn(oacc[j][2] * inv1, oacc[j][3] * inv1);
    }
}

// ---------------- host orchestration ---------------------------------------------
extern "C" void kernel_launch(void* const* d_in, const int* in_sizes, int n_in,
                              void* d_out, int out_size) {
    const float* img0        = (const float*)d_in[0];
    const float* img1        = (const float*)d_in[1];
    const float* conv_w      = (const float*)d_in[2];
    const float* ln_pre_w    = (const float*)d_in[3];
    const float* attn_norm_w = (const float*)d_in[4];
    const float* q_w         = (const float*)d_in[5];
    const float* k_w         = (const float*)d_in[6];
    const float* v_w         = (const float*)d_in[7];
    const float* o_w         = (const float*)d_in[8];
    const float* ffn_norm_w  = (const float*)d_in[9];
    const float* gate_w      = (const float*)d_in[10];
    const float* up_w        = (const float*)d_in[11];
    const float* down_w      = (const float*)d_in[12];
    float* out = (float*)d_out;

    float *p_x, *p_h2;
    __half *p_xpatch, *p_hn, *p_q, *p_k, *p_v, *p_ao, *p_t;
    __half *p_wconv, *p_wq, *p_wk, *p_wv, *p_wo, *p_wg, *p_wu, *p_wd;
    cudaGetSymbolAddress((void**)&p_x,  g_x);
    cudaGetSymbolAddress((void**)&p_h2, g_h2);
    cudaGetSymbolAddress((void**)&p_xpatch, a_xpatch);
    cudaGetSymbolAddress((void**)&p_hn, a_hn);
    cudaGetSymbolAddress((void**)&p_q,  a_q);
    cudaGetSymbolAddress((void**)&p_k,  a_k);
    cudaGetSymbolAddress((void**)&p_v,  a_v);
    cudaGetSymbolAddress((void**)&p_ao, a_ao);
    cudaGetSymbolAddress((void**)&p_t,  a_t);
    cudaGetSymbolAddress((void**)&p_wconv, h_wconv);
    cudaGetSymbolAddress((void**)&p_wq, h_wq);
    cudaGetSymbolAddress((void**)&p_wk, h_wk);
    cudaGetSymbolAddress((void**)&p_wv, h_wv);
    cudaGetSymbolAddress((void**)&p_wo, h_wo);
    cudaGetSymbolAddress((void**)&p_wg, h_wg);
    cudaGetSymbolAddress((void**)&p_wu, h_wu);
    cudaGetSymbolAddress((void**)&p_wd, h_wd);

    const int SMEM64  = 3 * (64 + 128) * SROWH * 2;
    const int SMEMGU  = 3 * (64 + 256) * SROW2 * 2;
    const int ASMEM   = 6 * 64 * SROWH * 2 + 64 * SP * 4 + 2 * 64 * 4;
    cudaFuncSetAttribute((const void*)gemm_f16<0, false>, cudaFuncAttributeMaxDynamicSharedMemorySize, SMEM64);
    cudaFuncSetAttribute((const void*)gemm_f16<1, false>, cudaFuncAttributeMaxDynamicSharedMemorySize, SMEM64);
    cudaFuncSetAttribute((const void*)gemm_qkv,           cudaFuncAttributeMaxDynamicSharedMemorySize, SMEM64);
    cudaFuncSetAttribute((const void*)gemm_gateup,        cudaFuncAttributeMaxDynamicSharedMemorySize, SMEMGU);
    cudaFuncSetAttribute((const void*)attn_mma_kernel,    cudaFuncAttributeMaxDynamicSharedMemorySize, ASMEM);

    // ---- side stream: weight conversion overlapped with compute ----
    cudaStream_t s2;
    cudaStreamCreateWithFlags(&s2, cudaStreamNonBlocking);
    cudaEvent_t evFork, evConv, evL[NLAYERS];
    cudaEventCreateWithFlags(&evFork, cudaEventDisableTiming);
    cudaEventCreateWithFlags(&evConv, cudaEventDisableTiming);
    for (int l = 0; l < NLAYERS; l++) cudaEventCreateWithFlags(&evL[l], cudaEventDisableTiming);

    cudaEventRecord(evFork, 0);
    cudaStreamWaitEvent(s2, evFork, 0);

    auto cvt = [&](const float* src, __half* dst, int n) {
        f2h_kernel<<<(n / 16 + 255) / 256, 256, 0, s2>>>(src, dst, n / 16);
    };
    cvt(conv_w, p_wconv, HID * KPATCH);
    cudaEventRecord(evConv, s2);
    for (int l = 0; l < NLAYERS; l++) {
        cvt(q_w    + (size_t)l * HID * HID,   p_wq + (size_t)l * HID * HID,   HID * HID);
        cvt(k_w    + (size_t)l * HID * HID,   p_wk + (size_t)l * HID * HID,   HID * HID);
        cvt(v_w    + (size_t)l * HID * HID,   p_wv + (size_t)l * HID * HID,   HID * HID);
        cvt(o_w    + (size_t)l * HID * HID,   p_wo + (size_t)l * HID * HID,   HID * HID);
        cvt(gate_w + (size_t)l * INTER * HID, p_wg + (size_t)l * INTER * HID, INTER * HID);
        cvt(up_w   + (size_t)l * INTER * HID, p_wu + (size_t)l * INTER * HID, INTER * HID);
        cvt(down_w + (size_t)l * HID * INTER, p_wd + (size_t)l * HID * INTER, HID * INTER);
        cudaEventRecord(evL[l], s2);
    }

    dim3 grid_n1k(HID / 128, S_TOK / 64);
    dim3 grid_qkv(HID / 128, S_TOK / 64, 3);
    dim3 grid_gu (INTER / 128, S_TOK / 64);

    im2col_kernel<<<(S_TOK * KPATCH + 255) / 256, 256>>>(img0, img1);
    rope_table_kernel<<<S_TOK, 64>>>();
    cudaStreamWaitEvent(0, evConv, 0);
    gemm_f16<0, false><<<grid_n1k, 256, SMEM64>>>(p_xpatch, p_wconv, nullptr, p_h2, HID, KPATCH);

    rms_kernel<false><<<S_TOK, 256>>>(p_h2, ln_pre_w, p_x);

    for (int l = 0; l < NLAYERS; l++) {
        const __half* qw = p_wq + (size_t)l * HID * HID;
        const __half* kw = p_wk + (size_t)l * HID * HID;
        const __half* vw = p_wv + (size_t)l * HID * HID;
        const __half* ow = p_wo + (size_t)l * HID * HID;
        const __half* gw = p_wg + (size_t)l * INTER * HID;
        const __half* uw = p_wu + (size_t)l * INTER * HID;
        const __half* dw = p_wd + (size_t)l * HID * INTER;

        rms_kernel<true><<<S_TOK, 256>>>(p_x, attn_norm_w + l * HID, p_hn);

        cudaStreamWaitEvent(0, evL[l], 0);   // layer-l weights ready

        gemm_qkv<<<grid_qkv, 256, SMEM64>>>(p_hn, qw, kw, vw, p_q, p_k, p_v, HID);

        rope_kernel<<<(S_TOK * HEADS * 32 + 255) / 256, 256>>>(p_q, p_k);

        attn_mma_kernel<<<dim3(S_TOK / 64, HEADS), 256, ASMEM>>>(p_q, p_k, p_v, p_ao);

        gemm_f16<1, false><<<grid_n1k, 256, SMEM64>>>(p_ao, ow, p_x, p_h2, HID, HID);

        rms_kernel<true><<<S_TOK, 256>>>(p_h2, ffn_norm_w + l * HID, p_hn);

        gemm_gateup<<<grid_gu, 256, SMEMGU>>>(p_hn, gw, uw, p_t, INTER, HID);

        float* dst = (l == NLAYERS - 1) ? out : p_x;
        gemm_f16<1, false><<<grid_n1k, 256, SMEM64>>>(p_t, dw, p_h2, dst, HID, INTER);
    }
    // NOTE: streams/events intentionally not destroyed here — destruction of a
    // forked stream during an active capture invalidates the capture. Host-side
    // objects only; kernel_launch is invoked a bounded number of times.
}